// round 3
// baseline (speedup 1.0000x reference)
#include <cuda_runtime.h>
#include <math.h>
#include <float.h>

// ---------------- problem constants (fixed shapes) ----------------
#define T_TOK 4096
#define C_SP  4096
#define HID   1024
#define METAF 20
#define SPAND 3092          // 3*HID + METAF
#define UHID  1024
#define M_TOP 1024
#define K_ANT 50
#define NEGV  (-1e30f)

// ---------------- device scratch ----------------------------------
__device__ float g_logits[T_TOK];
__device__ float g_span_emb[(size_t)C_SP * SPAND];
__device__ float g_hid1[(size_t)C_SP * UHID];
__device__ float g_mention[C_SP];
__device__ int   g_topidx[M_TOP];
__device__ float g_topm[M_TOP];
__device__ float g_topemb[(size_t)M_TOP * SPAND];
__device__ float g_tmp[(size_t)M_TOP * SPAND];
__device__ float g_fast[(size_t)M_TOP * M_TOP];

// ---------------- kernel 1: token logits (fp64 accumulate) --------
__global__ void k_token_logits(const float* __restrict__ hs,
                               const float* __restrict__ w_attn,
                               const float* __restrict__ b_attn) {
    int warp = (blockIdx.x * blockDim.x + threadIdx.x) >> 5;
    int lane = threadIdx.x & 31;
    if (warp >= T_TOK) return;
    const float* row = hs + (size_t)warp * HID;
    double acc = 0.0;
    #pragma unroll 8
    for (int i = lane; i < HID; i += 32) acc += (double)row[i] * (double)w_attn[i];
    #pragma unroll
    for (int o = 16; o; o >>= 1) acc += __shfl_xor_sync(0xffffffffu, acc, o);
    if (lane == 0) g_logits[warp] = (float)(acc + (double)b_attn[0]);
}

// ---------------- kernel 2: span embeddings (fp64 pooling) --------
__global__ void k_span_emb(const float* __restrict__ hs,
                           const int* __restrict__ starts,
                           const int* __restrict__ widths,
                           const float* __restrict__ w_width) {
    int c = blockIdx.x;
    int s = starts[c], w = widths[c];
    int e = s + w, L = w + 1;
    __shared__ float p[32];
    int tid = threadIdx.x;
    if (tid < 32) {
        double lg = (tid < L) ? (double)g_logits[s + tid] : -1e300;
        double mx = lg;
        #pragma unroll
        for (int o = 16; o; o >>= 1) {
            double v = __shfl_xor_sync(0xffffffffu, mx, o);
            mx = fmax(mx, v);
        }
        double ex = (tid < L) ? exp(lg - mx) : 0.0;
        double sm = ex;
        #pragma unroll
        for (int o = 16; o; o >>= 1) sm += __shfl_xor_sync(0xffffffffu, sm, o);
        p[tid] = (float)(ex / sm);
    }
    __syncthreads();
    float* out = g_span_emb + (size_t)c * SPAND;
    const float* hrow_s = hs + (size_t)s * HID;
    const float* hrow_e = hs + (size_t)e * HID;
    for (int h = tid; h < HID; h += blockDim.x) {
        out[h]        = hrow_s[h];
        out[HID + h]  = hrow_e[h];
        double acc = 0.0;
        for (int l = 0; l < L; ++l)
            acc += (double)p[l] * (double)hs[(size_t)(s + l) * HID + h];
        out[2 * HID + METAF + h] = (float)acc;
    }
    if (tid < METAF) out[2 * HID + tid] = w_width[w * METAF + tid];
}

// ---------------- Kahan-compensated tiled SGEMM -------------------
// C[M,N] = A[M,K] * op(B) + bias,   op(B)=B[K,N] (NN) or B[N,K]^T (NT)
// Compensated summation keeps |err| ~ 2*eps*|C| regardless of K.
template<int BM, int BN, int TM, int TN, bool RELU, bool NT, bool BIAS>
__global__ void k_gemm_kahan(const float* __restrict__ A, const float* __restrict__ B,
                             const float* __restrict__ bias, float* __restrict__ C,
                             int M, int N, int K) {
    __shared__ float As[16][BM];
    __shared__ float Bs[16][BN];
    const int tid  = threadIdx.x;      // 256 threads
    const int trow = tid >> 4;         // 0..15
    const int tcol = tid & 15;         // 0..15
    const int row0 = blockIdx.y * BM;
    const int col0 = blockIdx.x * BN;

    float acc[TM][TN];
    float cmp[TM][TN];
    #pragma unroll
    for (int i = 0; i < TM; ++i)
        #pragma unroll
        for (int j = 0; j < TN; ++j) { acc[i][j] = 0.f; cmp[i][j] = 0.f; }

    for (int k0 = 0; k0 < K; k0 += 16) {
        #pragma unroll
        for (int i = tid; i < BM * 16; i += 256) {
            int r = i >> 4, kk = i & 15;
            int gr = row0 + r, gk = k0 + kk;
            As[kk][r] = (gr < M && gk < K) ? A[(size_t)gr * K + gk] : 0.f;
        }
        if (!NT) {
            #pragma unroll
            for (int i = tid; i < 16 * BN; i += 256) {
                int kk = i / BN, n = i % BN;
                int gk = k0 + kk, gn = col0 + n;
                Bs[kk][n] = (gk < K && gn < N) ? B[(size_t)gk * N + gn] : 0.f;
            }
        } else {
            #pragma unroll
            for (int i = tid; i < BN * 16; i += 256) {
                int n = i >> 4, kk = i & 15;
                int gn = col0 + n, gk = k0 + kk;
                Bs[kk][n] = (gn < N && gk < K) ? B[(size_t)gn * K + gk] : 0.f;
            }
        }
        __syncthreads();
        #pragma unroll
        for (int kk = 0; kk < 16; ++kk) {
            float a[TM], b[TN];
            #pragma unroll
            for (int i = 0; i < TM; i += 4) {
                float4 t = *(const float4*)&As[kk][trow * TM + i];
                a[i] = t.x; a[i+1] = t.y; a[i+2] = t.z; a[i+3] = t.w;
            }
            #pragma unroll
            for (int j = 0; j < TN; j += 4) {
                float4 t = *(const float4*)&Bs[kk][tcol * TN + j];
                b[j] = t.x; b[j+1] = t.y; b[j+2] = t.z; b[j+3] = t.w;
            }
            #pragma unroll
            for (int i = 0; i < TM; ++i)
                #pragma unroll
                for (int j = 0; j < TN; ++j) {
                    // Kahan: y = a*b - c; t = s + y; c = (t - s) - y; s = t
                    float y = __fmaf_rn(a[i], b[j], -cmp[i][j]);
                    float t = __fadd_rn(acc[i][j], y);
                    cmp[i][j] = __fsub_rn(__fsub_rn(t, acc[i][j]), y);
                    acc[i][j] = t;
                }
        }
        __syncthreads();
    }
    #pragma unroll
    for (int i = 0; i < TM; ++i) {
        int r = row0 + trow * TM + i;
        if (r >= M) continue;
        #pragma unroll
        for (int j = 0; j < TN; ++j) {
            int cc = col0 + tcol * TN + j;
            if (cc >= N) continue;
            float v = acc[i][j];
            if (BIAS) v = __fadd_rn(v, bias[cc]);
            if (RELU) v = fmaxf(v, 0.f);
            C[(size_t)r * N + cc] = v;
        }
    }
}

// ---------------- kernel: mention score (fp64 accumulate) ---------
__global__ void k_score(const float* __restrict__ w_u2,
                        const float* __restrict__ b_u2) {
    int warp = (blockIdx.x * blockDim.x + threadIdx.x) >> 5;
    int lane = threadIdx.x & 31;
    if (warp >= C_SP) return;
    const float* row = g_hid1 + (size_t)warp * UHID;
    double acc = 0.0;
    #pragma unroll 8
    for (int i = lane; i < UHID; i += 32) acc += (double)row[i] * (double)w_u2[i];
    #pragma unroll
    for (int o = 16; o; o >>= 1) acc += __shfl_xor_sync(0xffffffffu, acc, o);
    if (lane == 0) g_mention[warp] = (float)(acc + (double)b_u2[0]);
}

// ---------------- kernel: sort + greedy non-crossing + compact ----
__global__ void k_extract(const int* __restrict__ starts,
                          const int* __restrict__ widths) {
    extern __shared__ int sh[];
    float* key = (float*)sh;           // later reused as latest_end (int)
    int* idx = sh + 4096;
    int* es  = sh + 8192;
    int* flg = sh + 12288;
    const int tid = threadIdx.x;       // 1024 threads

    for (int i = tid; i < C_SP; i += 1024) {
        key[i] = g_mention[i];
        idx[i] = i;
        flg[i] = 0;
    }
    __syncthreads();

    // bitonic sort: descending by score, ties -> ascending index
    for (unsigned k = 2; k <= 4096; k <<= 1) {
        for (unsigned j = k >> 1; j > 0; j >>= 1) {
            for (unsigned t = tid; t < 2048; t += 1024) {
                unsigned i = ((t & ~(j - 1)) << 1) | (t & (j - 1));
                unsigned l = i | j;
                float ki = key[i], kl = key[l];
                int   ii = idx[i], il = idx[l];
                bool before_l_i = (kl > ki) || (kl == ki && il < ii);
                bool dir = ((i & k) == 0);
                if (before_l_i == dir) {
                    key[i] = kl; key[l] = ki;
                    idx[i] = il; idx[l] = ii;
                }
            }
            __syncthreads();
        }
    }

    volatile int* le = (volatile int*)key;
    volatile int* ves = (volatile int*)es;
    for (int i = tid; i < T_TOK; i += 1024) {
        ((int*)key)[i] = -1;
        es[i] = T_TOK;
    }
    __syncthreads();

    // greedy non-crossing, warp 0 only, early exit at count==M_TOP
    if (tid < 32) {
        int lane = tid;
        int count = 0;
        for (int p = 0; p < C_SP && count < M_TOP; ++p) {
            int ci = idx[p];
            int s = starts[ci];
            int w = widths[ci];
            int e = s + w;
            bool crossing = false;
            if (lane < w) {                 // w <= 29 < 32
                crossing = (le[s + 1 + lane] > e) | (ves[s + lane] < s);
            }
            unsigned m = __ballot_sync(0xffffffffu, crossing);
            if (m == 0u) {
                if (lane == 0) {
                    int cur = le[s]; if (e > cur) ((int*)key)[s] = e;
                    int cur2 = ves[e]; if (s < cur2) es[e] = s;
                    flg[ci] = 1;
                }
                count++;
            }
            __syncwarp();
        }
    }
    __syncthreads();

    // compact selected candidate indices (ascending), pad with 4095
    __shared__ int wsum[32];
    __shared__ int woff[33];
    int base = tid * 4;
    int f0 = flg[base], f1 = flg[base + 1], f2 = flg[base + 2], f3 = flg[base + 3];
    int c = f0 + f1 + f2 + f3;
    int inc = c;
    int lane = tid & 31, wid = tid >> 5;
    #pragma unroll
    for (int o = 1; o < 32; o <<= 1) {
        int n = __shfl_up_sync(0xffffffffu, inc, o);
        if (lane >= o) inc += n;
    }
    if (lane == 31) wsum[wid] = inc;
    __syncthreads();
    if (tid == 0) {
        int run = 0;
        for (int i = 0; i < 32; ++i) { woff[i] = run; run += wsum[i]; }
        woff[32] = run;
    }
    __syncthreads();
    int pos = woff[wid] + (inc - c);
    if (f0) { if (pos < M_TOP) g_topidx[pos] = base;     pos++; }
    if (f1) { if (pos < M_TOP) g_topidx[pos] = base + 1; pos++; }
    if (f2) { if (pos < M_TOP) g_topidx[pos] = base + 2; pos++; }
    if (f3) { if (pos < M_TOP) g_topidx[pos] = base + 3; pos++; }
    int total = woff[32];
    for (int p = total + tid; p < M_TOP; p += 1024) g_topidx[p] = C_SP - 1;
}

// ---------------- kernel: gather top spans ------------------------
__global__ void k_gather(float* __restrict__ out_topidx) {
    int p = blockIdx.x;
    int ci = g_topidx[p];
    if (threadIdx.x == 0) {
        g_topm[p] = g_mention[ci];
        out_topidx[p] = (float)ci;
    }
    const float4* src = (const float4*)(g_span_emb + (size_t)ci * SPAND);
    float4* dst = (float4*)(g_topemb + (size_t)p * SPAND);
    for (int i = threadIdx.x; i < SPAND / 4; i += blockDim.x) dst[i] = src[i];
}

// ---------------- kernel: assemble fast scores + per-row top-50 ---
__global__ void k_topk(float* __restrict__ out_ant,
                       float* __restrict__ out_mask,
                       float* __restrict__ out_score) {
    __shared__ float v[M_TOP];
    __shared__ float rv[256];
    __shared__ int   ri[256];
    const int i = blockIdx.x;
    const int tid = threadIdx.x;
    const float mi = g_topm[i];
    for (int j = tid; j < M_TOP; j += 256) {
        // match reference association: ((m_i + m_j) + mask) + dot
        float val = __fadd_rn(__fadd_rn(__fadd_rn(mi, g_topm[j]),
                                        (j < i) ? 0.f : NEGV),
                              g_fast[(size_t)i * M_TOP + j]);
        v[j] = val;
    }
    __syncthreads();
    for (int k = 0; k < K_ANT; ++k) {
        float bv = -INFINITY; int bi = M_TOP;
        for (int j = tid; j < M_TOP; j += 256) {
            float x = v[j];
            if (x > bv || (x == bv && j < bi)) { bv = x; bi = j; }
        }
        rv[tid] = bv; ri[tid] = bi;
        __syncthreads();
        for (int s = 128; s > 0; s >>= 1) {
            if (tid < s) {
                if (rv[tid + s] > rv[tid] ||
                    (rv[tid + s] == rv[tid] && ri[tid + s] < ri[tid])) {
                    rv[tid] = rv[tid + s]; ri[tid] = ri[tid + s];
                }
            }
            __syncthreads();
        }
        if (tid == 0) {
            int j = ri[0];
            out_ant[(size_t)i * K_ANT + k]   = (float)j;
            out_mask[(size_t)i * K_ANT + k]  = (j < i) ? 1.f : 0.f;
            out_score[(size_t)i * K_ANT + k] = rv[0];
            v[j] = -INFINITY;
        }
        __syncthreads();
    }
}

// ---------------- launch ------------------------------------------
extern "C" void kernel_launch(void* const* d_in, const int* in_sizes, int n_in,
                              void* d_out, int out_size) {
    const float* hs      = (const float*)d_in[0];
    const int*   starts  = (const int*)d_in[1];
    const int*   widths  = (const int*)d_in[2];
    int base = 3;
    if (n_in >= 14 && in_sizes[3] == 1 && in_sizes[4] == 1) base = 5;
    const float* w_width = (const float*)d_in[base + 0];
    const float* w_attn  = (const float*)d_in[base + 1];
    const float* b_attn  = (const float*)d_in[base + 2];
    const float* w_u1    = (const float*)d_in[base + 3];
    const float* b_u1    = (const float*)d_in[base + 4];
    const float* w_u2    = (const float*)d_in[base + 5];
    const float* b_u2    = (const float*)d_in[base + 6];
    const float* w_fast  = (const float*)d_in[base + 7];
    const float* b_fast  = (const float*)d_in[base + 8];

    float* out = (float*)d_out;
    float* out_topidx = out;
    float* out_ant    = out + M_TOP;
    float* out_mask   = out + M_TOP + M_TOP * K_ANT;
    float* out_score  = out + M_TOP + 2 * M_TOP * K_ANT;

    float *p_span, *p_hid1, *p_topemb, *p_tmp, *p_fast;
    cudaGetSymbolAddress((void**)&p_span,   g_span_emb);
    cudaGetSymbolAddress((void**)&p_hid1,   g_hid1);
    cudaGetSymbolAddress((void**)&p_topemb, g_topemb);
    cudaGetSymbolAddress((void**)&p_tmp,    g_tmp);
    cudaGetSymbolAddress((void**)&p_fast,   g_fast);

    // 1. token logits (fp64 accumulate)
    k_token_logits<<<T_TOK * 32 / 256, 256>>>(hs, w_attn, b_attn);

    // 2. span embeddings (fp64 softmax pooling)
    k_span_emb<<<C_SP, 256>>>(hs, starts, widths, w_width);

    // 3. hid1 = relu(span_emb @ w_u1 + b_u1)   [4096,1024], Kahan
    {
        dim3 grid((UHID + 63) / 64, (C_SP + 127) / 128);
        k_gemm_kahan<128, 64, 8, 4, true, false, true><<<grid, 256>>>(
            p_span, w_u1, b_u1, p_hid1, C_SP, UHID, SPAND);
    }

    // 4. mention scores (fp64 accumulate)
    k_score<<<C_SP * 32 / 256, 256>>>(w_u2, b_u2);

    // 5. sort + greedy extraction + compact
    cudaFuncSetAttribute(k_extract, cudaFuncAttributeMaxDynamicSharedMemorySize, 65536);
    k_extract<<<1, 1024, 65536>>>(starts, widths);

    // 6. gather top_emb / top_m / write top_idx output
    k_gather<<<M_TOP, 256>>>(out_topidx);

    // 7. tmp = top_emb @ w_fast + b_fast   [1024,3092], Kahan
    {
        dim3 grid((SPAND + 63) / 64, (M_TOP + 127) / 128);
        k_gemm_kahan<128, 64, 8, 4, false, false, true><<<grid, 256>>>(
            p_topemb, w_fast, b_fast, p_tmp, M_TOP, SPAND, SPAND);
    }

    // 8. fast0 = tmp @ top_emb^T   [1024,1024], Kahan
    {
        dim3 grid((M_TOP + 63) / 64, (M_TOP + 63) / 64);
        k_gemm_kahan<64, 64, 4, 4, false, true, false><<<grid, 256>>>(
            p_tmp, p_topemb, nullptr, p_fast, M_TOP, M_TOP, SPAND);
    }

    // 9. assemble fast matrix + per-row top-50
    k_topk<<<M_TOP, 256>>>(out_ant, out_mask, out_score);

    (void)in_sizes; (void)n_in; (void)out_size;
}

// round 5
// speedup vs baseline: 1.9683x; 1.9683x over previous
#include <cuda_runtime.h>
#include <math.h>
#include <float.h>

// ---------------- problem constants (fixed shapes) ----------------
#define T_TOK 4096
#define C_SP  4096
#define HID   1024
#define METAF 20
#define SPAND 3092          // 3*HID + METAF
#define UHID  1024
#define M_TOP 1024
#define K_ANT 50
#define NEGV  (-1e30f)

// ---------------- device scratch ----------------------------------
__device__ float g_logits[T_TOK];
__device__ float g_span_emb[(size_t)C_SP * SPAND];
__device__ float g_hid1[(size_t)C_SP * UHID];
__device__ float g_mention[C_SP];
__device__ int   g_topidx[M_TOP];
__device__ float g_topm[M_TOP];
__device__ float g_topemb[(size_t)M_TOP * SPAND];
__device__ float g_tmp[(size_t)M_TOP * SPAND];
__device__ float g_fast[(size_t)M_TOP * M_TOP];

// ---------------- kernel 1: token logits (fp64 accumulate) --------
__global__ void k_token_logits(const float* __restrict__ hs,
                               const float* __restrict__ w_attn,
                               const float* __restrict__ b_attn) {
    int warp = (blockIdx.x * blockDim.x + threadIdx.x) >> 5;
    int lane = threadIdx.x & 31;
    if (warp >= T_TOK) return;
    const float* row = hs + (size_t)warp * HID;
    double acc = 0.0;
    #pragma unroll 8
    for (int i = lane; i < HID; i += 32) acc += (double)row[i] * (double)w_attn[i];
    #pragma unroll
    for (int o = 16; o; o >>= 1) acc += __shfl_xor_sync(0xffffffffu, acc, o);
    if (lane == 0) g_logits[warp] = (float)(acc + (double)b_attn[0]);
}

// ---------------- kernel 2: span embeddings -----------------------
// softmax weights in fp64 (32 threads, trivial); pooling sum in fp32
// Kahan over <=30 terms: per-element error ~2e-7, amplified through
// the downstream 3092-dot to ~1.5e-5 — inside the flip budget.
__global__ void k_span_emb(const float* __restrict__ hs,
                           const int* __restrict__ starts,
                           const int* __restrict__ widths,
                           const float* __restrict__ w_width) {
    int c = blockIdx.x;
    int s = starts[c], w = widths[c];
    int e = s + w, L = w + 1;
    __shared__ float p[32];
    int tid = threadIdx.x;
    if (tid < 32) {
        double lg = (tid < L) ? (double)g_logits[s + tid] : -1e300;
        double mx = lg;
        #pragma unroll
        for (int o = 16; o; o >>= 1) {
            double v = __shfl_xor_sync(0xffffffffu, mx, o);
            mx = fmax(mx, v);
        }
        double ex = (tid < L) ? exp(lg - mx) : 0.0;
        double sm = ex;
        #pragma unroll
        for (int o = 16; o; o >>= 1) sm += __shfl_xor_sync(0xffffffffu, sm, o);
        p[tid] = (float)(ex / sm);
    }
    __syncthreads();
    float* out = g_span_emb + (size_t)c * SPAND;
    const float* hrow_s = hs + (size_t)s * HID;
    const float* hrow_e = hs + (size_t)e * HID;
    for (int h = tid; h < HID; h += blockDim.x) {
        out[h]        = hrow_s[h];
        out[HID + h]  = hrow_e[h];
        // Kahan fp32 weighted sum
        float acc = 0.f, cmp = 0.f;
        for (int l = 0; l < L; ++l) {
            float y = __fmaf_rn(p[l], hs[(size_t)(s + l) * HID + h], -cmp);
            float t = __fadd_rn(acc, y);
            cmp = __fsub_rn(__fsub_rn(t, acc), y);
            acc = t;
        }
        out[2 * HID + METAF + h] = acc;
    }
    if (tid < METAF) out[2 * HID + tid] = w_width[w * METAF + tid];
}

// ---------------- tiled SGEMM (plain or chunk-Kahan) --------------
// C[M,N] = A[M,K] * op(B) + bias,   op(B)=B[K,N] (NN) or B[N,K]^T (NT)
// COMP==0: plain FMA accumulation.
// COMP==1: plain FMA inside each 16-wide k-tile into a local
//          accumulator, then one exact Kahan fold per tile into the
//          master sum. Error ~2e-5 absolute on a 3092-length dot —
//          30x below the level that caused rank flips in round 1.
template<int BM, int BN, int TM, int TN, int COMP, bool RELU, bool NT, bool BIAS>
__global__ void k_gemm(const float* __restrict__ A, const float* __restrict__ B,
                       const float* __restrict__ bias, float* __restrict__ C,
                       int M, int N, int K) {
    __shared__ float As[16][BM];
    __shared__ float Bs[16][BN];
    const int tid  = threadIdx.x;      // 256 threads
    const int trow = tid >> 4;         // 0..15
    const int tcol = tid & 15;         // 0..15
    const int row0 = blockIdx.y * BM;
    const int col0 = blockIdx.x * BN;

    float acc[TM][TN];
    float cmp[TM][TN];
    #pragma unroll
    for (int i = 0; i < TM; ++i)
        #pragma unroll
        for (int j = 0; j < TN; ++j) { acc[i][j] = 0.f; cmp[i][j] = 0.f; }

    for (int k0 = 0; k0 < K; k0 += 16) {
        #pragma unroll
        for (int i = tid; i < BM * 16; i += 256) {
            int r = i >> 4, kk = i & 15;
            int gr = row0 + r, gk = k0 + kk;
            As[kk][r] = (gr < M && gk < K) ? A[(size_t)gr * K + gk] : 0.f;
        }
        if (!NT) {
            #pragma unroll
            for (int i = tid; i < 16 * BN; i += 256) {
                int kk = i / BN, n = i % BN;
                int gk = k0 + kk, gn = col0 + n;
                Bs[kk][n] = (gk < K && gn < N) ? B[(size_t)gk * N + gn] : 0.f;
            }
        } else {
            #pragma unroll
            for (int i = tid; i < BN * 16; i += 256) {
                int n = i >> 4, kk = i & 15;
                int gn = col0 + n, gk = k0 + kk;
                Bs[kk][n] = (gn < N && gk < K) ? B[(size_t)gn * K + gk] : 0.f;
            }
        }
        __syncthreads();

        float loc[TM][TN];
        if (COMP) {
            #pragma unroll
            for (int i = 0; i < TM; ++i)
                #pragma unroll
                for (int j = 0; j < TN; ++j) loc[i][j] = 0.f;
        }

        #pragma unroll
        for (int kk = 0; kk < 16; ++kk) {
            float a[TM], b[TN];
            #pragma unroll
            for (int i = 0; i < TM; i += 4) {
                float4 t = *(const float4*)&As[kk][trow * TM + i];
                a[i] = t.x; a[i+1] = t.y; a[i+2] = t.z; a[i+3] = t.w;
            }
            #pragma unroll
            for (int j = 0; j < TN; j += 4) {
                float4 t = *(const float4*)&Bs[kk][tcol * TN + j];
                b[j] = t.x; b[j+1] = t.y; b[j+2] = t.z; b[j+3] = t.w;
            }
            if (COMP) {
                #pragma unroll
                for (int i = 0; i < TM; ++i)
                    #pragma unroll
                    for (int j = 0; j < TN; ++j)
                        loc[i][j] = __fmaf_rn(a[i], b[j], loc[i][j]);
            } else {
                #pragma unroll
                for (int i = 0; i < TM; ++i)
                    #pragma unroll
                    for (int j = 0; j < TN; ++j)
                        acc[i][j] = __fmaf_rn(a[i], b[j], acc[i][j]);
            }
        }

        if (COMP) {
            // Kahan fold of the tile-local partial into the master sum
            #pragma unroll
            for (int i = 0; i < TM; ++i)
                #pragma unroll
                for (int j = 0; j < TN; ++j) {
                    float y = __fsub_rn(loc[i][j], cmp[i][j]);
                    float t = __fadd_rn(acc[i][j], y);
                    cmp[i][j] = __fsub_rn(__fsub_rn(t, acc[i][j]), y);
                    acc[i][j] = t;
                }
        }
        __syncthreads();
    }
    #pragma unroll
    for (int i = 0; i < TM; ++i) {
        int r = row0 + trow * TM + i;
        if (r >= M) continue;
        #pragma unroll
        for (int j = 0; j < TN; ++j) {
            int cc = col0 + tcol * TN + j;
            if (cc >= N) continue;
            float v = acc[i][j];
            if (BIAS) v = __fadd_rn(v, bias[cc]);
            if (RELU) v = fmaxf(v, 0.f);
            C[(size_t)r * N + cc] = v;
        }
    }
}

// ---------------- kernel: mention score (fp64 accumulate) ---------
__global__ void k_score(const float* __restrict__ w_u2,
                        const float* __restrict__ b_u2) {
    int warp = (blockIdx.x * blockDim.x + threadIdx.x) >> 5;
    int lane = threadIdx.x & 31;
    if (warp >= C_SP) return;
    const float* row = g_hid1 + (size_t)warp * UHID;
    double acc = 0.0;
    #pragma unroll 8
    for (int i = lane; i < UHID; i += 32) acc += (double)row[i] * (double)w_u2[i];
    #pragma unroll
    for (int o = 16; o; o >>= 1) acc += __shfl_xor_sync(0xffffffffu, acc, o);
    if (lane == 0) g_mention[warp] = (float)(acc + (double)b_u2[0]);
}

// ---------------- kernel: sort + greedy non-crossing + compact ----
__global__ void k_extract(const int* __restrict__ starts,
                          const int* __restrict__ widths) {
    extern __shared__ int sh[];
    float* key = (float*)sh;           // later reused as latest_end (int)
    int* idx = sh + 4096;
    int* es  = sh + 8192;
    int* flg = sh + 12288;
    const int tid = threadIdx.x;       // 1024 threads

    for (int i = tid; i < C_SP; i += 1024) {
        key[i] = g_mention[i];
        idx[i] = i;
        flg[i] = 0;
    }
    __syncthreads();

    // bitonic sort: descending by score, ties -> ascending index
    for (unsigned k = 2; k <= 4096; k <<= 1) {
        for (unsigned j = k >> 1; j > 0; j >>= 1) {
            for (unsigned t = tid; t < 2048; t += 1024) {
                unsigned i = ((t & ~(j - 1)) << 1) | (t & (j - 1));
                unsigned l = i | j;
                float ki = key[i], kl = key[l];
                int   ii = idx[i], il = idx[l];
                bool before_l_i = (kl > ki) || (kl == ki && il < ii);
                bool dir = ((i & k) == 0);
                if (before_l_i == dir) {
                    key[i] = kl; key[l] = ki;
                    idx[i] = il; idx[l] = ii;
                }
            }
            __syncthreads();
        }
    }

    volatile int* le = (volatile int*)key;
    volatile int* ves = (volatile int*)es;
    for (int i = tid; i < T_TOK; i += 1024) {
        ((int*)key)[i] = -1;
        es[i] = T_TOK;
    }
    __syncthreads();

    // greedy non-crossing, warp 0 only, early exit at count==M_TOP
    if (tid < 32) {
        int lane = tid;
        int count = 0;
        for (int p = 0; p < C_SP && count < M_TOP; ++p) {
            int ci = idx[p];
            int s = starts[ci];
            int w = widths[ci];
            int e = s + w;
            bool crossing = false;
            if (lane < w) {                 // w <= 29 < 32
                crossing = (le[s + 1 + lane] > e) | (ves[s + lane] < s);
            }
            unsigned m = __ballot_sync(0xffffffffu, crossing);
            if (m == 0u) {
                if (lane == 0) {
                    int cur = le[s]; if (e > cur) ((int*)key)[s] = e;
                    int cur2 = ves[e]; if (s < cur2) es[e] = s;
                    flg[ci] = 1;
                }
                count++;
            }
            __syncwarp();
        }
    }
    __syncthreads();

    // compact selected candidate indices (ascending), pad with 4095
    __shared__ int wsum[32];
    __shared__ int woff[33];
    int base = tid * 4;
    int f0 = flg[base], f1 = flg[base + 1], f2 = flg[base + 2], f3 = flg[base + 3];
    int c = f0 + f1 + f2 + f3;
    int inc = c;
    int lane = tid & 31, wid = tid >> 5;
    #pragma unroll
    for (int o = 1; o < 32; o <<= 1) {
        int n = __shfl_up_sync(0xffffffffu, inc, o);
        if (lane >= o) inc += n;
    }
    if (lane == 31) wsum[wid] = inc;
    __syncthreads();
    if (tid == 0) {
        int run = 0;
        for (int i = 0; i < 32; ++i) { woff[i] = run; run += wsum[i]; }
        woff[32] = run;
    }
    __syncthreads();
    int pos = woff[wid] + (inc - c);
    if (f0) { if (pos < M_TOP) g_topidx[pos] = base;     pos++; }
    if (f1) { if (pos < M_TOP) g_topidx[pos] = base + 1; pos++; }
    if (f2) { if (pos < M_TOP) g_topidx[pos] = base + 2; pos++; }
    if (f3) { if (pos < M_TOP) g_topidx[pos] = base + 3; pos++; }
    int total = woff[32];
    for (int p = total + tid; p < M_TOP; p += 1024) g_topidx[p] = C_SP - 1;
}

// ---------------- kernel: gather top spans ------------------------
__global__ void k_gather(float* __restrict__ out_topidx) {
    int p = blockIdx.x;
    int ci = g_topidx[p];
    if (threadIdx.x == 0) {
        g_topm[p] = g_mention[ci];
        out_topidx[p] = (float)ci;
    }
    const float4* src = (const float4*)(g_span_emb + (size_t)ci * SPAND);
    float4* dst = (float4*)(g_topemb + (size_t)p * SPAND);
    for (int i = threadIdx.x; i < SPAND / 4; i += blockDim.x) dst[i] = src[i];
}

// ---------------- kernel: assemble fast scores + per-row top-50 ---
__global__ void k_topk(float* __restrict__ out_ant,
                       float* __restrict__ out_mask,
                       float* __restrict__ out_score) {
    __shared__ float v[M_TOP];
    __shared__ float rv[256];
    __shared__ int   ri[256];
    const int i = blockIdx.x;
    const int tid = threadIdx.x;
    const float mi = g_topm[i];
    for (int j = tid; j < M_TOP; j += 256) {
        float val = __fadd_rn(__fadd_rn(__fadd_rn(mi, g_topm[j]),
                                        (j < i) ? 0.f : NEGV),
                              g_fast[(size_t)i * M_TOP + j]);
        v[j] = val;
    }
    __syncthreads();
    for (int k = 0; k < K_ANT; ++k) {
        float bv = -INFINITY; int bi = M_TOP;
        for (int j = tid; j < M_TOP; j += 256) {
            float x = v[j];
            if (x > bv || (x == bv && j < bi)) { bv = x; bi = j; }
        }
        rv[tid] = bv; ri[tid] = bi;
        __syncthreads();
        for (int s = 128; s > 0; s >>= 1) {
            if (tid < s) {
                if (rv[tid + s] > rv[tid] ||
                    (rv[tid + s] == rv[tid] && ri[tid + s] < ri[tid])) {
                    rv[tid] = rv[tid + s]; ri[tid] = ri[tid + s];
                }
            }
            __syncthreads();
        }
        if (tid == 0) {
            int j = ri[0];
            out_ant[(size_t)i * K_ANT + k]   = (float)j;
            out_mask[(size_t)i * K_ANT + k]  = (j < i) ? 1.f : 0.f;
            out_score[(size_t)i * K_ANT + k] = rv[0];
            v[j] = -INFINITY;
        }
        __syncthreads();
    }
}

// ---------------- launch ------------------------------------------
extern "C" void kernel_launch(void* const* d_in, const int* in_sizes, int n_in,
                              void* d_out, int out_size) {
    const float* hs      = (const float*)d_in[0];
    const int*   starts  = (const int*)d_in[1];
    const int*   widths  = (const int*)d_in[2];
    int base = 3;
    if (n_in >= 14 && in_sizes[3] == 1 && in_sizes[4] == 1) base = 5;
    const float* w_width = (const float*)d_in[base + 0];
    const float* w_attn  = (const float*)d_in[base + 1];
    const float* b_attn  = (const float*)d_in[base + 2];
    const float* w_u1    = (const float*)d_in[base + 3];
    const float* b_u1    = (const float*)d_in[base + 4];
    const float* w_u2    = (const float*)d_in[base + 5];
    const float* b_u2    = (const float*)d_in[base + 6];
    const float* w_fast  = (const float*)d_in[base + 7];
    const float* b_fast  = (const float*)d_in[base + 8];

    float* out = (float*)d_out;
    float* out_topidx = out;
    float* out_ant    = out + M_TOP;
    float* out_mask   = out + M_TOP + M_TOP * K_ANT;
    float* out_score  = out + M_TOP + 2 * M_TOP * K_ANT;

    float *p_span, *p_hid1, *p_topemb, *p_tmp, *p_fast;
    cudaGetSymbolAddress((void**)&p_span,   g_span_emb);
    cudaGetSymbolAddress((void**)&p_hid1,   g_hid1);
    cudaGetSymbolAddress((void**)&p_topemb, g_topemb);
    cudaGetSymbolAddress((void**)&p_tmp,    g_tmp);
    cudaGetSymbolAddress((void**)&p_fast,   g_fast);

    // 1. token logits (fp64 accumulate)
    k_token_logits<<<T_TOK * 32 / 256, 256>>>(hs, w_attn, b_attn);

    // 2. span embeddings (fp64 softmax weights, Kahan fp32 pooling)
    k_span_emb<<<C_SP, 256>>>(hs, starts, widths, w_width);

    // 3. hid1 = relu(span_emb @ w_u1 + b_u1)  [4096,1024]  PLAIN fp32
    //    (round-1 evidence: mention path exact with plain fp32)
    {
        dim3 grid((UHID + 127) / 128, (C_SP + 127) / 128);
        k_gemm<128, 128, 8, 8, 0, true, false, true><<<grid, 256>>>(
            p_span, w_u1, b_u1, p_hid1, C_SP, UHID, SPAND);
    }

    // 4. mention scores (fp64 accumulate)
    k_score<<<C_SP * 32 / 256, 256>>>(w_u2, b_u2);

    // 5. sort + greedy extraction + compact
    cudaFuncSetAttribute(k_extract, cudaFuncAttributeMaxDynamicSharedMemorySize, 65536);
    k_extract<<<1, 1024, 65536>>>(starts, widths);

    // 6. gather top_emb / top_m / write top_idx output
    k_gather<<<M_TOP, 256>>>(out_topidx);

    // 7. tmp = top_emb @ w_fast + b_fast  [1024,3092]  chunk-Kahan
    {
        dim3 grid((SPAND + 63) / 64, (M_TOP + 127) / 128);
        k_gemm<128, 64, 8, 4, 1, false, false, true><<<grid, 256>>>(
            p_topemb, w_fast, b_fast, p_tmp, M_TOP, SPAND, SPAND);
    }

    // 8. fast0 = tmp @ top_emb^T  [1024,1024]  chunk-Kahan NT
    {
        dim3 grid((M_TOP + 63) / 64, (M_TOP + 63) / 64);
        k_gemm<64, 64, 4, 4, 1, false, true, false><<<grid, 256>>>(
            p_tmp, p_topemb, nullptr, p_fast, M_TOP, M_TOP, SPAND);
    }

    // 9. assemble fast matrix + per-row top-50
    k_topk<<<M_TOP, 256>>>(out_ant, out_mask, out_score);

    (void)in_sizes; (void)n_in; (void)out_size;
}

// round 7
// speedup vs baseline: 2.0453x; 1.0391x over previous
#include <cuda_runtime.h>
#include <math.h>
#include <float.h>
#include <stdint.h>

// ---------------- problem constants (fixed shapes) ----------------
#define T_TOK 4096
#define C_SP  4096
#define HID   1024
#define METAF 20
#define SPAND 3092          // 3*HID + METAF
#define UHID  1024
#define M_TOP 1024
#define K_ANT 50
#define NEGV  (-1e30f)

// ---------------- device scratch ----------------------------------
__device__ float g_logits[T_TOK];
__device__ float g_span_emb[(size_t)C_SP * SPAND];
__device__ float g_hid1[(size_t)C_SP * UHID];
__device__ float g_mention[C_SP];
__device__ int   g_topidx[M_TOP];
__device__ float g_topm[M_TOP];
__device__ float g_topemb[(size_t)M_TOP * SPAND];
__device__ float g_tmp[(size_t)M_TOP * SPAND];
__device__ float g_fast[(size_t)M_TOP * M_TOP];

// ---------------- kernel 1: token logits (fp64 accumulate) --------
__global__ void k_token_logits(const float* __restrict__ hs,
                               const float* __restrict__ w_attn,
                               const float* __restrict__ b_attn) {
    int warp = (blockIdx.x * blockDim.x + threadIdx.x) >> 5;
    int lane = threadIdx.x & 31;
    if (warp >= T_TOK) return;
    const float* row = hs + (size_t)warp * HID;
    double acc = 0.0;
    #pragma unroll 8
    for (int i = lane; i < HID; i += 32) acc += (double)row[i] * (double)w_attn[i];
    #pragma unroll
    for (int o = 16; o; o >>= 1) acc += __shfl_xor_sync(0xffffffffu, acc, o);
    if (lane == 0) g_logits[warp] = (float)(acc + (double)b_attn[0]);
}

// ---------------- kernel 2: span embeddings -----------------------
__global__ void k_span_emb(const float* __restrict__ hs,
                           const int* __restrict__ starts,
                           const int* __restrict__ widths,
                           const float* __restrict__ w_width) {
    int c = blockIdx.x;
    int s = starts[c], w = widths[c];
    int e = s + w, L = w + 1;
    __shared__ float p[32];
    int tid = threadIdx.x;
    if (tid < 32) {
        double lg = (tid < L) ? (double)g_logits[s + tid] : -1e300;
        double mx = lg;
        #pragma unroll
        for (int o = 16; o; o >>= 1) {
            double v = __shfl_xor_sync(0xffffffffu, mx, o);
            mx = fmax(mx, v);
        }
        double ex = (tid < L) ? exp(lg - mx) : 0.0;
        double sm = ex;
        #pragma unroll
        for (int o = 16; o; o >>= 1) sm += __shfl_xor_sync(0xffffffffu, sm, o);
        p[tid] = (float)(ex / sm);
    }
    __syncthreads();
    float* out = g_span_emb + (size_t)c * SPAND;
    const float* hrow_s = hs + (size_t)s * HID;
    const float* hrow_e = hs + (size_t)e * HID;
    for (int h = tid; h < HID; h += blockDim.x) {
        out[h]        = hrow_s[h];
        out[HID + h]  = hrow_e[h];
        float acc = 0.f, cmp = 0.f;
        for (int l = 0; l < L; ++l) {
            float y = __fmaf_rn(p[l], hs[(size_t)(s + l) * HID + h], -cmp);
            float t = __fadd_rn(acc, y);
            cmp = __fsub_rn(__fsub_rn(t, acc), y);
            acc = t;
        }
        out[2 * HID + METAF + h] = acc;
    }
    if (tid < METAF) out[2 * HID + tid] = w_width[w * METAF + tid];
}

// ---------------- tf32 helpers ------------------------------------
__device__ __forceinline__ void split_tf32(float x, float& hi, float& lo) {
    unsigned h;
    asm("cvt.rna.tf32.f32 %0, %1;" : "=r"(h) : "f"(x));
    hi = __uint_as_float(h);
    float l = __fsub_rn(x, hi);
    unsigned lb;
    asm("cvt.rna.tf32.f32 %0, %1;" : "=r"(lb) : "f"(l));
    lo = __uint_as_float(lb);
}

__device__ __forceinline__ void mma_tf32(float c[4], const uint4& a, const uint2& b) {
    asm volatile(
        "mma.sync.aligned.m16n8k8.row.col.f32.tf32.tf32.f32 "
        "{%0,%1,%2,%3}, {%4,%5,%6,%7}, {%8,%9}, {%0,%1,%2,%3};"
        : "+f"(c[0]), "+f"(c[1]), "+f"(c[2]), "+f"(c[3])
        : "r"(a.x), "r"(a.y), "r"(a.z), "r"(a.w), "r"(b.x), "r"(b.y));
}

// ---------------- tf32x2 TC GEMM, 3-pass (mention path) -----------
// Block 128x128, 8 warps (4m x 2n), warp tile 32x64.
// Proven: produces exact top_idx (round-6 output 0 == reference).
template<bool NT, bool RELU, bool BIAS>
__global__ __launch_bounds__(256, 1)
void k_gemm_tc(const float* __restrict__ A, const float* __restrict__ B,
               const float* __restrict__ bias, float* __restrict__ C,
               int M, int N, int K) {
    __shared__ float sAh[2][8][32][4];
    __shared__ float sAl[2][8][32][4];
    __shared__ float sBh[2][16][32][2];
    __shared__ float sBl[2][16][32][2];

    const int tid   = threadIdx.x;
    const int lane  = tid & 31;
    const int wid   = tid >> 5;
    const int warp_m = wid >> 1;
    const int warp_n = wid & 1;
    const int row0 = blockIdx.y * 128;
    const int col0 = blockIdx.x * 128;

    float c[2][8][4];
    #pragma unroll
    for (int ma = 0; ma < 2; ++ma)
        #pragma unroll
        for (int nb = 0; nb < 8; ++nb)
            #pragma unroll
            for (int q = 0; q < 4; ++q) c[ma][nb][q] = 0.f;

    for (int k0 = 0; k0 < K; k0 += 16) {
        #pragma unroll
        for (int it = tid; it < 512; it += 256) {
            int r = it >> 2;
            int q = it & 3;
            int gk0 = k0 + q * 4;
            float4 v = make_float4(0.f, 0.f, 0.f, 0.f);
            if (gk0 + 3 < K)
                v = *(const float4*)&A[(size_t)(row0 + r) * K + gk0];
            float xs[4] = {v.x, v.y, v.z, v.w};
            int matom = r >> 4, rr = r & 15;
            #pragma unroll
            for (int j = 0; j < 4; ++j) {
                int kk = q * 4 + j;
                int k8 = kk >> 3, kc = kk & 7;
                int reg = ((kc >> 2) << 1) | (rr >> 3);
                int ln  = ((rr & 7) << 2) | (kc & 3);
                float hi, lo; split_tf32(xs[j], hi, lo);
                sAh[k8][matom][ln][reg] = hi;
                sAl[k8][matom][ln][reg] = lo;
            }
        }
        if (!NT) {
            #pragma unroll
            for (int it = tid; it < 512; it += 256) {
                int kk = it >> 5;
                int q  = it & 31;
                int gk = k0 + kk;
                int gn0 = col0 + q * 4;
                float4 v = make_float4(0.f, 0.f, 0.f, 0.f);
                if (gk < K && gn0 + 3 < N)
                    v = *(const float4*)&B[(size_t)gk * N + gn0];
                float xs[4] = {v.x, v.y, v.z, v.w};
                int k8 = kk >> 3, kc = kk & 7;
                int reg = kc >> 2;
                #pragma unroll
                for (int j = 0; j < 4; ++j) {
                    int n = q * 4 + j;
                    int natom = n >> 3, nn = n & 7;
                    int ln = (nn << 2) | (kc & 3);
                    float hi, lo; split_tf32(xs[j], hi, lo);
                    sBh[k8][natom][ln][reg] = hi;
                    sBl[k8][natom][ln][reg] = lo;
                }
            }
        } else {
            #pragma unroll
            for (int it = tid; it < 512; it += 256) {
                int n = it >> 2;
                int q = it & 3;
                int gn = col0 + n;
                int gk0 = k0 + q * 4;
                float4 v = make_float4(0.f, 0.f, 0.f, 0.f);
                if (gn < N && gk0 + 3 < K)
                    v = *(const float4*)&B[(size_t)gn * K + gk0];
                float xs[4] = {v.x, v.y, v.z, v.w};
                int natom = n >> 3, nn = n & 7;
                #pragma unroll
                for (int j = 0; j < 4; ++j) {
                    int kk = q * 4 + j;
                    int k8 = kk >> 3, kc = kk & 7;
                    int reg = kc >> 2;
                    int ln = (nn << 2) | (kc & 3);
                    float hi, lo; split_tf32(xs[j], hi, lo);
                    sBh[k8][natom][ln][reg] = hi;
                    sBl[k8][natom][ln][reg] = lo;
                }
            }
        }
        __syncthreads();

        #pragma unroll
        for (int k8 = 0; k8 < 2; ++k8) {
            uint4 ah[2], al[2];
            #pragma unroll
            for (int ma = 0; ma < 2; ++ma) {
                ah[ma] = *(const uint4*)&sAh[k8][warp_m * 2 + ma][lane][0];
                al[ma] = *(const uint4*)&sAl[k8][warp_m * 2 + ma][lane][0];
            }
            uint2 bh[8], bl[8];
            #pragma unroll
            for (int nb = 0; nb < 8; ++nb) {
                bh[nb] = *(const uint2*)&sBh[k8][warp_n * 8 + nb][lane][0];
                bl[nb] = *(const uint2*)&sBl[k8][warp_n * 8 + nb][lane][0];
            }
            #pragma unroll
            for (int ma = 0; ma < 2; ++ma)
                #pragma unroll
                for (int nb = 0; nb < 8; ++nb) {
                    mma_tf32(c[ma][nb], ah[ma], bh[nb]);
                    mma_tf32(c[ma][nb], ah[ma], bl[nb]);
                    mma_tf32(c[ma][nb], al[ma], bh[nb]);
                }
        }
        __syncthreads();
    }

    const int g = lane >> 2, t = lane & 3;
    #pragma unroll
    for (int ma = 0; ma < 2; ++ma) {
        int r0 = row0 + (warp_m * 2 + ma) * 16 + g;
        #pragma unroll
        for (int nb = 0; nb < 8; ++nb) {
            int cc = col0 + (warp_n * 8 + nb) * 8 + 2 * t;
            if (cc >= N) continue;
            float v0 = c[ma][nb][0], v1 = c[ma][nb][1];
            float v2 = c[ma][nb][2], v3 = c[ma][nb][3];
            if (BIAS) {
                float b0 = bias[cc], b1 = bias[cc + 1];
                v0 = __fadd_rn(v0, b0); v1 = __fadd_rn(v1, b1);
                v2 = __fadd_rn(v2, b0); v3 = __fadd_rn(v3, b1);
            }
            if (RELU) {
                v0 = fmaxf(v0, 0.f); v1 = fmaxf(v1, 0.f);
                v2 = fmaxf(v2, 0.f); v3 = fmaxf(v3, 0.f);
            }
            if (r0 < M) *(float2*)&C[(size_t)r0 * N + cc] = make_float2(v0, v1);
            if (r0 + 8 < M) *(float2*)&C[(size_t)(r0 + 8) * N + cc] = make_float2(v2, v3);
        }
    }
}

// ---------------- tf32x2 TC GEMM, 4-pass + per-tile Kahan ---------
// Antecedent-score path: needs noise < ~2e-5 on a 3092-length dot.
// 4 MMA passes (hh+hl+lh+ll, no dropped term) accumulate into a
// per-16k-tile local accumulator, folded exactly (Kahan) into the
// master sum -> noise ~1.4e-5 (vs ~1e-4 for straight 3-pass, which
// flipped 4 ranks in round 6).
// Block 128x64, 8 warps (4m x 2n), warp tile 32x32 (2m x 4n atoms).
template<bool NT, bool BIAS>
__global__ __launch_bounds__(256, 1)
void k_gemm_tc4(const float* __restrict__ A, const float* __restrict__ B,
                const float* __restrict__ bias, float* __restrict__ C,
                int M, int N, int K) {
    __shared__ float sAh[2][8][32][4];
    __shared__ float sAl[2][8][32][4];
    __shared__ float sBh[2][8][32][2];
    __shared__ float sBl[2][8][32][2];

    const int tid   = threadIdx.x;
    const int lane  = tid & 31;
    const int wid   = tid >> 5;
    const int warp_m = wid >> 1;          // 0..3
    const int warp_n = wid & 1;           // 0..1
    const int row0 = blockIdx.y * 128;
    const int col0 = blockIdx.x * 64;

    float acc[2][4][4], cmp[2][4][4];
    #pragma unroll
    for (int ma = 0; ma < 2; ++ma)
        #pragma unroll
        for (int nb = 0; nb < 4; ++nb)
            #pragma unroll
            for (int q = 0; q < 4; ++q) { acc[ma][nb][q] = 0.f; cmp[ma][nb][q] = 0.f; }

    for (int k0 = 0; k0 < K; k0 += 16) {
        // A tile 128x16
        #pragma unroll
        for (int it = tid; it < 512; it += 256) {
            int r = it >> 2;
            int q = it & 3;
            int gk0 = k0 + q * 4;
            float4 v = make_float4(0.f, 0.f, 0.f, 0.f);
            if (gk0 + 3 < K)
                v = *(const float4*)&A[(size_t)(row0 + r) * K + gk0];
            float xs[4] = {v.x, v.y, v.z, v.w};
            int matom = r >> 4, rr = r & 15;
            #pragma unroll
            for (int j = 0; j < 4; ++j) {
                int kk = q * 4 + j;
                int k8 = kk >> 3, kc = kk & 7;
                int reg = ((kc >> 2) << 1) | (rr >> 3);
                int ln  = ((rr & 7) << 2) | (kc & 3);
                float hi, lo; split_tf32(xs[j], hi, lo);
                sAh[k8][matom][ln][reg] = hi;
                sAl[k8][matom][ln][reg] = lo;
            }
        }
        // B tile 16x64
        if (!NT) {
            for (int it = tid; it < 256; it += 256) {
                int kk = it >> 4;           // 0..15
                int q  = it & 15;           // 0..15 (float4 across 64 cols)
                int gk = k0 + kk;
                int gn0 = col0 + q * 4;
                float4 v = make_float4(0.f, 0.f, 0.f, 0.f);
                if (gk < K && gn0 + 3 < N)
                    v = *(const float4*)&B[(size_t)gk * N + gn0];
                float xs[4] = {v.x, v.y, v.z, v.w};
                int k8 = kk >> 3, kc = kk & 7;
                int reg = kc >> 2;
                #pragma unroll
                for (int j = 0; j < 4; ++j) {
                    int n = q * 4 + j;
                    int natom = n >> 3, nn = n & 7;
                    int ln = (nn << 2) | (kc & 3);
                    float hi, lo; split_tf32(xs[j], hi, lo);
                    sBh[k8][natom][ln][reg] = hi;
                    sBl[k8][natom][ln][reg] = lo;
                }
            }
        } else {
            for (int it = tid; it < 256; it += 256) {
                int n = it >> 2;            // 0..63
                int q = it & 3;
                int gn = col0 + n;
                int gk0 = k0 + q * 4;
                float4 v = make_float4(0.f, 0.f, 0.f, 0.f);
                if (gn < N && gk0 + 3 < K)
                    v = *(const float4*)&B[(size_t)gn * K + gk0];
                float xs[4] = {v.x, v.y, v.z, v.w};
                int natom = n >> 3, nn = n & 7;
                #pragma unroll
                for (int j = 0; j < 4; ++j) {
                    int kk = q * 4 + j;
                    int k8 = kk >> 3, kc = kk & 7;
                    int reg = kc >> 2;
                    int ln = (nn << 2) | (kc & 3);
                    float hi, lo; split_tf32(xs[j], hi, lo);
                    sBh[k8][natom][ln][reg] = hi;
                    sBl[k8][natom][ln][reg] = lo;
                }
            }
        }
        __syncthreads();

        // per-tile local accumulator
        float loc[2][4][4];
        #pragma unroll
        for (int ma = 0; ma < 2; ++ma)
            #pragma unroll
            for (int nb = 0; nb < 4; ++nb)
                #pragma unroll
                for (int q = 0; q < 4; ++q) loc[ma][nb][q] = 0.f;

        #pragma unroll
        for (int k8 = 0; k8 < 2; ++k8) {
            uint4 ah[2], al[2];
            #pragma unroll
            for (int ma = 0; ma < 2; ++ma) {
                ah[ma] = *(const uint4*)&sAh[k8][warp_m * 2 + ma][lane][0];
                al[ma] = *(const uint4*)&sAl[k8][warp_m * 2 + ma][lane][0];
            }
            uint2 bh[4], bl[4];
            #pragma unroll
            for (int nb = 0; nb < 4; ++nb) {
                bh[nb] = *(const uint2*)&sBh[k8][warp_n * 4 + nb][lane][0];
                bl[nb] = *(const uint2*)&sBl[k8][warp_n * 4 + nb][lane][0];
            }
            #pragma unroll
            for (int ma = 0; ma < 2; ++ma)
                #pragma unroll
                for (int nb = 0; nb < 4; ++nb) {
                    mma_tf32(loc[ma][nb], ah[ma], bh[nb]);
                    mma_tf32(loc[ma][nb], ah[ma], bl[nb]);
                    mma_tf32(loc[ma][nb], al[ma], bh[nb]);
                    mma_tf32(loc[ma][nb], al[ma], bl[nb]);
                }
        }

        // exact Kahan fold of tile partial into master
        #pragma unroll
        for (int ma = 0; ma < 2; ++ma)
            #pragma unroll
            for (int nb = 0; nb < 4; ++nb)
                #pragma unroll
                for (int q = 0; q < 4; ++q) {
                    float y = __fsub_rn(loc[ma][nb][q], cmp[ma][nb][q]);
                    float t = __fadd_rn(acc[ma][nb][q], y);
                    cmp[ma][nb][q] = __fsub_rn(__fsub_rn(t, acc[ma][nb][q]), y);
                    acc[ma][nb][q] = t;
                }
        __syncthreads();
    }

    const int g = lane >> 2, t = lane & 3;
    #pragma unroll
    for (int ma = 0; ma < 2; ++ma) {
        int r0 = row0 + (warp_m * 2 + ma) * 16 + g;
        #pragma unroll
        for (int nb = 0; nb < 4; ++nb) {
            int cc = col0 + (warp_n * 4 + nb) * 8 + 2 * t;
            if (cc >= N) continue;
            float v0 = acc[ma][nb][0], v1 = acc[ma][nb][1];
            float v2 = acc[ma][nb][2], v3 = acc[ma][nb][3];
            if (BIAS) {
                float b0 = bias[cc], b1 = bias[cc + 1];
                v0 = __fadd_rn(v0, b0); v1 = __fadd_rn(v1, b1);
                v2 = __fadd_rn(v2, b0); v3 = __fadd_rn(v3, b1);
            }
            if (r0 < M) *(float2*)&C[(size_t)r0 * N + cc] = make_float2(v0, v1);
            if (r0 + 8 < M) *(float2*)&C[(size_t)(r0 + 8) * N + cc] = make_float2(v2, v3);
        }
    }
}

// ---------------- kernel: mention score (fp64 accumulate) ---------
__global__ void k_score(const float* __restrict__ w_u2,
                        const float* __restrict__ b_u2) {
    int warp = (blockIdx.x * blockDim.x + threadIdx.x) >> 5;
    int lane = threadIdx.x & 31;
    if (warp >= C_SP) return;
    const float* row = g_hid1 + (size_t)warp * UHID;
    double acc = 0.0;
    #pragma unroll 8
    for (int i = lane; i < UHID; i += 32) acc += (double)row[i] * (double)w_u2[i];
    #pragma unroll
    for (int o = 16; o; o >>= 1) acc += __shfl_xor_sync(0xffffffffu, acc, o);
    if (lane == 0) g_mention[warp] = (float)(acc + (double)b_u2[0]);
}

// ---------------- kernel: sort + greedy non-crossing + compact ----
__global__ void k_extract(const int* __restrict__ starts,
                          const int* __restrict__ widths) {
    extern __shared__ int sh[];
    float* key = (float*)sh;
    int* idx = sh + 4096;
    int* es  = sh + 8192;
    int* flg = sh + 12288;
    const int tid = threadIdx.x;       // 1024 threads

    for (int i = tid; i < C_SP; i += 1024) {
        key[i] = g_mention[i];
        idx[i] = i;
        flg[i] = 0;
    }
    __syncthreads();

    for (unsigned k = 2; k <= 4096; k <<= 1) {
        for (unsigned j = k >> 1; j > 0; j >>= 1) {
            for (unsigned t = tid; t < 2048; t += 1024) {
                unsigned i = ((t & ~(j - 1)) << 1) | (t & (j - 1));
                unsigned l = i | j;
                float ki = key[i], kl = key[l];
                int   ii = idx[i], il = idx[l];
                bool before_l_i = (kl > ki) || (kl == ki && il < ii);
                bool dir = ((i & k) == 0);
                if (before_l_i == dir) {
                    key[i] = kl; key[l] = ki;
                    idx[i] = il; idx[l] = ii;
                }
            }
            __syncthreads();
        }
    }

    volatile int* le = (volatile int*)key;
    volatile int* ves = (volatile int*)es;
    for (int i = tid; i < T_TOK; i += 1024) {
        ((int*)key)[i] = -1;
        es[i] = T_TOK;
    }
    __syncthreads();

    if (tid < 32) {
        int lane = tid;
        int count = 0;
        for (int p = 0; p < C_SP && count < M_TOP; ++p) {
            int ci = idx[p];
            int s = starts[ci];
            int w = widths[ci];
            int e = s + w;
            bool crossing = false;
            if (lane < w) {
                crossing = (le[s + 1 + lane] > e) | (ves[s + lane] < s);
            }
            unsigned m = __ballot_sync(0xffffffffu, crossing);
            if (m == 0u) {
                if (lane == 0) {
                    int cur = le[s]; if (e > cur) ((int*)key)[s] = e;
                    int cur2 = ves[e]; if (s < cur2) es[e] = s;
                    flg[ci] = 1;
                }
                count++;
            }
            __syncwarp();
        }
    }
    __syncthreads();

    __shared__ int wsum[32];
    __shared__ int woff[33];
    int base = tid * 4;
    int f0 = flg[base], f1 = flg[base + 1], f2 = flg[base + 2], f3 = flg[base + 3];
    int c = f0 + f1 + f2 + f3;
    int inc = c;
    int lane = tid & 31, wid = tid >> 5;
    #pragma unroll
    for (int o = 1; o < 32; o <<= 1) {
        int n = __shfl_up_sync(0xffffffffu, inc, o);
        if (lane >= o) inc += n;
    }
    if (lane == 31) wsum[wid] = inc;
    __syncthreads();
    if (tid == 0) {
        int run = 0;
        for (int i = 0; i < 32; ++i) { woff[i] = run; run += wsum[i]; }
        woff[32] = run;
    }
    __syncthreads();
    int pos = woff[wid] + (inc - c);
    if (f0) { if (pos < M_TOP) g_topidx[pos] = base;     pos++; }
    if (f1) { if (pos < M_TOP) g_topidx[pos] = base + 1; pos++; }
    if (f2) { if (pos < M_TOP) g_topidx[pos] = base + 2; pos++; }
    if (f3) { if (pos < M_TOP) g_topidx[pos] = base + 3; pos++; }
    int total = woff[32];
    for (int p = total + tid; p < M_TOP; p += 1024) g_topidx[p] = C_SP - 1;
}

// ---------------- kernel: gather top spans ------------------------
__global__ void k_gather(float* __restrict__ out_topidx) {
    int p = blockIdx.x;
    int ci = g_topidx[p];
    if (threadIdx.x == 0) {
        g_topm[p] = g_mention[ci];
        out_topidx[p] = (float)ci;
    }
    const float4* src = (const float4*)(g_span_emb + (size_t)ci * SPAND);
    float4* dst = (float4*)(g_topemb + (size_t)p * SPAND);
    for (int i = threadIdx.x; i < SPAND / 4; i += blockDim.x) dst[i] = src[i];
}

// ---------------- kernel: assemble fast scores + per-row top-50 ---
__global__ void k_topk(float* __restrict__ out_ant,
                       float* __restrict__ out_mask,
                       float* __restrict__ out_score) {
    __shared__ float v[M_TOP];
    __shared__ float rv[256];
    __shared__ int   ri[256];
    const int i = blockIdx.x;
    const int tid = threadIdx.x;
    const float mi = g_topm[i];
    for (int j = tid; j < M_TOP; j += 256) {
        float val = __fadd_rn(__fadd_rn(__fadd_rn(mi, g_topm[j]),
                                        (j < i) ? 0.f : NEGV),
                              g_fast[(size_t)i * M_TOP + j]);
        v[j] = val;
    }
    __syncthreads();
    for (int k = 0; k < K_ANT; ++k) {
        float bv = -INFINITY; int bi = M_TOP;
        for (int j = tid; j < M_TOP; j += 256) {
            float x = v[j];
            if (x > bv || (x == bv && j < bi)) { bv = x; bi = j; }
        }
        rv[tid] = bv; ri[tid] = bi;
        __syncthreads();
        for (int s = 128; s > 0; s >>= 1) {
            if (tid < s) {
                if (rv[tid + s] > rv[tid] ||
                    (rv[tid + s] == rv[tid] && ri[tid + s] < ri[tid])) {
                    rv[tid] = rv[tid + s]; ri[tid] = ri[tid + s];
                }
            }
            __syncthreads();
        }
        if (tid == 0) {
            int j = ri[0];
            out_ant[(size_t)i * K_ANT + k]   = (float)j;
            out_mask[(size_t)i * K_ANT + k]  = (j < i) ? 1.f : 0.f;
            out_score[(size_t)i * K_ANT + k] = rv[0];
            v[j] = -INFINITY;
        }
        __syncthreads();
    }
}

// ---------------- launch ------------------------------------------
extern "C" void kernel_launch(void* const* d_in, const int* in_sizes, int n_in,
                              void* d_out, int out_size) {
    const float* hs      = (const float*)d_in[0];
    const int*   starts  = (const int*)d_in[1];
    const int*   widths  = (const int*)d_in[2];
    int base = 3;
    if (n_in >= 14 && in_sizes[3] == 1 && in_sizes[4] == 1) base = 5;
    const float* w_width = (const float*)d_in[base + 0];
    const float* w_attn  = (const float*)d_in[base + 1];
    const float* b_attn  = (const float*)d_in[base + 2];
    const float* w_u1    = (const float*)d_in[base + 3];
    const float* b_u1    = (const float*)d_in[base + 4];
    const float* w_u2    = (const float*)d_in[base + 5];
    const float* b_u2    = (const float*)d_in[base + 6];
    const float* w_fast  = (const float*)d_in[base + 7];
    const float* b_fast  = (const float*)d_in[base + 8];

    float* out = (float*)d_out;
    float* out_topidx = out;
    float* out_ant    = out + M_TOP;
    float* out_mask   = out + M_TOP + M_TOP * K_ANT;
    float* out_score  = out + M_TOP + 2 * M_TOP * K_ANT;

    float *p_span, *p_hid1, *p_topemb, *p_tmp, *p_fast;
    cudaGetSymbolAddress((void**)&p_span,   g_span_emb);
    cudaGetSymbolAddress((void**)&p_hid1,   g_hid1);
    cudaGetSymbolAddress((void**)&p_topemb, g_topemb);
    cudaGetSymbolAddress((void**)&p_tmp,    g_tmp);
    cudaGetSymbolAddress((void**)&p_fast,   g_fast);

    // 1. token logits (fp64 accumulate)
    k_token_logits<<<T_TOK * 32 / 256, 256>>>(hs, w_attn, b_attn);

    // 2. span embeddings
    k_span_emb<<<C_SP, 256>>>(hs, starts, widths, w_width);

    // 3. hid1 = relu(span_emb @ w_u1 + b_u1)  [4096,1024]  tf32x2 3-pass
    {
        dim3 grid(UHID / 128, C_SP / 128);
        k_gemm_tc<false, true, true><<<grid, 256>>>(
            p_span, w_u1, b_u1, p_hid1, C_SP, UHID, SPAND);
    }

    // 4. mention scores (fp64 accumulate)
    k_score<<<C_SP * 32 / 256, 256>>>(w_u2, b_u2);

    // 5. sort + greedy extraction + compact
    cudaFuncSetAttribute(k_extract, cudaFuncAttributeMaxDynamicSharedMemorySize, 65536);
    k_extract<<<1, 1024, 65536>>>(starts, widths);

    // 6. gather top_emb / top_m / write top_idx output
    k_gather<<<M_TOP, 256>>>(out_topidx);

    // 7. tmp = top_emb @ w_fast + b_fast  [1024,3092]  tf32x2 4-pass Kahan
    {
        dim3 grid((SPAND + 63) / 64, M_TOP / 128);       // 49 x 8
        k_gemm_tc4<false, true><<<grid, 256>>>(
            p_topemb, w_fast, b_fast, p_tmp, M_TOP, SPAND, SPAND);
    }

    // 8. fast0 = tmp @ top_emb^T  [1024,1024]  tf32x2 4-pass Kahan (NT)
    {
        dim3 grid(M_TOP / 64, M_TOP / 128);              // 16 x 8
        k_gemm_tc4<true, false><<<grid, 256>>>(
            p_tmp, p_topemb, nullptr, p_fast, M_TOP, M_TOP, SPAND);
    }

    // 9. assemble fast matrix + per-row top-50
    k_topk<<<M_TOP, 256>>>(out_ant, out_mask, out_score);

    (void)in_sizes; (void)n_in; (void)out_size;
}

// round 8
// speedup vs baseline: 2.0465x; 1.0006x over previous
#include <cuda_runtime.h>
#include <math.h>
#include <float.h>
#include <stdint.h>

// ---------------- problem constants (fixed shapes) ----------------
#define T_TOK 4096
#define C_SP  4096
#define HID   1024
#define METAF 20
#define SPAND 3092          // 3*HID + METAF
#define UHID  1024
#define M_TOP 1024
#define K_ANT 50
#define NEGV  (-1e30f)

// ---------------- device scratch ----------------------------------
__device__ float g_logits[T_TOK];
__device__ float g_span_emb[(size_t)C_SP * SPAND];
__device__ float g_hid1[(size_t)C_SP * UHID];
__device__ float g_mention[C_SP];
__device__ int   g_topidx[M_TOP];
__device__ float g_topm[M_TOP];
__device__ float g_topemb[(size_t)M_TOP * SPAND];
__device__ float g_tmp[(size_t)M_TOP * SPAND];
__device__ float g_fast[(size_t)M_TOP * M_TOP];

// ---------------- kernel 1: token logits (fp64 accumulate) --------
__global__ void k_token_logits(const float* __restrict__ hs,
                               const float* __restrict__ w_attn,
                               const float* __restrict__ b_attn) {
    int warp = (blockIdx.x * blockDim.x + threadIdx.x) >> 5;
    int lane = threadIdx.x & 31;
    if (warp >= T_TOK) return;
    const float* row = hs + (size_t)warp * HID;
    double acc = 0.0;
    #pragma unroll 8
    for (int i = lane; i < HID; i += 32) acc += (double)row[i] * (double)w_attn[i];
    #pragma unroll
    for (int o = 16; o; o >>= 1) acc += __shfl_xor_sync(0xffffffffu, acc, o);
    if (lane == 0) g_logits[warp] = (float)(acc + (double)b_attn[0]);
}

// ---------------- kernel 2: span embeddings -----------------------
__global__ void k_span_emb(const float* __restrict__ hs,
                           const int* __restrict__ starts,
                           const int* __restrict__ widths,
                           const float* __restrict__ w_width) {
    int c = blockIdx.x;
    int s = starts[c], w = widths[c];
    int e = s + w, L = w + 1;
    __shared__ float p[32];
    int tid = threadIdx.x;
    if (tid < 32) {
        double lg = (tid < L) ? (double)g_logits[s + tid] : -1e300;
        double mx = lg;
        #pragma unroll
        for (int o = 16; o; o >>= 1) {
            double v = __shfl_xor_sync(0xffffffffu, mx, o);
            mx = fmax(mx, v);
        }
        double ex = (tid < L) ? exp(lg - mx) : 0.0;
        double sm = ex;
        #pragma unroll
        for (int o = 16; o; o >>= 1) sm += __shfl_xor_sync(0xffffffffu, sm, o);
        p[tid] = (float)(ex / sm);
    }
    __syncthreads();
    float* out = g_span_emb + (size_t)c * SPAND;
    const float* hrow_s = hs + (size_t)s * HID;
    const float* hrow_e = hs + (size_t)e * HID;
    for (int h = tid; h < HID; h += blockDim.x) {
        out[h]        = hrow_s[h];
        out[HID + h]  = hrow_e[h];
        float acc = 0.f, cmp = 0.f;
        for (int l = 0; l < L; ++l) {
            float y = __fmaf_rn(p[l], hs[(size_t)(s + l) * HID + h], -cmp);
            float t = __fadd_rn(acc, y);
            cmp = __fsub_rn(__fsub_rn(t, acc), y);
            acc = t;
        }
        out[2 * HID + METAF + h] = acc;
    }
    if (tid < METAF) out[2 * HID + tid] = w_width[w * METAF + tid];
}

// ---------------- tf32 helpers ------------------------------------
__device__ __forceinline__ void split_tf32(float x, float& hi, float& lo) {
    unsigned h;
    asm("cvt.rna.tf32.f32 %0, %1;" : "=r"(h) : "f"(x));
    hi = __uint_as_float(h);
    float l = __fsub_rn(x, hi);
    unsigned lb;
    asm("cvt.rna.tf32.f32 %0, %1;" : "=r"(lb) : "f"(l));
    lo = __uint_as_float(lb);
}

__device__ __forceinline__ void mma_tf32(float c[4], const uint4& a, const uint2& b) {
    asm volatile(
        "mma.sync.aligned.m16n8k8.row.col.f32.tf32.tf32.f32 "
        "{%0,%1,%2,%3}, {%4,%5,%6,%7}, {%8,%9}, {%0,%1,%2,%3};"
        : "+f"(c[0]), "+f"(c[1]), "+f"(c[2]), "+f"(c[3])
        : "r"(a.x), "r"(a.y), "r"(a.z), "r"(a.w), "r"(b.x), "r"(b.y));
}

// ---------------- tf32x2 TC GEMM, 3-pass (mention path) -----------
// Block 128x128, 8 warps (4m x 2n), warp tile 32x64.
// Proven: produces exact top_idx (round-6 output 0 == reference).
template<bool NT, bool RELU, bool BIAS>
__global__ __launch_bounds__(256, 1)
void k_gemm_tc(const float* __restrict__ A, const float* __restrict__ B,
               const float* __restrict__ bias, float* __restrict__ C,
               int M, int N, int K) {
    __shared__ float sAh[2][8][32][4];
    __shared__ float sAl[2][8][32][4];
    __shared__ float sBh[2][16][32][2];
    __shared__ float sBl[2][16][32][2];

    const int tid   = threadIdx.x;
    const int lane  = tid & 31;
    const int wid   = tid >> 5;
    const int warp_m = wid >> 1;
    const int warp_n = wid & 1;
    const int row0 = blockIdx.y * 128;
    const int col0 = blockIdx.x * 128;

    float c[2][8][4];
    #pragma unroll
    for (int ma = 0; ma < 2; ++ma)
        #pragma unroll
        for (int nb = 0; nb < 8; ++nb)
            #pragma unroll
            for (int q = 0; q < 4; ++q) c[ma][nb][q] = 0.f;

    for (int k0 = 0; k0 < K; k0 += 16) {
        #pragma unroll
        for (int it = tid; it < 512; it += 256) {
            int r = it >> 2;
            int q = it & 3;
            int gk0 = k0 + q * 4;
            float4 v = make_float4(0.f, 0.f, 0.f, 0.f);
            if (gk0 + 3 < K)
                v = *(const float4*)&A[(size_t)(row0 + r) * K + gk0];
            float xs[4] = {v.x, v.y, v.z, v.w};
            int matom = r >> 4, rr = r & 15;
            #pragma unroll
            for (int j = 0; j < 4; ++j) {
                int kk = q * 4 + j;
                int k8 = kk >> 3, kc = kk & 7;
                int reg = ((kc >> 2) << 1) | (rr >> 3);
                int ln  = ((rr & 7) << 2) | (kc & 3);
                float hi, lo; split_tf32(xs[j], hi, lo);
                sAh[k8][matom][ln][reg] = hi;
                sAl[k8][matom][ln][reg] = lo;
            }
        }
        if (!NT) {
            #pragma unroll
            for (int it = tid; it < 512; it += 256) {
                int kk = it >> 5;
                int q  = it & 31;
                int gk = k0 + kk;
                int gn0 = col0 + q * 4;
                float4 v = make_float4(0.f, 0.f, 0.f, 0.f);
                if (gk < K && gn0 + 3 < N)
                    v = *(const float4*)&B[(size_t)gk * N + gn0];
                float xs[4] = {v.x, v.y, v.z, v.w};
                int k8 = kk >> 3, kc = kk & 7;
                int reg = kc >> 2;
                #pragma unroll
                for (int j = 0; j < 4; ++j) {
                    int n = q * 4 + j;
                    int natom = n >> 3, nn = n & 7;
                    int ln = (nn << 2) | (kc & 3);
                    float hi, lo; split_tf32(xs[j], hi, lo);
                    sBh[k8][natom][ln][reg] = hi;
                    sBl[k8][natom][ln][reg] = lo;
                }
            }
        } else {
            #pragma unroll
            for (int it = tid; it < 512; it += 256) {
                int n = it >> 2;
                int q = it & 3;
                int gn = col0 + n;
                int gk0 = k0 + q * 4;
                float4 v = make_float4(0.f, 0.f, 0.f, 0.f);
                if (gn < N && gk0 + 3 < K)
                    v = *(const float4*)&B[(size_t)gn * K + gk0];
                float xs[4] = {v.x, v.y, v.z, v.w};
                int natom = n >> 3, nn = n & 7;
                #pragma unroll
                for (int j = 0; j < 4; ++j) {
                    int kk = q * 4 + j;
                    int k8 = kk >> 3, kc = kk & 7;
                    int reg = kc >> 2;
                    int ln = (nn << 2) | (kc & 3);
                    float hi, lo; split_tf32(xs[j], hi, lo);
                    sBh[k8][natom][ln][reg] = hi;
                    sBl[k8][natom][ln][reg] = lo;
                }
            }
        }
        __syncthreads();

        #pragma unroll
        for (int k8 = 0; k8 < 2; ++k8) {
            uint4 ah[2], al[2];
            #pragma unroll
            for (int ma = 0; ma < 2; ++ma) {
                ah[ma] = *(const uint4*)&sAh[k8][warp_m * 2 + ma][lane][0];
                al[ma] = *(const uint4*)&sAl[k8][warp_m * 2 + ma][lane][0];
            }
            uint2 bh[8], bl[8];
            #pragma unroll
            for (int nb = 0; nb < 8; ++nb) {
                bh[nb] = *(const uint2*)&sBh[k8][warp_n * 8 + nb][lane][0];
                bl[nb] = *(const uint2*)&sBl[k8][warp_n * 8 + nb][lane][0];
            }
            #pragma unroll
            for (int ma = 0; ma < 2; ++ma)
                #pragma unroll
                for (int nb = 0; nb < 8; ++nb) {
                    mma_tf32(c[ma][nb], ah[ma], bh[nb]);
                    mma_tf32(c[ma][nb], ah[ma], bl[nb]);
                    mma_tf32(c[ma][nb], al[ma], bh[nb]);
                }
        }
        __syncthreads();
    }

    const int g = lane >> 2, t = lane & 3;
    #pragma unroll
    for (int ma = 0; ma < 2; ++ma) {
        int r0 = row0 + (warp_m * 2 + ma) * 16 + g;
        #pragma unroll
        for (int nb = 0; nb < 8; ++nb) {
            int cc = col0 + (warp_n * 8 + nb) * 8 + 2 * t;
            if (cc >= N) continue;
            float v0 = c[ma][nb][0], v1 = c[ma][nb][1];
            float v2 = c[ma][nb][2], v3 = c[ma][nb][3];
            if (BIAS) {
                float b0 = bias[cc], b1 = bias[cc + 1];
                v0 = __fadd_rn(v0, b0); v1 = __fadd_rn(v1, b1);
                v2 = __fadd_rn(v2, b0); v3 = __fadd_rn(v3, b1);
            }
            if (RELU) {
                v0 = fmaxf(v0, 0.f); v1 = fmaxf(v1, 0.f);
                v2 = fmaxf(v2, 0.f); v3 = fmaxf(v3, 0.f);
            }
            if (r0 < M) *(float2*)&C[(size_t)r0 * N + cc] = make_float2(v0, v1);
            if (r0 + 8 < M) *(float2*)&C[(size_t)(r0 + 8) * N + cc] = make_float2(v2, v3);
        }
    }
}

// ---------------- tf32x2 TC GEMM, 4-pass + per-tile Kahan ---------
// Antecedent-score path: needs noise < ~2e-5 on a 3092-length dot.
// 4 MMA passes (hh+hl+lh+ll, no dropped term) accumulate into a
// per-16k-tile local accumulator, folded exactly (Kahan) into the
// master sum -> noise ~1.4e-5 (vs ~1e-4 for straight 3-pass, which
// flipped 4 ranks in round 6).
// Block 128x64, 8 warps (4m x 2n), warp tile 32x32 (2m x 4n atoms).
template<bool NT, bool BIAS>
__global__ __launch_bounds__(256, 1)
void k_gemm_tc4(const float* __restrict__ A, const float* __restrict__ B,
                const float* __restrict__ bias, float* __restrict__ C,
                int M, int N, int K) {
    __shared__ float sAh[2][8][32][4];
    __shared__ float sAl[2][8][32][4];
    __shared__ float sBh[2][8][32][2];
    __shared__ float sBl[2][8][32][2];

    const int tid   = threadIdx.x;
    const int lane  = tid & 31;
    const int wid   = tid >> 5;
    const int warp_m = wid >> 1;          // 0..3
    const int warp_n = wid & 1;           // 0..1
    const int row0 = blockIdx.y * 128;
    const int col0 = blockIdx.x * 64;

    float acc[2][4][4], cmp[2][4][4];
    #pragma unroll
    for (int ma = 0; ma < 2; ++ma)
        #pragma unroll
        for (int nb = 0; nb < 4; ++nb)
            #pragma unroll
            for (int q = 0; q < 4; ++q) { acc[ma][nb][q] = 0.f; cmp[ma][nb][q] = 0.f; }

    for (int k0 = 0; k0 < K; k0 += 16) {
        // A tile 128x16
        #pragma unroll
        for (int it = tid; it < 512; it += 256) {
            int r = it >> 2;
            int q = it & 3;
            int gk0 = k0 + q * 4;
            float4 v = make_float4(0.f, 0.f, 0.f, 0.f);
            if (gk0 + 3 < K)
                v = *(const float4*)&A[(size_t)(row0 + r) * K + gk0];
            float xs[4] = {v.x, v.y, v.z, v.w};
            int matom = r >> 4, rr = r & 15;
            #pragma unroll
            for (int j = 0; j < 4; ++j) {
                int kk = q * 4 + j;
                int k8 = kk >> 3, kc = kk & 7;
                int reg = ((kc >> 2) << 1) | (rr >> 3);
                int ln  = ((rr & 7) << 2) | (kc & 3);
                float hi, lo; split_tf32(xs[j], hi, lo);
                sAh[k8][matom][ln][reg] = hi;
                sAl[k8][matom][ln][reg] = lo;
            }
        }
        // B tile 16x64
        if (!NT) {
            for (int it = tid; it < 256; it += 256) {
                int kk = it >> 4;           // 0..15
                int q  = it & 15;           // 0..15 (float4 across 64 cols)
                int gk = k0 + kk;
                int gn0 = col0 + q * 4;
                float4 v = make_float4(0.f, 0.f, 0.f, 0.f);
                if (gk < K && gn0 + 3 < N)
                    v = *(const float4*)&B[(size_t)gk * N + gn0];
                float xs[4] = {v.x, v.y, v.z, v.w};
                int k8 = kk >> 3, kc = kk & 7;
                int reg = kc >> 2;
                #pragma unroll
                for (int j = 0; j < 4; ++j) {
                    int n = q * 4 + j;
                    int natom = n >> 3, nn = n & 7;
                    int ln = (nn << 2) | (kc & 3);
                    float hi, lo; split_tf32(xs[j], hi, lo);
                    sBh[k8][natom][ln][reg] = hi;
                    sBl[k8][natom][ln][reg] = lo;
                }
            }
        } else {
            for (int it = tid; it < 256; it += 256) {
                int n = it >> 2;            // 0..63
                int q = it & 3;
                int gn = col0 + n;
                int gk0 = k0 + q * 4;
                float4 v = make_float4(0.f, 0.f, 0.f, 0.f);
                if (gn < N && gk0 + 3 < K)
                    v = *(const float4*)&B[(size_t)gn * K + gk0];
                float xs[4] = {v.x, v.y, v.z, v.w};
                int natom = n >> 3, nn = n & 7;
                #pragma unroll
                for (int j = 0; j < 4; ++j) {
                    int kk = q * 4 + j;
                    int k8 = kk >> 3, kc = kk & 7;
                    int reg = kc >> 2;
                    int ln = (nn << 2) | (kc & 3);
                    float hi, lo; split_tf32(xs[j], hi, lo);
                    sBh[k8][natom][ln][reg] = hi;
                    sBl[k8][natom][ln][reg] = lo;
                }
            }
        }
        __syncthreads();

        // per-tile local accumulator
        float loc[2][4][4];
        #pragma unroll
        for (int ma = 0; ma < 2; ++ma)
            #pragma unroll
            for (int nb = 0; nb < 4; ++nb)
                #pragma unroll
                for (int q = 0; q < 4; ++q) loc[ma][nb][q] = 0.f;

        #pragma unroll
        for (int k8 = 0; k8 < 2; ++k8) {
            uint4 ah[2], al[2];
            #pragma unroll
            for (int ma = 0; ma < 2; ++ma) {
                ah[ma] = *(const uint4*)&sAh[k8][warp_m * 2 + ma][lane][0];
                al[ma] = *(const uint4*)&sAl[k8][warp_m * 2 + ma][lane][0];
            }
            uint2 bh[4], bl[4];
            #pragma unroll
            for (int nb = 0; nb < 4; ++nb) {
                bh[nb] = *(const uint2*)&sBh[k8][warp_n * 4 + nb][lane][0];
                bl[nb] = *(const uint2*)&sBl[k8][warp_n * 4 + nb][lane][0];
            }
            #pragma unroll
            for (int ma = 0; ma < 2; ++ma)
                #pragma unroll
                for (int nb = 0; nb < 4; ++nb) {
                    mma_tf32(loc[ma][nb], ah[ma], bh[nb]);
                    mma_tf32(loc[ma][nb], ah[ma], bl[nb]);
                    mma_tf32(loc[ma][nb], al[ma], bh[nb]);
                    mma_tf32(loc[ma][nb], al[ma], bl[nb]);
                }
        }

        // exact Kahan fold of tile partial into master
        #pragma unroll
        for (int ma = 0; ma < 2; ++ma)
            #pragma unroll
            for (int nb = 0; nb < 4; ++nb)
                #pragma unroll
                for (int q = 0; q < 4; ++q) {
                    float y = __fsub_rn(loc[ma][nb][q], cmp[ma][nb][q]);
                    float t = __fadd_rn(acc[ma][nb][q], y);
                    cmp[ma][nb][q] = __fsub_rn(__fsub_rn(t, acc[ma][nb][q]), y);
                    acc[ma][nb][q] = t;
                }
        __syncthreads();
    }

    const int g = lane >> 2, t = lane & 3;
    #pragma unroll
    for (int ma = 0; ma < 2; ++ma) {
        int r0 = row0 + (warp_m * 2 + ma) * 16 + g;
        #pragma unroll
        for (int nb = 0; nb < 4; ++nb) {
            int cc = col0 + (warp_n * 4 + nb) * 8 + 2 * t;
            if (cc >= N) continue;
            float v0 = acc[ma][nb][0], v1 = acc[ma][nb][1];
            float v2 = acc[ma][nb][2], v3 = acc[ma][nb][3];
            if (BIAS) {
                float b0 = bias[cc], b1 = bias[cc + 1];
                v0 = __fadd_rn(v0, b0); v1 = __fadd_rn(v1, b1);
                v2 = __fadd_rn(v2, b0); v3 = __fadd_rn(v3, b1);
            }
            if (r0 < M) *(float2*)&C[(size_t)r0 * N + cc] = make_float2(v0, v1);
            if (r0 + 8 < M) *(float2*)&C[(size_t)(r0 + 8) * N + cc] = make_float2(v2, v3);
        }
    }
}

// ---------------- kernel: mention score (fp64 accumulate) ---------
__global__ void k_score(const float* __restrict__ w_u2,
                        const float* __restrict__ b_u2) {
    int warp = (blockIdx.x * blockDim.x + threadIdx.x) >> 5;
    int lane = threadIdx.x & 31;
    if (warp >= C_SP) return;
    const float* row = g_hid1 + (size_t)warp * UHID;
    double acc = 0.0;
    #pragma unroll 8
    for (int i = lane; i < UHID; i += 32) acc += (double)row[i] * (double)w_u2[i];
    #pragma unroll
    for (int o = 16; o; o >>= 1) acc += __shfl_xor_sync(0xffffffffu, acc, o);
    if (lane == 0) g_mention[warp] = (float)(acc + (double)b_u2[0]);
}

// ---------------- kernel: sort + greedy non-crossing + compact ----
__global__ void k_extract(const int* __restrict__ starts,
                          const int* __restrict__ widths) {
    extern __shared__ int sh[];
    float* key = (float*)sh;
    int* idx = sh + 4096;
    int* es  = sh + 8192;
    int* flg = sh + 12288;
    const int tid = threadIdx.x;       // 1024 threads

    for (int i = tid; i < C_SP; i += 1024) {
        key[i] = g_mention[i];
        idx[i] = i;
        flg[i] = 0;
    }
    __syncthreads();

    for (unsigned k = 2; k <= 4096; k <<= 1) {
        for (unsigned j = k >> 1; j > 0; j >>= 1) {
            for (unsigned t = tid; t < 2048; t += 1024) {
                unsigned i = ((t & ~(j - 1)) << 1) | (t & (j - 1));
                unsigned l = i | j;
                float ki = key[i], kl = key[l];
                int   ii = idx[i], il = idx[l];
                bool before_l_i = (kl > ki) || (kl == ki && il < ii);
                bool dir = ((i & k) == 0);
                if (before_l_i == dir) {
                    key[i] = kl; key[l] = ki;
                    idx[i] = il; idx[l] = ii;
                }
            }
            __syncthreads();
        }
    }

    volatile int* le = (volatile int*)key;
    volatile int* ves = (volatile int*)es;
    for (int i = tid; i < T_TOK; i += 1024) {
        ((int*)key)[i] = -1;
        es[i] = T_TOK;
    }
    __syncthreads();

    if (tid < 32) {
        int lane = tid;
        int count = 0;
        for (int p = 0; p < C_SP && count < M_TOP; ++p) {
            int ci = idx[p];
            int s = starts[ci];
            int w = widths[ci];
            int e = s + w;
            bool crossing = false;
            if (lane < w) {
                crossing = (le[s + 1 + lane] > e) | (ves[s + lane] < s);
            }
            unsigned m = __ballot_sync(0xffffffffu, crossing);
            if (m == 0u) {
                if (lane == 0) {
                    int cur = le[s]; if (e > cur) ((int*)key)[s] = e;
                    int cur2 = ves[e]; if (s < cur2) es[e] = s;
                    flg[ci] = 1;
                }
                count++;
            }
            __syncwarp();
        }
    }
    __syncthreads();

    __shared__ int wsum[32];
    __shared__ int woff[33];
    int base = tid * 4;
    int f0 = flg[base], f1 = flg[base + 1], f2 = flg[base + 2], f3 = flg[base + 3];
    int c = f0 + f1 + f2 + f3;
    int inc = c;
    int lane = tid & 31, wid = tid >> 5;
    #pragma unroll
    for (int o = 1; o < 32; o <<= 1) {
        int n = __shfl_up_sync(0xffffffffu, inc, o);
        if (lane >= o) inc += n;
    }
    if (lane == 31) wsum[wid] = inc;
    __syncthreads();
    if (tid == 0) {
        int run = 0;
        for (int i = 0; i < 32; ++i) { woff[i] = run; run += wsum[i]; }
        woff[32] = run;
    }
    __syncthreads();
    int pos = woff[wid] + (inc - c);
    if (f0) { if (pos < M_TOP) g_topidx[pos] = base;     pos++; }
    if (f1) { if (pos < M_TOP) g_topidx[pos] = base + 1; pos++; }
    if (f2) { if (pos < M_TOP) g_topidx[pos] = base + 2; pos++; }
    if (f3) { if (pos < M_TOP) g_topidx[pos] = base + 3; pos++; }
    int total = woff[32];
    for (int p = total + tid; p < M_TOP; p += 1024) g_topidx[p] = C_SP - 1;
}

// ---------------- kernel: gather top spans ------------------------
__global__ void k_gather(float* __restrict__ out_topidx) {
    int p = blockIdx.x;
    int ci = g_topidx[p];
    if (threadIdx.x == 0) {
        g_topm[p] = g_mention[ci];
        out_topidx[p] = (float)ci;
    }
    const float4* src = (const float4*)(g_span_emb + (size_t)ci * SPAND);
    float4* dst = (float4*)(g_topemb + (size_t)p * SPAND);
    for (int i = threadIdx.x; i < SPAND / 4; i += blockDim.x) dst[i] = src[i];
}

// ---------------- kernel: assemble fast scores + per-row top-50 ---
__global__ void k_topk(float* __restrict__ out_ant,
                       float* __restrict__ out_mask,
                       float* __restrict__ out_score) {
    __shared__ float v[M_TOP];
    __shared__ float rv[256];
    __shared__ int   ri[256];
    const int i = blockIdx.x;
    const int tid = threadIdx.x;
    const float mi = g_topm[i];
    for (int j = tid; j < M_TOP; j += 256) {
        float val = __fadd_rn(__fadd_rn(__fadd_rn(mi, g_topm[j]),
                                        (j < i) ? 0.f : NEGV),
                              g_fast[(size_t)i * M_TOP + j]);
        v[j] = val;
    }
    __syncthreads();
    for (int k = 0; k < K_ANT; ++k) {
        float bv = -INFINITY; int bi = M_TOP;
        for (int j = tid; j < M_TOP; j += 256) {
            float x = v[j];
            if (x > bv || (x == bv && j < bi)) { bv = x; bi = j; }
        }
        rv[tid] = bv; ri[tid] = bi;
        __syncthreads();
        for (int s = 128; s > 0; s >>= 1) {
            if (tid < s) {
                if (rv[tid + s] > rv[tid] ||
                    (rv[tid + s] == rv[tid] && ri[tid + s] < ri[tid])) {
                    rv[tid] = rv[tid + s]; ri[tid] = ri[tid + s];
                }
            }
            __syncthreads();
        }
        if (tid == 0) {
            int j = ri[0];
            out_ant[(size_t)i * K_ANT + k]   = (float)j;
            out_mask[(size_t)i * K_ANT + k]  = (j < i) ? 1.f : 0.f;
            out_score[(size_t)i * K_ANT + k] = rv[0];
            v[j] = -INFINITY;
        }
        __syncthreads();
    }
}

// ---------------- launch ------------------------------------------
extern "C" void kernel_launch(void* const* d_in, const int* in_sizes, int n_in,
                              void* d_out, int out_size) {
    const float* hs      = (const float*)d_in[0];
    const int*   starts  = (const int*)d_in[1];
    const int*   widths  = (const int*)d_in[2];
    int base = 3;
    if (n_in >= 14 && in_sizes[3] == 1 && in_sizes[4] == 1) base = 5;
    const float* w_width = (const float*)d_in[base + 0];
    const float* w_attn  = (const float*)d_in[base + 1];
    const float* b_attn  = (const float*)d_in[base + 2];
    const float* w_u1    = (const float*)d_in[base + 3];
    const float* b_u1    = (const float*)d_in[base + 4];
    const float* w_u2    = (const float*)d_in[base + 5];
    const float* b_u2    = (const float*)d_in[base + 6];
    const float* w_fast  = (const float*)d_in[base + 7];
    const float* b_fast  = (const float*)d_in[base + 8];

    float* out = (float*)d_out;
    float* out_topidx = out;
    float* out_ant    = out + M_TOP;
    float* out_mask   = out + M_TOP + M_TOP * K_ANT;
    float* out_score  = out + M_TOP + 2 * M_TOP * K_ANT;

    float *p_span, *p_hid1, *p_topemb, *p_tmp, *p_fast;
    cudaGetSymbolAddress((void**)&p_span,   g_span_emb);
    cudaGetSymbolAddress((void**)&p_hid1,   g_hid1);
    cudaGetSymbolAddress((void**)&p_topemb, g_topemb);
    cudaGetSymbolAddress((void**)&p_tmp,    g_tmp);
    cudaGetSymbolAddress((void**)&p_fast,   g_fast);

    // 1. token logits (fp64 accumulate)
    k_token_logits<<<T_TOK * 32 / 256, 256>>>(hs, w_attn, b_attn);

    // 2. span embeddings
    k_span_emb<<<C_SP, 256>>>(hs, starts, widths, w_width);

    // 3. hid1 = relu(span_emb @ w_u1 + b_u1)  [4096,1024]  tf32x2 3-pass
    {
        dim3 grid(UHID / 128, C_SP / 128);
        k_gemm_tc<false, true, true><<<grid, 256>>>(
            p_span, w_u1, b_u1, p_hid1, C_SP, UHID, SPAND);
    }

    // 4. mention scores (fp64 accumulate)
    k_score<<<C_SP * 32 / 256, 256>>>(w_u2, b_u2);

    // 5. sort + greedy extraction + compact
    cudaFuncSetAttribute(k_extract, cudaFuncAttributeMaxDynamicSharedMemorySize, 65536);
    k_extract<<<1, 1024, 65536>>>(starts, widths);

    // 6. gather top_emb / top_m / write top_idx output
    k_gather<<<M_TOP, 256>>>(out_topidx);

    // 7. tmp = top_emb @ w_fast + b_fast  [1024,3092]  tf32x2 4-pass Kahan
    {
        dim3 grid((SPAND + 63) / 64, M_TOP / 128);       // 49 x 8
        k_gemm_tc4<false, true><<<grid, 256>>>(
            p_topemb, w_fast, b_fast, p_tmp, M_TOP, SPAND, SPAND);
    }

    // 8. fast0 = tmp @ top_emb^T  [1024,1024]  tf32x2 4-pass Kahan (NT)
    {
        dim3 grid(M_TOP / 64, M_TOP / 128);              // 16 x 8
        k_gemm_tc4<true, false><<<grid, 256>>>(
            p_tmp, p_topemb, nullptr, p_fast, M_TOP, M_TOP, SPAND);
    }

    // 9. assemble fast matrix + per-row top-50
    k_topk<<<M_TOP, 256>>>(out_ant, out_mask, out_score);

    (void)in_sizes; (void)n_in; (void)out_size;
}

// round 11
// speedup vs baseline: 3.7693x; 1.8418x over previous
#include <cuda_runtime.h>
#include <cuda_bf16.h>
#include <math.h>
#include <float.h>
#include <stdint.h>

// ---------------- problem constants (fixed shapes) ----------------
#define T_TOK 4096
#define C_SP  4096
#define HID   1024
#define METAF 20
#define SPAND 3092          // 3*HID + META
#define UHID  1024
#define M_TOP 1024
#define K_ANT 50
#define NEGV  (-1e30f)
#define KPAD  3136          // SPAND padded to 49*64
#define NPADF 3136          // w_fast^T rows padded

// ---------------- device scratch ----------------------------------
__device__ float g_logits[T_TOK];
__device__ float g_span_emb[(size_t)C_SP * SPAND];
__device__ float g_hid1[(size_t)C_SP * UHID];
__device__ float g_mention[C_SP];
__device__ int   g_topidx[M_TOP];
__device__ float g_topm[M_TOP];
__device__ float g_tmp[(size_t)M_TOP * SPAND];
__device__ float g_fast[(size_t)M_TOP * M_TOP];
// bf16 split operands
__device__ __nv_bfloat16 g_sa0[(size_t)C_SP * KPAD];   // span_emb splits
__device__ __nv_bfloat16 g_sa1[(size_t)C_SP * KPAD];
__device__ __nv_bfloat16 g_sa2[(size_t)C_SP * KPAD];
__device__ __nv_bfloat16 g_wb0[(size_t)UHID * KPAD];   // w_u1^T splits
__device__ __nv_bfloat16 g_wb1[(size_t)UHID * KPAD];
__device__ __nv_bfloat16 g_fb0[(size_t)NPADF * KPAD];  // w_fast^T splits
__device__ __nv_bfloat16 g_fb1[(size_t)NPADF * KPAD];
__device__ __nv_bfloat16 g_fb2[(size_t)NPADF * KPAD];
__device__ __nv_bfloat16 g_ta0[(size_t)M_TOP * KPAD];  // top_emb splits
__device__ __nv_bfloat16 g_ta1[(size_t)M_TOP * KPAD];
__device__ __nv_bfloat16 g_ta2[(size_t)M_TOP * KPAD];
__device__ __nv_bfloat16 g_tb0[(size_t)M_TOP * KPAD];  // tmp splits
__device__ __nv_bfloat16 g_tb1[(size_t)M_TOP * KPAD];
__device__ __nv_bfloat16 g_tb2[(size_t)M_TOP * KPAD];

// ---------------- kernel 1: token logits (fp64 accumulate) --------
__global__ void k_token_logits(const float* __restrict__ hs,
                               const float* __restrict__ w_attn,
                               const float* __restrict__ b_attn) {
    int warp = (blockIdx.x * blockDim.x + threadIdx.x) >> 5;
    int lane = threadIdx.x & 31;
    if (warp >= T_TOK) return;
    const float* row = hs + (size_t)warp * HID;
    double acc = 0.0;
    #pragma unroll 8
    for (int i = lane; i < HID; i += 32) acc += (double)row[i] * (double)w_attn[i];
    #pragma unroll
    for (int o = 16; o; o >>= 1) acc += __shfl_xor_sync(0xffffffffu, acc, o);
    if (lane == 0) g_logits[warp] = (float)(acc + (double)b_attn[0]);
}

// ---------------- kernel 2: span embeddings -----------------------
__global__ void k_span_emb(const float* __restrict__ hs,
                           const int* __restrict__ starts,
                           const int* __restrict__ widths,
                           const float* __restrict__ w_width) {
    int c = blockIdx.x;
    int s = starts[c], w = widths[c];
    int e = s + w, L = w + 1;
    __shared__ float p[32];
    int tid = threadIdx.x;
    if (tid < 32) {
        double lg = (tid < L) ? (double)g_logits[s + tid] : -1e300;
        double mx = lg;
        #pragma unroll
        for (int o = 16; o; o >>= 1) {
            double v = __shfl_xor_sync(0xffffffffu, mx, o);
            mx = fmax(mx, v);
        }
        double ex = (tid < L) ? exp(lg - mx) : 0.0;
        double sm = ex;
        #pragma unroll
        for (int o = 16; o; o >>= 1) sm += __shfl_xor_sync(0xffffffffu, sm, o);
        p[tid] = (float)(ex / sm);
    }
    __syncthreads();
    float* out = g_span_emb + (size_t)c * SPAND;
    const float* hrow_s = hs + (size_t)s * HID;
    const float* hrow_e = hs + (size_t)e * HID;
    for (int h = tid; h < HID; h += blockDim.x) {
        out[h]        = hrow_s[h];
        out[HID + h]  = hrow_e[h];
        float acc = 0.f, cmp = 0.f;
        for (int l = 0; l < L; ++l) {
            float y = __fmaf_rn(p[l], hs[(size_t)(s + l) * HID + h], -cmp);
            float t = __fadd_rn(acc, y);
            cmp = __fsub_rn(__fsub_rn(t, acc), y);
            acc = t;
        }
        out[2 * HID + METAF + h] = acc;
    }
    if (tid < METAF) out[2 * HID + tid] = w_width[w * METAF + tid];
}

// ---------------- bf16 split helpers ------------------------------
__device__ __forceinline__ void split3(float x, __nv_bfloat16& o0,
                                       __nv_bfloat16& o1, __nv_bfloat16& o2) {
    __nv_bfloat16 b0 = __float2bfloat16(x);
    float r1 = __fsub_rn(x, __bfloat162float(b0));
    __nv_bfloat16 b1 = __float2bfloat16(r1);
    float r2 = __fsub_rn(r1, __bfloat162float(b1));
    o0 = b0; o1 = b1; o2 = __float2bfloat16(r2);
}

__global__ void k_split_spans() {      // span_emb -> sa0/1/2
    int r = blockIdx.x;
    const float* src = g_span_emb + (size_t)r * SPAND;
    size_t o = (size_t)r * KPAD;
    for (int k = threadIdx.x; k < KPAD; k += 256) {
        float x = (k < SPAND) ? src[k] : 0.f;
        split3(x, g_sa0[o + k], g_sa1[o + k], g_sa2[o + k]);
    }
}

__global__ void k_split_w1(const float* __restrict__ w) {  // w_u1[K,N] -> wb[n][k] x2
    __shared__ float t[64][65];
    int k0 = blockIdx.x * 64, n0 = blockIdx.y * 64;
    int tn = threadIdx.x & 63, t4 = threadIdx.x >> 6;
    for (int kk = t4; kk < 64; kk += 4) {
        int gk = k0 + kk;
        t[kk][tn] = (gk < SPAND) ? w[(size_t)gk * UHID + n0 + tn] : 0.f;
    }
    __syncthreads();
    for (int nn = t4; nn < 64; nn += 4) {
        size_t o = (size_t)(n0 + nn) * KPAD + k0 + tn;
        __nv_bfloat16 b0 = __float2bfloat16(t[tn][nn]);
        float r1 = __fsub_rn(t[tn][nn], __bfloat162float(b0));
        g_wb0[o] = b0;
        g_wb1[o] = __float2bfloat16(r1);
    }
}

__global__ void k_split_wfast(const float* __restrict__ w) { // w_fast[K,N] -> fb[n][k] x3
    __shared__ float t[64][65];
    int k0 = blockIdx.x * 64, n0 = blockIdx.y * 64;
    int tn = threadIdx.x & 63, t4 = threadIdx.x >> 6;
    for (int kk = t4; kk < 64; kk += 4) {
        int gk = k0 + kk, gn = n0 + tn;
        t[kk][tn] = (gk < SPAND && gn < SPAND) ? w[(size_t)gk * SPAND + gn] : 0.f;
    }
    __syncthreads();
    for (int nn = t4; nn < 64; nn += 4) {
        size_t o = (size_t)(n0 + nn) * KPAD + k0 + tn;
        split3(t[tn][nn], g_fb0[o], g_fb1[o], g_fb2[o]);
    }
}

__global__ void k_split_tmp() {        // tmp[1024,3092] -> tb0/1/2
    int r = blockIdx.x;
    const float* src = g_tmp + (size_t)r * SPAND;
    size_t o = (size_t)r * KPAD;
    for (int k = threadIdx.x; k < KPAD; k += 256) {
        float x = (k < SPAND) ? src[k] : 0.f;
        split3(x, g_tb0[o + k], g_tb1[o + k], g_tb2[o + k]);
    }
}

// ---------------- bf16 MMA helper ---------------------------------
__device__ __forceinline__ void mma_bf16(float c[4], const uint4& a, const uint2& b) {
    asm volatile(
        "mma.sync.aligned.m16n8k16.row.col.f32.bf16.bf16.f32 "
        "{%0,%1,%2,%3}, {%4,%5,%6,%7}, {%8,%9}, {%0,%1,%2,%3};"
        : "+f"(c[0]), "+f"(c[1]), "+f"(c[2]), "+f"(c[3])
        : "r"(a.x), "r"(a.y), "r"(a.z), "r"(a.w), "r"(b.x), "r"(b.y));
}

// Fragment-major SMEM fill for A-side tiles (128 rows x 64 k per split).
// Per-split tile = 128*64*2 = 16384 B; layout [k16(4)][matom(8)][lane(32)][reg(4)].
// m16n8k16 A frag: reg = (rr>=8) + 2*(kpair>=4); lane = (rr&7)*4 + (kpair&3).
__device__ __forceinline__ void fill_A_tile(char* sA, int row0, int k0, int tid,
                                            int nsplit,
                                            const __nv_bfloat16* const* srcs) {
    for (int it = tid; it < nsplit * 1024; it += 256) {
        int s = it >> 10, rc = it & 1023;
        int r = rc >> 3, c = rc & 7;          // row, k-octet (8 bf16)
        const uint4 v = *(const uint4*)&srcs[s][(size_t)(row0 + r) * KPAD + k0 + c * 8];
        int matom = r >> 4, rr = r & 15;
        int k16 = c >> 1;
        int regb = (rr >> 3) + 2 * (c & 1);   // (row>=8) + 2*(kpair>=4)
        uint32_t base = (uint32_t)(s * 16384 + k16 * 4096 + matom * 512 + (rr & 7) * 64 + regb * 4);
        const uint32_t w[4] = {v.x, v.y, v.z, v.w};
        #pragma unroll
        for (int j = 0; j < 4; ++j)           // j = kpair&3 -> lane low bits
            *(uint32_t*)(sA + base + j * 16) = w[j];
    }
}

// B-side tiles (BN rows x 64 k per split). Per-split tile = BN*128 B;
// layout [k16(4)][natom(BN/8)][lane(32)][reg(2)].
// frag: reg = (kpair>=4); lane = nn*4 + (kpair&3).
// FIX(R11): split stride was BN*256 and k16 stride BN*64 -> SMEM OOB (crash).
template<int BN>
__device__ __forceinline__ void fill_B_tile(char* sB, int col0, int k0, int tid,
                                            int nsplit, const __nv_bfloat16* const* srcs) {
    const int per = BN * 8;                   // uint4 loads per split
    for (int it = tid; it < nsplit * per; it += 256) {
        int s = it / per, rc = it % per;
        int n = rc >> 3, c = rc & 7;
        const uint4 v = *(const uint4*)&srcs[s][(size_t)(col0 + n) * KPAD + k0 + c * 8];
        int natom = n >> 3, nn = n & 7;
        int k16 = c >> 1;
        int reg = c & 1;
        uint32_t base = (uint32_t)(s * (BN * 128) + k16 * (BN * 32) + natom * 256 + nn * 32 + reg * 4);
        const uint32_t w[4] = {v.x, v.y, v.z, v.w};
        #pragma unroll
        for (int j = 0; j < 4; ++j)           // j = kpair&3 -> lane low bits
            *(uint32_t*)(sB + base + j * 8) = w[j];
    }
}

// ---------------- GEMM3: bf16x2 3-pass, block 128x128 -------------
// hid1 = relu(span_emb @ w_u1 + b_u1). Noise ~2e-5 on hid1 -> mention
// noise ~2e-5 vs gaps 7e-4 (35x margin; R6 proved tolerance to 1e-4).
__global__ __launch_bounds__(256, 1)
void k_gemm3(const float* __restrict__ bias, float* __restrict__ C) {
    extern __shared__ char sm[];
    char* sA = sm;                 // 2 splits x 16KB = 32KB
    char* sB = sm + 32768;         // 2 splits x 16KB = 32KB (BN=128)
    const int tid = threadIdx.x, lane = tid & 31, wid = tid >> 5;
    const int warp_m = wid >> 1, warp_n = wid & 1;
    const int row0 = blockIdx.y * 128, col0 = blockIdx.x * 128;

    const __nv_bfloat16* As[2] = {g_sa0, g_sa1};
    const __nv_bfloat16* Bs[2] = {g_wb0, g_wb1};

    float c[2][8][4];
    #pragma unroll
    for (int ma = 0; ma < 2; ++ma)
        #pragma unroll
        for (int nb = 0; nb < 8; ++nb)
            #pragma unroll
            for (int q = 0; q < 4; ++q) c[ma][nb][q] = 0.f;

    const int sa_i[3] = {0, 0, 1}, sb_i[3] = {0, 1, 0};

    for (int kt = 0; kt < KPAD / 64; ++kt) {
        int k0 = kt * 64;
        fill_A_tile(sA, row0, k0, tid, 2, As);
        fill_B_tile<128>(sB, col0, k0, tid, 2, Bs);
        __syncthreads();
        #pragma unroll
        for (int k16 = 0; k16 < 4; ++k16) {
            #pragma unroll
            for (int pr = 0; pr < 3; ++pr) {
                uint4 a[2]; uint2 b[8];
                #pragma unroll
                for (int ma = 0; ma < 2; ++ma)
                    a[ma] = *(const uint4*)(sA + sa_i[pr] * 16384 + k16 * 4096
                                            + (warp_m * 2 + ma) * 512 + lane * 16);
                #pragma unroll
                for (int nb = 0; nb < 8; ++nb)
                    b[nb] = *(const uint2*)(sB + sb_i[pr] * 16384 + k16 * 4096
                                            + (warp_n * 8 + nb) * 256 + lane * 8);
                #pragma unroll
                for (int ma = 0; ma < 2; ++ma)
                    #pragma unroll
                    for (int nb = 0; nb < 8; ++nb)
                        mma_bf16(c[ma][nb], a[ma], b[nb]);
            }
        }
        __syncthreads();
    }

    const int g = lane >> 2, t = lane & 3;
    #pragma unroll
    for (int ma = 0; ma < 2; ++ma) {
        int r0 = row0 + (warp_m * 2 + ma) * 16 + g;
        #pragma unroll
        for (int nb = 0; nb < 8; ++nb) {
            int cc = col0 + (warp_n * 8 + nb) * 8 + 2 * t;
            float b0 = bias[cc], b1 = bias[cc + 1];
            float v0 = fmaxf(__fadd_rn(c[ma][nb][0], b0), 0.f);
            float v1 = fmaxf(__fadd_rn(c[ma][nb][1], b1), 0.f);
            float v2 = fmaxf(__fadd_rn(c[ma][nb][2], b0), 0.f);
            float v3 = fmaxf(__fadd_rn(c[ma][nb][3], b1), 0.f);
            *(float2*)&C[(size_t)r0 * UHID + cc] = make_float2(v0, v1);
            *(float2*)&C[(size_t)(r0 + 8) * UHID + cc] = make_float2(v2, v3);
        }
    }
}

// ---------------- GEMM 6-pass bf16x3 + per-k32 Kahan, 128x64 ------
// Antecedent path: rep residual ~5e-6, accumulation ~1.2e-5 -> inside
// the proven-passing noise class (R5/R8 configs: rel_err 1e-34).
__global__ __launch_bounds__(256, 1)
void k_gemm6(const __nv_bfloat16* __restrict__ A0, const __nv_bfloat16* __restrict__ A1,
             const __nv_bfloat16* __restrict__ A2,
             const __nv_bfloat16* __restrict__ B0, const __nv_bfloat16* __restrict__ B1,
             const __nv_bfloat16* __restrict__ B2,
             const float* __restrict__ bias, float* __restrict__ C,
             int Nstore, int ldc) {
    extern __shared__ char sm[];
    char* sA = sm;                 // 3 x 16KB = 48KB
    char* sB = sm + 49152;         // 3 x 8KB  = 24KB (BN=64)
    const int tid = threadIdx.x, lane = tid & 31, wid = tid >> 5;
    const int warp_m = wid >> 1, warp_n = wid & 1;
    const int row0 = blockIdx.y * 128, col0 = blockIdx.x * 64;

    const __nv_bfloat16* As[3] = {A0, A1, A2};
    const __nv_bfloat16* Bs[3] = {B0, B1, B2};

    float acc[2][4][4], cmp[2][4][4];
    #pragma unroll
    for (int ma = 0; ma < 2; ++ma)
        #pragma unroll
        for (int nb = 0; nb < 4; ++nb)
            #pragma unroll
            for (int q = 0; q < 4; ++q) { acc[ma][nb][q] = 0.f; cmp[ma][nb][q] = 0.f; }

    const int sa_i[6] = {0, 0, 1, 1, 0, 2};
    const int sb_i[6] = {0, 1, 0, 1, 2, 0};

    for (int kt = 0; kt < KPAD / 64; ++kt) {
        int k0 = kt * 64;
        fill_A_tile(sA, row0, k0, tid, 3, As);
        fill_B_tile<64>(sB, col0, k0, tid, 3, Bs);
        __syncthreads();
        #pragma unroll
        for (int kh = 0; kh < 2; ++kh) {     // two k32 halves per k64 tile
            float loc[2][4][4];
            #pragma unroll
            for (int ma = 0; ma < 2; ++ma)
                #pragma unroll
                for (int nb = 0; nb < 4; ++nb)
                    #pragma unroll
                    for (int q = 0; q < 4; ++q) loc[ma][nb][q] = 0.f;
            #pragma unroll
            for (int k16 = 2 * kh; k16 < 2 * kh + 2; ++k16) {
                #pragma unroll
                for (int pr = 0; pr < 6; ++pr) {
                    uint4 a[2]; uint2 b[4];
                    #pragma unroll
                    for (int ma = 0; ma < 2; ++ma)
                        a[ma] = *(const uint4*)(sA + sa_i[pr] * 16384 + k16 * 4096
                                                + (warp_m * 2 + ma) * 512 + lane * 16);
                    #pragma unroll
                    for (int nb = 0; nb < 4; ++nb)
                        b[nb] = *(const uint2*)(sB + sb_i[pr] * 8192 + k16 * 2048
                                                + (warp_n * 4 + nb) * 256 + lane * 8);
                    #pragma unroll
                    for (int ma = 0; ma < 2; ++ma)
                        #pragma unroll
                        for (int nb = 0; nb < 4; ++nb)
                            mma_bf16(loc[ma][nb], a[ma], b[nb]);
                }
            }
            // exact Kahan fold of k32 partial into master
            #pragma unroll
            for (int ma = 0; ma < 2; ++ma)
                #pragma unroll
                for (int nb = 0; nb < 4; ++nb)
                    #pragma unroll
                    for (int q = 0; q < 4; ++q) {
                        float y = __fsub_rn(loc[ma][nb][q], cmp[ma][nb][q]);
                        float t = __fadd_rn(acc[ma][nb][q], y);
                        cmp[ma][nb][q] = __fsub_rn(__fsub_rn(t, acc[ma][nb][q]), y);
                        acc[ma][nb][q] = t;
                    }
        }
        __syncthreads();
    }

    const int g = lane >> 2, t = lane & 3;
    #pragma unroll
    for (int ma = 0; ma < 2; ++ma) {
        int r0 = row0 + (warp_m * 2 + ma) * 16 + g;
        #pragma unroll
        for (int nb = 0; nb < 4; ++nb) {
            int cc = col0 + (warp_n * 4 + nb) * 8 + 2 * t;
            if (cc >= Nstore) continue;
            float v0 = acc[ma][nb][0], v1 = acc[ma][nb][1];
            float v2 = acc[ma][nb][2], v3 = acc[ma][nb][3];
            if (bias) {
                float b0 = bias[cc];
                float b1 = (cc + 1 < Nstore) ? bias[cc + 1] : 0.f;
                v0 = __fadd_rn(v0, b0); v1 = __fadd_rn(v1, b1);
                v2 = __fadd_rn(v2, b0); v3 = __fadd_rn(v3, b1);
            }
            if (cc + 1 < Nstore) {
                *(float2*)&C[(size_t)r0 * ldc + cc] = make_float2(v0, v1);
                *(float2*)&C[(size_t)(r0 + 8) * ldc + cc] = make_float2(v2, v3);
            } else {
                C[(size_t)r0 * ldc + cc] = v0;
                C[(size_t)(r0 + 8) * ldc + cc] = v2;
            }
        }
    }
}

// ---------------- kernel: mention score (fp64 accumulate) ---------
__global__ void k_score(const float* __restrict__ w_u2,
                        const float* __restrict__ b_u2) {
    int warp = (blockIdx.x * blockDim.x + threadIdx.x) >> 5;
    int lane = threadIdx.x & 31;
    if (warp >= C_SP) return;
    const float* row = g_hid1 + (size_t)warp * UHID;
    double acc = 0.0;
    #pragma unroll 8
    for (int i = lane; i < UHID; i += 32) acc += (double)row[i] * (double)w_u2[i];
    #pragma unroll
    for (int o = 16; o; o >>= 1) acc += __shfl_xor_sync(0xffffffffu, acc, o);
    if (lane == 0) g_mention[warp] = (float)(acc + (double)b_u2[0]);
}

// ---------------- kernel: sort + greedy non-crossing + compact ----
__global__ void k_extract(const int* __restrict__ starts,
                          const int* __restrict__ widths) {
    extern __shared__ int sh[];
    float* key = (float*)sh;
    int* idx = sh + 4096;
    int* es  = sh + 8192;
    int* flg = sh + 12288;
    const int tid = threadIdx.x;       // 1024 threads

    for (int i = tid; i < C_SP; i += 1024) {
        key[i] = g_mention[i];
        idx[i] = i;
        flg[i] = 0;
    }
    __syncthreads();

    for (unsigned k = 2; k <= 4096; k <<= 1) {
        for (unsigned j = k >> 1; j > 0; j >>= 1) {
            for (unsigned t = tid; t < 2048; t += 1024) {
                unsigned i = ((t & ~(j - 1)) << 1) | (t & (j - 1));
                unsigned l = i | j;
                float ki = key[i], kl = key[l];
                int   ii = idx[i], il = idx[l];
                bool before_l_i = (kl > ki) || (kl == ki && il < ii);
                bool dir = ((i & k) == 0);
                if (before_l_i == dir) {
                    key[i] = kl; key[l] = ki;
                    idx[i] = il; idx[l] = ii;
                }
            }
            __syncthreads();
        }
    }

    volatile int* le = (volatile int*)key;
    volatile int* ves = (volatile int*)es;
    for (int i = tid; i < T_TOK; i += 1024) {
        ((int*)key)[i] = -1;
        es[i] = T_TOK;
    }
    __syncthreads();

    if (tid < 32) {
        int lane = tid;
        int count = 0;
        for (int p = 0; p < C_SP && count < M_TOP; ++p) {
            int ci = idx[p];
            int s = starts[ci];
            int w = widths[ci];
            int e = s + w;
            bool crossing = false;
            if (lane < w) {
                crossing = (le[s + 1 + lane] > e) | (ves[s + lane] < s);
            }
            unsigned m = __ballot_sync(0xffffffffu, crossing);
            if (m == 0u) {
                if (lane == 0) {
                    int cur = le[s]; if (e > cur) ((int*)key)[s] = e;
                    int cur2 = ves[e]; if (s < cur2) es[e] = s;
                    flg[ci] = 1;
                }
                count++;
            }
            __syncwarp();
        }
    }
    __syncthreads();

    __shared__ int wsum[32];
    __shared__ int woff[33];
    int base = tid * 4;
    int f0 = flg[base], f1 = flg[base + 1], f2 = flg[base + 2], f3 = flg[base + 3];
    int c = f0 + f1 + f2 + f3;
    int inc = c;
    int lane = tid & 31, wid = tid >> 5;
    #pragma unroll
    for (int o = 1; o < 32; o <<= 1) {
        int n = __shfl_up_sync(0xffffffffu, inc, o);
        if (lane >= o) inc += n;
    }
    if (lane == 31) wsum[wid] = inc;
    __syncthreads();
    if (tid == 0) {
        int run = 0;
        for (int i = 0; i < 32; ++i) { woff[i] = run; run += wsum[i]; }
        woff[32] = run;
    }
    __syncthreads();
    int pos = woff[wid] + (inc - c);
    if (f0) { if (pos < M_TOP) g_topidx[pos] = base;     pos++; }
    if (f1) { if (pos < M_TOP) g_topidx[pos] = base + 1; pos++; }
    if (f2) { if (pos < M_TOP) g_topidx[pos] = base + 2; pos++; }
    if (f3) { if (pos < M_TOP) g_topidx[pos] = base + 3; pos++; }
    int total = woff[32];
    for (int p = total + tid; p < M_TOP; p += 1024) g_topidx[p] = C_SP - 1;
}

// ---------------- kernel: gather top span splits ------------------
__global__ void k_gather(float* __restrict__ out_topidx) {
    int p = blockIdx.x;
    int ci = g_topidx[p];
    if (threadIdx.x == 0) {
        g_topm[p] = g_mention[ci];
        out_topidx[p] = (float)ci;
    }
    size_t so = (size_t)ci * KPAD, dof = (size_t)p * KPAD;
    const uint4* s0 = (const uint4*)(g_sa0 + so);
    const uint4* s1 = (const uint4*)(g_sa1 + so);
    const uint4* s2 = (const uint4*)(g_sa2 + so);
    uint4* d0 = (uint4*)(g_ta0 + dof);
    uint4* d1 = (uint4*)(g_ta1 + dof);
    uint4* d2 = (uint4*)(g_ta2 + dof);
    for (int i = threadIdx.x; i < KPAD / 8; i += blockDim.x) {
        d0[i] = s0[i]; d1[i] = s1[i]; d2[i] = s2[i];
    }
}

// ---------------- kernel: assemble fast scores + per-row top-50 ---
__global__ void k_topk(float* __restrict__ out_ant,
                       float* __restrict__ out_mask,
                       float* __restrict__ out_score) {
    __shared__ float v[M_TOP];
    __shared__ float rv[256];
    __shared__ int   ri[256];
    const int i = blockIdx.x;
    const int tid = threadIdx.x;
    const float mi = g_topm[i];
    for (int j = tid; j < M_TOP; j += 256) {
        float val = __fadd_rn(__fadd_rn(__fadd_rn(mi, g_topm[j]),
                                        (j < i) ? 0.f : NEGV),
                              g_fast[(size_t)i * M_TOP + j]);
        v[j] = val;
    }
    __syncthreads();
    for (int k = 0; k < K_ANT; ++k) {
        float bv = -INFINITY; int bi = M_TOP;
        for (int j = tid; j < M_TOP; j += 256) {
            float x = v[j];
            if (x > bv || (x == bv && j < bi)) { bv = x; bi = j; }
        }
        rv[tid] = bv; ri[tid] = bi;
        __syncthreads();
        for (int s = 128; s > 0; s >>= 1) {
            if (tid < s) {
                if (rv[tid + s] > rv[tid] ||
                    (rv[tid + s] == rv[tid] && ri[tid + s] < ri[tid])) {
                    rv[tid] = rv[tid + s]; ri[tid] = ri[tid + s];
                }
            }
            __syncthreads();
        }
        if (tid == 0) {
            int j = ri[0];
            out_ant[(size_t)i * K_ANT + k]   = (float)j;
            out_mask[(size_t)i * K_ANT + k]  = (j < i) ? 1.f : 0.f;
            out_score[(size_t)i * K_ANT + k] = rv[0];
            v[j] = -INFINITY;
        }
        __syncthreads();
    }
}

// ---------------- launch ------------------------------------------
extern "C" void kernel_launch(void* const* d_in, const int* in_sizes, int n_in,
                              void* d_out, int out_size) {
    const float* hs      = (const float*)d_in[0];
    const int*   starts  = (const int*)d_in[1];
    const int*   widths  = (const int*)d_in[2];
    int base = 3;
    if (n_in >= 14 && in_sizes[3] == 1 && in_sizes[4] == 1) base = 5;
    const float* w_width = (const float*)d_in[base + 0];
    const float* w_attn  = (const float*)d_in[base + 1];
    const float* b_attn  = (const float*)d_in[base + 2];
    const float* w_u1    = (const float*)d_in[base + 3];
    const float* b_u1    = (const float*)d_in[base + 4];
    const float* w_u2    = (const float*)d_in[base + 5];
    const float* b_u2    = (const float*)d_in[base + 6];
    const float* w_fast  = (const float*)d_in[base + 7];
    const float* b_fast  = (const float*)d_in[base + 8];

    float* out = (float*)d_out;
    float* out_topidx = out;
    float* out_ant    = out + M_TOP;
    float* out_mask   = out + M_TOP + M_TOP * K_ANT;
    float* out_score  = out + M_TOP + 2 * M_TOP * K_ANT;

    float *p_hid1, *p_tmp, *p_fast;
    __nv_bfloat16 *p_ta0, *p_ta1, *p_ta2, *p_tb0, *p_tb1, *p_tb2;
    __nv_bfloat16 *p_fb0, *p_fb1, *p_fb2;
    cudaGetSymbolAddress((void**)&p_hid1, g_hid1);
    cudaGetSymbolAddress((void**)&p_tmp,  g_tmp);
    cudaGetSymbolAddress((void**)&p_fast, g_fast);
    cudaGetSymbolAddress((void**)&p_ta0, g_ta0);
    cudaGetSymbolAddress((void**)&p_ta1, g_ta1);
    cudaGetSymbolAddress((void**)&p_ta2, g_ta2);
    cudaGetSymbolAddress((void**)&p_tb0, g_tb0);
    cudaGetSymbolAddress((void**)&p_tb1, g_tb1);
    cudaGetSymbolAddress((void**)&p_tb2, g_tb2);
    cudaGetSymbolAddress((void**)&p_fb0, g_fb0);
    cudaGetSymbolAddress((void**)&p_fb1, g_fb1);
    cudaGetSymbolAddress((void**)&p_fb2, g_fb2);

    cudaFuncSetAttribute(k_gemm3, cudaFuncAttributeMaxDynamicSharedMemorySize, 65536);
    cudaFuncSetAttribute(k_gemm6, cudaFuncAttributeMaxDynamicSharedMemorySize, 73728);

    // 1. token logits
    k_token_logits<<<T_TOK * 32 / 256, 256>>>(hs, w_attn, b_attn);
    // 2. span embeddings
    k_span_emb<<<C_SP, 256>>>(hs, starts, widths, w_width);
    // 2b. splits (w_fast split is input-only; launch early)
    k_split_spans<<<C_SP, 256>>>();
    { dim3 g(KPAD / 64, UHID / 64);  k_split_w1<<<g, 256>>>(w_u1); }
    { dim3 g(KPAD / 64, NPADF / 64); k_split_wfast<<<g, 256>>>(w_fast); }
    // 3. hid1 = relu(span_emb @ w_u1 + b_u1)  bf16x2 3-pass
    { dim3 g(UHID / 128, C_SP / 128); k_gemm3<<<g, 256, 65536>>>(b_u1, p_hid1); }
    // 4. mention scores
    k_score<<<C_SP * 32 / 256, 256>>>(w_u2, b_u2);
    // 5. sort + greedy extraction + compact
    cudaFuncSetAttribute(k_extract, cudaFuncAttributeMaxDynamicSharedMemorySize, 65536);
    k_extract<<<1, 1024, 65536>>>(starts, widths);
    // 6. gather split rows of selected spans
    k_gather<<<M_TOP, 256>>>(out_topidx);
    // 7. tmp = top_emb @ w_fast + b_fast   bf16x3 6-pass Kahan
    { dim3 g(NPADF / 64, M_TOP / 128);
      k_gemm6<<<g, 256, 73728>>>(p_ta0, p_ta1, p_ta2, p_fb0, p_fb1, p_fb2,
                                 b_fast, p_tmp, SPAND, SPAND); }
    // 7b. split tmp
    k_split_tmp<<<M_TOP, 256>>>();
    // 8. fast = tmp @ top_emb^T   bf16x3 6-pass Kahan
    { dim3 g(M_TOP / 64, M_TOP / 128);
      k_gemm6<<<g, 256, 73728>>>(p_tb0, p_tb1, p_tb2, p_ta0, p_ta1, p_ta2,
                                 nullptr, p_fast, M_TOP, M_TOP); }
    // 9. assemble fast matrix + per-row top-50
    k_topk<<<M_TOP, 256>>>(out_ant, out_mask, out_score);

    (void)in_sizes; (void)n_in; (void)out_size;
}

// round 12
// speedup vs baseline: 5.2893x; 1.4033x over previous
#include <cuda_runtime.h>
#include <cuda_bf16.h>
#include <math.h>
#include <float.h>
#include <stdint.h>

// ---------------- problem constants -------------------------------
#define T_TOK 4096
#define C_SP  4096
#define HID   1024
#define METAF 20
#define SPAND 3092
#define UHID  1024
#define M_TOP 1024
#define K_ANT 50
#define NEGV  (-1e30f)
#define KPAD  3136
#define NKT   49            // KPAD/64 k-tiles

// ---------------- device scratch ----------------------------------
__device__ float g_logits[T_TOK];
__device__ float g_span_emb[(size_t)C_SP * SPAND];
__device__ float g_hid1[(size_t)C_SP * UHID];
__device__ float g_mention[C_SP];
__device__ int   g_topidx[M_TOP];
__device__ float g_topm[M_TOP];
__device__ float g_tmp[(size_t)M_TOP * SPAND];
__device__ float g_fast[(size_t)M_TOP * M_TOP];
// fragment-major bf16 split operands (tile layouts documented below)
__device__ __nv_bfloat16 g_sa0[(size_t)C_SP * KPAD];   // span_emb, A-frag-128
__device__ __nv_bfloat16 g_sa1[(size_t)C_SP * KPAD];
__device__ __nv_bfloat16 g_sa2[(size_t)C_SP * KPAD];
__device__ __nv_bfloat16 g_wb0[(size_t)UHID * KPAD];   // w_u1^T, B-frag-128
__device__ __nv_bfloat16 g_wb1[(size_t)UHID * KPAD];
__device__ __nv_bfloat16 g_fb0[(size_t)KPAD * KPAD / KPAD * KPAD];  // placeholder avoided below
// (real decls)
__device__ __nv_bfloat16 g_fbx0[(size_t)KPAD * KPAD];  // w_fast^T, B-frag-64 (3136 rows)
__device__ __nv_bfloat16 g_fbx1[(size_t)KPAD * KPAD];
__device__ __nv_bfloat16 g_fbx2[(size_t)KPAD * KPAD];
__device__ __nv_bfloat16 g_ta0[(size_t)M_TOP * KPAD];  // top_emb, A-frag-128
__device__ __nv_bfloat16 g_ta1[(size_t)M_TOP * KPAD];
__device__ __nv_bfloat16 g_ta2[(size_t)M_TOP * KPAD];
__device__ __nv_bfloat16 g_taB0[(size_t)M_TOP * KPAD]; // top_emb, B-frag-64
__device__ __nv_bfloat16 g_taB1[(size_t)M_TOP * KPAD];
__device__ __nv_bfloat16 g_taB2[(size_t)M_TOP * KPAD];
__device__ __nv_bfloat16 g_tb0[(size_t)M_TOP * KPAD];  // tmp, A-frag-128
__device__ __nv_bfloat16 g_tb1[(size_t)M_TOP * KPAD];
__device__ __nv_bfloat16 g_tb2[(size_t)M_TOP * KPAD];

// ---------------- fragment-layout helpers (single source of truth) --
// A-frag-128 tile = 16KB per (tile_m, kt): [k16(4)][matom(8)][lane(32)][reg(4)] 4B words.
// word(rloc,k16,kp) : lane=(rr&7)*4+(kp&3), reg=(rr>>3)+2*(kp>>2), rr=rloc&15.
__device__ __forceinline__ uint32_t a_word(int rloc, int k16, int kp) {
    int rr = rloc & 15;
    return (uint32_t)(k16 * 1024 + (rloc >> 4) * 128
                      + ((rr & 7) * 4 + (kp & 3)) * 4 + (rr >> 3) + 2 * (kp >> 2));
}
// inverse: word w (0..4095) -> rloc,k16,kp
__device__ __forceinline__ void a_inv(int w, int& rloc, int& k16, int& kp) {
    k16 = w >> 10; int r = w & 1023;
    int matom = r >> 7; int r2 = r & 127;
    int lane = r2 >> 2, j = r2 & 3;
    int rr = (lane >> 2) + 8 * (j & 1);
    kp = (lane & 3) + 4 * (j >> 1);
    rloc = matom * 16 + rr;
}
// B-frag tile: BN=64 -> 8KB/2048 words, BN=128 -> 16KB/4096 words.
// word(nloc,k16,kp): [k16][natom][lane(32)][reg(2)], lane=nn*4+(kp&3), reg=kp>>2.
template<int BN>
__device__ __forceinline__ void b_inv(int w, int& nloc, int& k16, int& kp) {
    if (BN == 128) { k16 = w >> 10; } else { k16 = w >> 9; }
    int r = w & (BN * 8 - 1);
    int natom = r >> 6; int r2 = r & 63;
    int lane = r2 >> 1, j = r2 & 1;
    kp = (lane & 3) + 4 * j;
    nloc = natom * 8 + (lane >> 2);
}

__device__ __forceinline__ uint32_t pack_bf(__nv_bfloat16 lo, __nv_bfloat16 hi) {
    return (uint32_t)__bfloat16_as_ushort(lo) | ((uint32_t)__bfloat16_as_ushort(hi) << 16);
}
__device__ __forceinline__ void split3(float x, __nv_bfloat16& o0,
                                       __nv_bfloat16& o1, __nv_bfloat16& o2) {
    __nv_bfloat16 b0 = __float2bfloat16(x);
    float r1 = __fsub_rn(x, __bfloat162float(b0));
    __nv_bfloat16 b1 = __float2bfloat16(r1);
    float r2 = __fsub_rn(r1, __bfloat162float(b1));
    o0 = b0; o1 = b1; o2 = __float2bfloat16(r2);
}

#define CP_ASYNC16(smaddr, gptr) \
    asm volatile("cp.async.cg.shared.global [%0], [%1], 16;\n" :: "r"(smaddr), "l"(gptr))
#define CP_COMMIT() asm volatile("cp.async.commit_group;\n" ::: "memory")
#define CP_WAIT1()  asm volatile("cp.async.wait_group 1;\n" ::: "memory")

__device__ __forceinline__ uint32_t sm_addr(const void* p) {
    return (uint32_t)__cvta_generic_to_shared(p);
}

// ---------------- kernel: token logits ----------------------------
__global__ void k_token_logits(const float* __restrict__ hs,
                               const float* __restrict__ w_attn,
                               const float* __restrict__ b_attn) {
    int warp = (blockIdx.x * blockDim.x + threadIdx.x) >> 5;
    int lane = threadIdx.x & 31;
    if (warp >= T_TOK) return;
    const float* row = hs + (size_t)warp * HID;
    double acc = 0.0;
    #pragma unroll 8
    for (int i = lane; i < HID; i += 32) acc += (double)row[i] * (double)w_attn[i];
    #pragma unroll
    for (int o = 16; o; o >>= 1) acc += __shfl_xor_sync(0xffffffffu, acc, o);
    if (lane == 0) g_logits[warp] = (float)(acc + (double)b_attn[0]);
}

// ---------------- kernel: span embeddings -------------------------
__global__ void k_span_emb(const float* __restrict__ hs,
                           const int* __restrict__ starts,
                           const int* __restrict__ widths,
                           const float* __restrict__ w_width) {
    int c = blockIdx.x;
    int s = starts[c], w = widths[c];
    int e = s + w, L = w + 1;
    __shared__ float p[32];
    int tid = threadIdx.x;
    if (tid < 32) {
        double lg = (tid < L) ? (double)g_logits[s + tid] : -1e300;
        double mx = lg;
        #pragma unroll
        for (int o = 16; o; o >>= 1) {
            double v = __shfl_xor_sync(0xffffffffu, mx, o);
            mx = fmax(mx, v);
        }
        double ex = (tid < L) ? exp(lg - mx) : 0.0;
        double sm = ex;
        #pragma unroll
        for (int o = 16; o; o >>= 1) sm += __shfl_xor_sync(0xffffffffu, sm, o);
        p[tid] = (float)(ex / sm);
    }
    __syncthreads();
    float* out = g_span_emb + (size_t)c * SPAND;
    const float* hrow_s = hs + (size_t)s * HID;
    const float* hrow_e = hs + (size_t)e * HID;
    for (int h = tid; h < HID; h += blockDim.x) {
        out[h]        = hrow_s[h];
        out[HID + h]  = hrow_e[h];
        float acc = 0.f, cmp = 0.f;
        for (int l = 0; l < L; ++l) {
            float y = __fmaf_rn(p[l], hs[(size_t)(s + l) * HID + h], -cmp);
            float t = __fadd_rn(acc, y);
            cmp = __fsub_rn(__fsub_rn(t, acc), y);
            acc = t;
        }
        out[2 * HID + METAF + h] = acc;
    }
    if (tid < METAF) out[2 * HID + tid] = w_width[w * METAF + tid];
}

// ---------------- split: row-major fp32 -> A-frag-128 -------------
// grid (NKT, rows/128); dynamic smem 128*68*4 B.
__global__ void k_splitA_frag(const float* __restrict__ src,
                              __nv_bfloat16* __restrict__ D0,
                              __nv_bfloat16* __restrict__ D1,
                              __nv_bfloat16* __restrict__ D2) {
    extern __shared__ float ts[];     // [128][68]
    const int tid = threadIdx.x;
    const int kt = blockIdx.x, tm = blockIdx.y;
    for (int i = tid; i < 128 * 16; i += 256) {
        int r = i >> 4, c4 = i & 15;
        int k = kt * 64 + c4 * 4;
        float4 v = make_float4(0.f, 0.f, 0.f, 0.f);
        if (k < SPAND)
            v = *(const float4*)&src[(size_t)(tm * 128 + r) * SPAND + k];
        float* d = &ts[r * 68 + c4 * 4];
        d[0] = v.x; d[1] = v.y; d[2] = v.z; d[3] = v.w;
    }
    __syncthreads();
    size_t wb = (size_t)(tm * NKT + kt) * 4096;
    uint32_t* o0 = (uint32_t*)D0;
    uint32_t* o1 = (uint32_t*)D1;
    uint32_t* o2 = (uint32_t*)D2;
    for (int w = tid; w < 4096; w += 256) {
        int rloc, k16, kp;
        a_inv(w, rloc, k16, kp);
        int kk = k16 * 16 + kp * 2;
        float x0 = ts[rloc * 68 + kk], x1 = ts[rloc * 68 + kk + 1];
        __nv_bfloat16 a0, a1, a2, b0, b1, b2;
        split3(x0, a0, a1, a2);
        split3(x1, b0, b1, b2);
        o0[wb + w] = pack_bf(a0, b0);
        o1[wb + w] = pack_bf(a1, b1);
        if (D2) o2[wb + w] = pack_bf(a2, b2);
    }
}

// ---------------- split: W[K,N] -> B-frag (transpose) -------------
// grid (NKT, ceil(N/BN)); dynamic smem 64*(BN+4)*4.
template<int BN, int NS>
__global__ void k_splitB_frag(const float* __restrict__ W, int ldw, int Kmax, int Nmax,
                              __nv_bfloat16* __restrict__ D0,
                              __nv_bfloat16* __restrict__ D1,
                              __nv_bfloat16* __restrict__ D2) {
    extern __shared__ float ts[];     // [64][BN+4]
    const int PAD = BN + 4;
    const int tid = threadIdx.x;
    const int kt = blockIdx.x, tn = blockIdx.y;
    for (int i = tid; i < 64 * (BN / 4); i += 256) {
        int kk = i / (BN / 4), c4 = i % (BN / 4);
        int gk = kt * 64 + kk, gn = tn * BN + c4 * 4;
        float4 v = make_float4(0.f, 0.f, 0.f, 0.f);
        if (gk < Kmax && gn < Nmax)
            v = *(const float4*)&W[(size_t)gk * ldw + gn];
        float* d = &ts[kk * PAD + c4 * 4];
        d[0] = v.x; d[1] = v.y; d[2] = v.z; d[3] = v.w;
    }
    __syncthreads();
    const int WORDS = BN * 32;
    size_t wb = (size_t)(tn * NKT + kt) * WORDS;
    uint32_t* o0 = (uint32_t*)D0;
    uint32_t* o1 = (uint32_t*)D1;
    uint32_t* o2 = (uint32_t*)D2;
    for (int w = tid; w < WORDS; w += 256) {
        int nloc, k16, kp;
        b_inv<BN>(w, nloc, k16, kp);
        int kk = k16 * 16 + kp * 2;
        float x0 = ts[kk * PAD + nloc], x1 = ts[(kk + 1) * PAD + nloc];
        if (NS == 2) {
            __nv_bfloat16 a0 = __float2bfloat16(x0);
            __nv_bfloat16 a1 = __float2bfloat16(__fsub_rn(x0, __bfloat162float(a0)));
            __nv_bfloat16 b0 = __float2bfloat16(x1);
            __nv_bfloat16 b1 = __float2bfloat16(__fsub_rn(x1, __bfloat162float(b0)));
            o0[wb + w] = pack_bf(a0, b0);
            o1[wb + w] = pack_bf(a1, b1);
        } else {
            __nv_bfloat16 a0, a1, a2, b0, b1, b2;
            split3(x0, a0, a1, a2);
            split3(x1, b0, b1, b2);
            o0[wb + w] = pack_bf(a0, b0);
            o1[wb + w] = pack_bf(a1, b1);
            o2[wb + w] = pack_bf(a2, b2);
        }
    }
}

// ---------------- gathers (frag-to-frag word moves) ---------------
__global__ void k_gatherA() {         // grid (NKT, 8)
    __shared__ int cidx[128];
    const int tid = threadIdx.x;
    const int kt = blockIdx.x, tm = blockIdx.y;
    if (tid < 128) cidx[tid] = g_topidx[tm * 128 + tid];
    __syncthreads();
    size_t wb = (size_t)(tm * NKT + kt) * 4096;
    for (int w = tid; w < 4096; w += 256) {
        int rloc, k16, kp;
        a_inv(w, rloc, k16, kp);
        int ci = cidx[rloc];
        size_t sw = (size_t)((ci >> 7) * NKT + kt) * 4096 + a_word(ci & 127, k16, kp);
        ((uint32_t*)g_ta0)[wb + w] = ((const uint32_t*)g_sa0)[sw];
        ((uint32_t*)g_ta1)[wb + w] = ((const uint32_t*)g_sa1)[sw];
        ((uint32_t*)g_ta2)[wb + w] = ((const uint32_t*)g_sa2)[sw];
    }
}
__global__ void k_gatherB() {         // grid (NKT, 16)
    __shared__ int cidx[64];
    const int tid = threadIdx.x;
    const int kt = blockIdx.x, tn = blockIdx.y;
    if (tid < 64) cidx[tid] = g_topidx[tn * 64 + tid];
    __syncthreads();
    size_t wb = (size_t)(tn * NKT + kt) * 2048;
    for (int w = tid; w < 2048; w += 256) {
        int nloc, k16, kp;
        b_inv<64>(w, nloc, k16, kp);
        int ci = cidx[nloc];
        size_t sw = (size_t)((ci >> 7) * NKT + kt) * 4096 + a_word(ci & 127, k16, kp);
        ((uint32_t*)g_taB0)[wb + w] = ((const uint32_t*)g_sa0)[sw];
        ((uint32_t*)g_taB1)[wb + w] = ((const uint32_t*)g_sa1)[sw];
        ((uint32_t*)g_taB2)[wb + w] = ((const uint32_t*)g_sa2)[sw];
    }
}
__global__ void k_topmeta(float* __restrict__ out_topidx) {
    int t = threadIdx.x;
    int ci = g_topidx[t];
    g_topm[t] = g_mention[ci];
    out_topidx[t] = (float)ci;
}

// ---------------- bf16 MMA ----------------------------------------
__device__ __forceinline__ void mma_bf16(float c[4], const uint4& a, const uint2& b) {
    asm volatile(
        "mma.sync.aligned.m16n8k16.row.col.f32.bf16.bf16.f32 "
        "{%0,%1,%2,%3}, {%4,%5,%6,%7}, {%8,%9}, {%0,%1,%2,%3};"
        : "+f"(c[0]), "+f"(c[1]), "+f"(c[2]), "+f"(c[3])
        : "r"(a.x), "r"(a.y), "r"(a.z), "r"(a.w), "r"(b.x), "r"(b.y));
}

// ---------------- GEMM3: bf16x2 3-pass, cp.async pipelined --------
// 128x128 tile; stage = A(2x16K) + B(2x16K) = 64KB; 2 stages = 128KB.
__global__ __launch_bounds__(256, 1)
void k_gemm3(const float* __restrict__ bias, float* __restrict__ C) {
    extern __shared__ char sm[];
    const int tid = threadIdx.x, lane = tid & 31, wid = tid >> 5;
    const int warp_m = wid >> 1, warp_n = wid & 1;
    const int tm = blockIdx.y, tn = blockIdx.x;
    const __nv_bfloat16* Ab[2] = {g_sa0, g_sa1};
    const __nv_bfloat16* Bb[2] = {g_wb0, g_wb1};

    float c[2][8][4];
    #pragma unroll
    for (int ma = 0; ma < 2; ++ma)
        #pragma unroll
        for (int nb = 0; nb < 8; ++nb)
            #pragma unroll
            for (int q = 0; q < 4; ++q) c[ma][nb][q] = 0.f;

    auto load_tile = [&](int kt, int buf) {
        char* dst = sm + buf * 65536;
        for (int i = tid; i < 4096; i += 256) {
            int region = i >> 10, off = i & 1023;
            const char* src = (region < 2)
                ? (const char*)Ab[region] + ((size_t)(tm * NKT + kt)) * 16384 + (size_t)off * 16
                : (const char*)Bb[region - 2] + ((size_t)(tn * NKT + kt)) * 16384 + (size_t)off * 16;
            CP_ASYNC16(sm_addr(dst + region * 16384 + off * 16), src);
        }
        CP_COMMIT();
    };
    load_tile(0, 0);
    load_tile(1, 1);

    for (int kt = 0; kt < NKT; ++kt) {
        CP_WAIT1();
        __syncthreads();
        char* bA = sm + (kt & 1) * 65536;
        char* bB = bA + 32768;
        #pragma unroll
        for (int k16 = 0; k16 < 4; ++k16) {
            uint4 a[2][2]; uint2 b[2][8];
            #pragma unroll
            for (int s = 0; s < 2; ++s)
                #pragma unroll
                for (int ma = 0; ma < 2; ++ma)
                    a[s][ma] = *(const uint4*)(bA + s * 16384 + k16 * 4096
                                               + (warp_m * 2 + ma) * 512 + lane * 16);
            #pragma unroll
            for (int s = 0; s < 2; ++s)
                #pragma unroll
                for (int nb = 0; nb < 8; ++nb)
                    b[s][nb] = *(const uint2*)(bB + s * 16384 + k16 * 4096
                                               + (warp_n * 8 + nb) * 256 + lane * 8);
            #pragma unroll
            for (int ma = 0; ma < 2; ++ma)
                #pragma unroll
                for (int nb = 0; nb < 8; ++nb) {
                    mma_bf16(c[ma][nb], a[0][ma], b[0][nb]);
                    mma_bf16(c[ma][nb], a[0][ma], b[1][nb]);
                    mma_bf16(c[ma][nb], a[1][ma], b[0][nb]);
                }
        }
        __syncthreads();
        if (kt + 2 < NKT) load_tile(kt + 2, kt & 1);
        else CP_COMMIT();           // keep group-count invariant
    }

    const int g = lane >> 2, t = lane & 3;
    const int row0 = tm * 128, col0 = tn * 128;
    #pragma unroll
    for (int ma = 0; ma < 2; ++ma) {
        int r0 = row0 + (warp_m * 2 + ma) * 16 + g;
        #pragma unroll
        for (int nb = 0; nb < 8; ++nb) {
            int cc = col0 + (warp_n * 8 + nb) * 8 + 2 * t;
            float b0 = bias[cc], b1 = bias[cc + 1];
            float v0 = fmaxf(__fadd_rn(c[ma][nb][0], b0), 0.f);
            float v1 = fmaxf(__fadd_rn(c[ma][nb][1], b1), 0.f);
            float v2 = fmaxf(__fadd_rn(c[ma][nb][2], b0), 0.f);
            float v3 = fmaxf(__fadd_rn(c[ma][nb][3], b1), 0.f);
            *(float2*)&C[(size_t)r0 * UHID + cc] = make_float2(v0, v1);
            *(float2*)&C[(size_t)(r0 + 8) * UHID + cc] = make_float2(v2, v3);
        }
    }
}

// ---------------- GEMM6: bf16x3 6-pass + k32 Kahan, pipelined -----
// 128x64 tile; stage = A(3x16K) + B(3x8K) = 72KB; 2 stages = 144KB.
__global__ __launch_bounds__(256, 1)
void k_gemm6(const __nv_bfloat16* __restrict__ A0, const __nv_bfloat16* __restrict__ A1,
             const __nv_bfloat16* __restrict__ A2,
             const __nv_bfloat16* __restrict__ B0, const __nv_bfloat16* __restrict__ B1,
             const __nv_bfloat16* __restrict__ B2,
             const float* __restrict__ bias, float* __restrict__ C,
             int Nstore, int ldc) {
    extern __shared__ char sm[];
    const int tid = threadIdx.x, lane = tid & 31, wid = tid >> 5;
    const int warp_m = wid >> 1, warp_n = wid & 1;
    const int tm = blockIdx.y, tn = blockIdx.x;
    const __nv_bfloat16* Ab[3] = {A0, A1, A2};
    const __nv_bfloat16* Bb[3] = {B0, B1, B2};

    float acc[2][4][4], cmp[2][4][4];
    #pragma unroll
    for (int ma = 0; ma < 2; ++ma)
        #pragma unroll
        for (int nb = 0; nb < 4; ++nb)
            #pragma unroll
            for (int q = 0; q < 4; ++q) { acc[ma][nb][q] = 0.f; cmp[ma][nb][q] = 0.f; }

    auto load_tile = [&](int kt, int buf) {
        char* dst = sm + buf * 73728;
        for (int i = tid; i < 4608; i += 256) {
            const char* src; uint32_t doff;
            if (i < 3072) {
                int s = i >> 10, off = i & 1023;
                src = (const char*)Ab[s] + ((size_t)(tm * NKT + kt)) * 16384 + (size_t)off * 16;
                doff = s * 16384 + off * 16;
            } else {
                int j = i - 3072;
                int s = j >> 9, off = j & 511;
                src = (const char*)Bb[s] + ((size_t)(tn * NKT + kt)) * 8192 + (size_t)off * 16;
                doff = 49152 + s * 8192 + off * 16;
            }
            CP_ASYNC16(sm_addr(dst + doff), src);
        }
        CP_COMMIT();
    };
    load_tile(0, 0);
    load_tile(1, 1);

    const int pa[6] = {0, 0, 1, 1, 0, 2};
    const int pb[6] = {0, 1, 0, 1, 2, 0};

    for (int kt = 0; kt < NKT; ++kt) {
        CP_WAIT1();
        __syncthreads();
        char* bA = sm + (kt & 1) * 73728;
        char* bB = bA + 49152;
        #pragma unroll
        for (int kh = 0; kh < 2; ++kh) {
            float loc[2][4][4];
            #pragma unroll
            for (int ma = 0; ma < 2; ++ma)
                #pragma unroll
                for (int nb = 0; nb < 4; ++nb)
                    #pragma unroll
                    for (int q = 0; q < 4; ++q) loc[ma][nb][q] = 0.f;
            #pragma unroll
            for (int k16 = 2 * kh; k16 < 2 * kh + 2; ++k16) {
                uint4 a[3][2]; uint2 b[3][4];
                #pragma unroll
                for (int s = 0; s < 3; ++s)
                    #pragma unroll
                    for (int ma = 0; ma < 2; ++ma)
                        a[s][ma] = *(const uint4*)(bA + s * 16384 + k16 * 4096
                                                   + (warp_m * 2 + ma) * 512 + lane * 16);
                #pragma unroll
                for (int s = 0; s < 3; ++s)
                    #pragma unroll
                    for (int nb = 0; nb < 4; ++nb)
                        b[s][nb] = *(const uint2*)(bB + s * 8192 + k16 * 2048
                                                   + (warp_n * 4 + nb) * 256 + lane * 8);
                #pragma unroll
                for (int pr = 0; pr < 6; ++pr)
                    #pragma unroll
                    for (int ma = 0; ma < 2; ++ma)
                        #pragma unroll
                        for (int nb = 0; nb < 4; ++nb)
                            mma_bf16(loc[ma][nb], a[pa[pr]][ma], b[pb[pr]][nb]);
            }
            #pragma unroll
            for (int ma = 0; ma < 2; ++ma)
                #pragma unroll
                for (int nb = 0; nb < 4; ++nb)
                    #pragma unroll
                    for (int q = 0; q < 4; ++q) {
                        float y = __fsub_rn(loc[ma][nb][q], cmp[ma][nb][q]);
                        float t = __fadd_rn(acc[ma][nb][q], y);
                        cmp[ma][nb][q] = __fsub_rn(__fsub_rn(t, acc[ma][nb][q]), y);
                        acc[ma][nb][q] = t;
                    }
        }
        __syncthreads();
        if (kt + 2 < NKT) load_tile(kt + 2, kt & 1);
        else CP_COMMIT();
    }

    const int g = lane >> 2, t = lane & 3;
    const int row0 = tm * 128, col0 = tn * 64;
    #pragma unroll
    for (int ma = 0; ma < 2; ++ma) {
        int r0 = row0 + (warp_m * 2 + ma) * 16 + g;
        #pragma unroll
        for (int nb = 0; nb < 4; ++nb) {
            int cc = col0 + (warp_n * 4 + nb) * 8 + 2 * t;
            if (cc >= Nstore) continue;
            float v0 = acc[ma][nb][0], v1 = acc[ma][nb][1];
            float v2 = acc[ma][nb][2], v3 = acc[ma][nb][3];
            if (bias) {
                float b0 = bias[cc];
                float b1 = (cc + 1 < Nstore) ? bias[cc + 1] : 0.f;
                v0 = __fadd_rn(v0, b0); v1 = __fadd_rn(v1, b1);
                v2 = __fadd_rn(v2, b0); v3 = __fadd_rn(v3, b1);
            }
            if (cc + 1 < Nstore) {
                *(float2*)&C[(size_t)r0 * ldc + cc] = make_float2(v0, v1);
                *(float2*)&C[(size_t)(r0 + 8) * ldc + cc] = make_float2(v2, v3);
            } else {
                C[(size_t)r0 * ldc + cc] = v0;
                C[(size_t)(r0 + 8) * ldc + cc] = v2;
            }
        }
    }
}

// ---------------- mention score -----------------------------------
__global__ void k_score(const float* __restrict__ w_u2,
                        const float* __restrict__ b_u2) {
    int warp = (blockIdx.x * blockDim.x + threadIdx.x) >> 5;
    int lane = threadIdx.x & 31;
    if (warp >= C_SP) return;
    const float* row = g_hid1 + (size_t)warp * UHID;
    double acc = 0.0;
    #pragma unroll 8
    for (int i = lane; i < UHID; i += 32) acc += (double)row[i] * (double)w_u2[i];
    #pragma unroll
    for (int o = 16; o; o >>= 1) acc += __shfl_xor_sync(0xffffffffu, acc, o);
    if (lane == 0) g_mention[warp] = (float)(acc + (double)b_u2[0]);
}

// ---------------- sort + greedy + compact -------------------------
__global__ void k_extract(const int* __restrict__ starts,
                          const int* __restrict__ widths) {
    extern __shared__ int sh[];
    float* key = (float*)sh;
    int* idx = sh + 4096;
    int* es  = sh + 8192;
    int* flg = sh + 12288;
    const int tid = threadIdx.x;

    for (int i = tid; i < C_SP; i += 1024) {
        key[i] = g_mention[i];
        idx[i] = i;
        flg[i] = 0;
    }
    __syncthreads();

    for (unsigned k = 2; k <= 4096; k <<= 1) {
        for (unsigned j = k >> 1; j > 0; j >>= 1) {
            for (unsigned t = tid; t < 2048; t += 1024) {
                unsigned i = ((t & ~(j - 1)) << 1) | (t & (j - 1));
                unsigned l = i | j;
                float ki = key[i], kl = key[l];
                int   ii = idx[i], il = idx[l];
                bool before_l_i = (kl > ki) || (kl == ki && il < ii);
                bool dir = ((i & k) == 0);
                if (before_l_i == dir) {
                    key[i] = kl; key[l] = ki;
                    idx[i] = il; idx[l] = ii;
                }
            }
            __syncthreads();
        }
    }

    volatile int* le = (volatile int*)key;
    volatile int* ves = (volatile int*)es;
    for (int i = tid; i < T_TOK; i += 1024) {
        ((int*)key)[i] = -1;
        es[i] = T_TOK;
    }
    __syncthreads();

    if (tid < 32) {
        int lane = tid;
        int count = 0;
        for (int p = 0; p < C_SP && count < M_TOP; ++p) {
            int ci = idx[p];
            int s = starts[ci];
            int w = widths[ci];
            int e = s + w;
            bool crossing = false;
            if (lane < w) {
                crossing = (le[s + 1 + lane] > e) | (ves[s + lane] < s);
            }
            unsigned m = __ballot_sync(0xffffffffu, crossing);
            if (m == 0u) {
                if (lane == 0) {
                    int cur = le[s]; if (e > cur) ((int*)key)[s] = e;
                    int cur2 = ves[e]; if (s < cur2) es[e] = s;
                    flg[ci] = 1;
                }
                count++;
            }
            __syncwarp();
        }
    }
    __syncthreads();

    __shared__ int wsum[32];
    __shared__ int woff[33];
    int base = tid * 4;
    int f0 = flg[base], f1 = flg[base + 1], f2 = flg[base + 2], f3 = flg[base + 3];
    int c = f0 + f1 + f2 + f3;
    int inc = c;
    int lane = tid & 31, wid = tid >> 5;
    #pragma unroll
    for (int o = 1; o < 32; o <<= 1) {
        int n = __shfl_up_sync(0xffffffffu, inc, o);
        if (lane >= o) inc += n;
    }
    if (lane == 31) wsum[wid] = inc;
    __syncthreads();
    if (tid == 0) {
        int run = 0;
        for (int i = 0; i < 32; ++i) { woff[i] = run; run += wsum[i]; }
        woff[32] = run;
    }
    __syncthreads();
    int pos = woff[wid] + (inc - c);
    if (f0) { if (pos < M_TOP) g_topidx[pos] = base;     pos++; }
    if (f1) { if (pos < M_TOP) g_topidx[pos] = base + 1; pos++; }
    if (f2) { if (pos < M_TOP) g_topidx[pos] = base + 2; pos++; }
    if (f3) { if (pos < M_TOP) g_topidx[pos] = base + 3; pos++; }
    int total = woff[32];
    for (int p = total + tid; p < M_TOP; p += 1024) g_topidx[p] = C_SP - 1;
}

// ---------------- fast scores + per-row top-50 --------------------
__global__ void k_topk(float* __restrict__ out_ant,
                       float* __restrict__ out_mask,
                       float* __restrict__ out_score) {
    __shared__ float v[M_TOP];
    __shared__ float rv[256];
    __shared__ int   ri[256];
    const int i = blockIdx.x;
    const int tid = threadIdx.x;
    const float mi = g_topm[i];
    for (int j = tid; j < M_TOP; j += 256) {
        float val = __fadd_rn(__fadd_rn(__fadd_rn(mi, g_topm[j]),
                                        (j < i) ? 0.f : NEGV),
                              g_fast[(size_t)i * M_TOP + j]);
        v[j] = val;
    }
    __syncthreads();
    for (int k = 0; k < K_ANT; ++k) {
        float bv = -INFINITY; int bi = M_TOP;
        for (int j = tid; j < M_TOP; j += 256) {
            float x = v[j];
            if (x > bv || (x == bv && j < bi)) { bv = x; bi = j; }
        }
        rv[tid] = bv; ri[tid] = bi;
        __syncthreads();
        for (int s = 128; s > 0; s >>= 1) {
            if (tid < s) {
                if (rv[tid + s] > rv[tid] ||
                    (rv[tid + s] == rv[tid] && ri[tid + s] < ri[tid])) {
                    rv[tid] = rv[tid + s]; ri[tid] = ri[tid + s];
                }
            }
            __syncthreads();
        }
        if (tid == 0) {
            int j = ri[0];
            out_ant[(size_t)i * K_ANT + k]   = (float)j;
            out_mask[(size_t)i * K_ANT + k]  = (j < i) ? 1.f : 0.f;
            out_score[(size_t)i * K_ANT + k] = rv[0];
            v[j] = -INFINITY;
        }
        __syncthreads();
    }
}

// ---------------- launch ------------------------------------------
extern "C" void kernel_launch(void* const* d_in, const int* in_sizes, int n_in,
                              void* d_out, int out_size) {
    const float* hs      = (const float*)d_in[0];
    const int*   starts  = (const int*)d_in[1];
    const int*   widths  = (const int*)d_in[2];
    int base = 3;
    if (n_in >= 14 && in_sizes[3] == 1 && in_sizes[4] == 1) base = 5;
    const float* w_width = (const float*)d_in[base + 0];
    const float* w_attn  = (const float*)d_in[base + 1];
    const float* b_attn  = (const float*)d_in[base + 2];
    const float* w_u1    = (const float*)d_in[base + 3];
    const float* b_u1    = (const float*)d_in[base + 4];
    const float* w_u2    = (const float*)d_in[base + 5];
    const float* b_u2    = (const float*)d_in[base + 6];
    const float* w_fast  = (const float*)d_in[base + 7];
    const float* b_fast  = (const float*)d_in[base + 8];

    float* out = (float*)d_out;
    float* out_topidx = out;
    float* out_ant    = out + M_TOP;
    float* out_mask   = out + M_TOP + M_TOP * K_ANT;
    float* out_score  = out + M_TOP + 2 * M_TOP * K_ANT;

    float *p_span, *p_hid1, *p_tmp, *p_fast;
    __nv_bfloat16 *p_sa0, *p_sa1, *p_sa2, *p_wb0, *p_wb1;
    __nv_bfloat16 *p_fb0, *p_fb1, *p_fb2;
    __nv_bfloat16 *p_ta0, *p_ta1, *p_ta2, *p_taB0, *p_taB1, *p_taB2;
    __nv_bfloat16 *p_tb0, *p_tb1, *p_tb2;
    cudaGetSymbolAddress((void**)&p_span, g_span_emb);
    cudaGetSymbolAddress((void**)&p_hid1, g_hid1);
    cudaGetSymbolAddress((void**)&p_tmp,  g_tmp);
    cudaGetSymbolAddress((void**)&p_fast, g_fast);
    cudaGetSymbolAddress((void**)&p_sa0, g_sa0);
    cudaGetSymbolAddress((void**)&p_sa1, g_sa1);
    cudaGetSymbolAddress((void**)&p_sa2, g_sa2);
    cudaGetSymbolAddress((void**)&p_wb0, g_wb0);
    cudaGetSymbolAddress((void**)&p_wb1, g_wb1);
    cudaGetSymbolAddress((void**)&p_fb0, g_fbx0);
    cudaGetSymbolAddress((void**)&p_fb1, g_fbx1);
    cudaGetSymbolAddress((void**)&p_fb2, g_fbx2);
    cudaGetSymbolAddress((void**)&p_ta0, g_ta0);
    cudaGetSymbolAddress((void**)&p_ta1, g_ta1);
    cudaGetSymbolAddress((void**)&p_ta2, g_ta2);
    cudaGetSymbolAddress((void**)&p_taB0, g_taB0);
    cudaGetSymbolAddress((void**)&p_taB1, g_taB1);
    cudaGetSymbolAddress((void**)&p_taB2, g_taB2);
    cudaGetSymbolAddress((void**)&p_tb0, g_tb0);
    cudaGetSymbolAddress((void**)&p_tb1, g_tb1);
    cudaGetSymbolAddress((void**)&p_tb2, g_tb2);

    cudaFuncSetAttribute(k_gemm3, cudaFuncAttributeMaxDynamicSharedMemorySize, 131072);
    cudaFuncSetAttribute(k_gemm6, cudaFuncAttributeMaxDynamicSharedMemorySize, 147456);
    cudaFuncSetAttribute(k_extract, cudaFuncAttributeMaxDynamicSharedMemorySize, 65536);

    const int smA  = 128 * 68 * 4;       // k_splitA_frag
    const int smB128 = 64 * 132 * 4;     // k_splitB_frag<128,2>
    const int smB64  = 64 * 68 * 4;      // k_splitB_frag<64,3>

    // independent weight splits first
    { dim3 g(NKT, UHID / 128);
      k_splitB_frag<128, 2><<<g, 256, smB128>>>(w_u1, UHID, SPAND, UHID,
                                                p_wb0, p_wb1, nullptr); }
    { dim3 g(NKT, NKT);
      k_splitB_frag<64, 3><<<g, 256, smB64>>>(w_fast, SPAND, SPAND, SPAND,
                                              p_fb0, p_fb1, p_fb2); }
    // mention path
    k_token_logits<<<T_TOK * 32 / 256, 256>>>(hs, w_attn, b_attn);
    k_span_emb<<<C_SP, 256>>>(hs, starts, widths, w_width);
    { dim3 g(NKT, C_SP / 128);
      k_splitA_frag<<<g, 256, smA>>>(p_span, p_sa0, p_sa1, p_sa2); }
    { dim3 g(UHID / 128, C_SP / 128);
      k_gemm3<<<g, 256, 131072>>>(b_u1, p_hid1); }
    k_score<<<C_SP * 32 / 256, 256>>>(w_u2, b_u2);
    k_extract<<<1, 1024, 65536>>>(starts, widths);
    k_topmeta<<<1, 1024>>>(out_topidx);
    { dim3 g(NKT, 8);  k_gatherA<<<g, 256>>>(); }
    { dim3 g(NKT, 16); k_gatherB<<<g, 256>>>(); }
    // antecedent path
    { dim3 g(NKT, M_TOP / 128);   // GEMM7: [1024,3136] <- ta @ fb
      k_gemm6<<<g, 256, 147456>>>(p_ta0, p_ta1, p_ta2, p_fb0, p_fb1, p_fb2,
                                  b_fast, p_tmp, SPAND, SPAND); }
    { dim3 g(NKT, M_TOP / 128);
      k_splitA_frag<<<g, 256, smA>>>(p_tmp, p_tb0, p_tb1, p_tb2); }
    { dim3 g(M_TOP / 64, M_TOP / 128);  // GEMM8: [1024,1024] <- tb @ taB
      k_gemm6<<<g, 256, 147456>>>(p_tb0, p_tb1, p_tb2, p_taB0, p_taB1, p_taB2,
                                  nullptr, p_fast, M_TOP, M_TOP); }
    k_topk<<<M_TOP, 256>>>(out_ant, out_mask, out_score);

    (void)in_sizes; (void)n_in; (void)out_size;
}

// round 13
// speedup vs baseline: 5.4386x; 1.0282x over previous
#include <cuda_runtime.h>
#include <cuda_bf16.h>
#include <math.h>
#include <float.h>
#include <stdint.h>

// ---------------- problem constants -------------------------------
#define T_TOK 4096
#define C_SP  4096
#define HID   1024
#define METAF 20
#define SPAND 3092
#define UHID  1024
#define M_TOP 1024
#define K_ANT 50
#define NEGV  (-1e30f)
#define KPAD  3136
#define NKT   49            // KPAD/64 k-tiles

// ---------------- device scratch ----------------------------------
__device__ float g_logits[T_TOK];
__device__ float g_span_emb[(size_t)C_SP * SPAND];
__device__ float g_hid1[(size_t)C_SP * UHID];
__device__ float g_mention[C_SP];
__device__ int   g_topidx[M_TOP];
__device__ float g_topm[M_TOP];
__device__ float g_tmp[(size_t)M_TOP * SPAND];
__device__ float g_fast[(size_t)M_TOP * M_TOP];
// fragment-major bf16 split operands
__device__ __nv_bfloat16 g_sa0[(size_t)C_SP * KPAD];   // span_emb, A-frag-128
__device__ __nv_bfloat16 g_sa1[(size_t)C_SP * KPAD];
__device__ __nv_bfloat16 g_sa2[(size_t)C_SP * KPAD];
__device__ __nv_bfloat16 g_wb0[(size_t)UHID * KPAD];   // w_u1^T, B-frag-128
__device__ __nv_bfloat16 g_wb1[(size_t)UHID * KPAD];
__device__ __nv_bfloat16 g_fbx0[(size_t)KPAD * KPAD];  // w_fast^T, B-frag-64
__device__ __nv_bfloat16 g_fbx1[(size_t)KPAD * KPAD];
__device__ __nv_bfloat16 g_fbx2[(size_t)KPAD * KPAD];
__device__ __nv_bfloat16 g_ta0[(size_t)M_TOP * KPAD];  // top_emb, A-frag-128
__device__ __nv_bfloat16 g_ta1[(size_t)M_TOP * KPAD];
__device__ __nv_bfloat16 g_ta2[(size_t)M_TOP * KPAD];
__device__ __nv_bfloat16 g_taB0[(size_t)M_TOP * KPAD]; // top_emb, B-frag-64
__device__ __nv_bfloat16 g_taB1[(size_t)M_TOP * KPAD];
__device__ __nv_bfloat16 g_taB2[(size_t)M_TOP * KPAD];
__device__ __nv_bfloat16 g_tb0[(size_t)M_TOP * KPAD];  // tmp, A-frag-128
__device__ __nv_bfloat16 g_tb1[(size_t)M_TOP * KPAD];
__device__ __nv_bfloat16 g_tb2[(size_t)M_TOP * KPAD];

// ---------------- fragment-layout helpers -------------------------
__device__ __forceinline__ uint32_t a_word(int rloc, int k16, int kp) {
    int rr = rloc & 15;
    return (uint32_t)(k16 * 1024 + (rloc >> 4) * 128
                      + ((rr & 7) * 4 + (kp & 3)) * 4 + (rr >> 3) + 2 * (kp >> 2));
}
__device__ __forceinline__ void a_inv(int w, int& rloc, int& k16, int& kp) {
    k16 = w >> 10; int r = w & 1023;
    int matom = r >> 7; int r2 = r & 127;
    int lane = r2 >> 2, j = r2 & 3;
    int rr = (lane >> 2) + 8 * (j & 1);
    kp = (lane & 3) + 4 * (j >> 1);
    rloc = matom * 16 + rr;
}
template<int BN>
__device__ __forceinline__ void b_inv(int w, int& nloc, int& k16, int& kp) {
    if (BN == 128) { k16 = w >> 10; } else { k16 = w >> 9; }
    int r = w & (BN * 8 - 1);
    int natom = r >> 6; int r2 = r & 63;
    int lane = r2 >> 1, j = r2 & 1;
    kp = (lane & 3) + 4 * j;
    nloc = natom * 8 + (lane >> 2);
}

__device__ __forceinline__ uint32_t pack_bf(__nv_bfloat16 lo, __nv_bfloat16 hi) {
    return (uint32_t)__bfloat16_as_ushort(lo) | ((uint32_t)__bfloat16_as_ushort(hi) << 16);
}
__device__ __forceinline__ void split3(float x, __nv_bfloat16& o0,
                                       __nv_bfloat16& o1, __nv_bfloat16& o2) {
    __nv_bfloat16 b0 = __float2bfloat16(x);
    float r1 = __fsub_rn(x, __bfloat162float(b0));
    __nv_bfloat16 b1 = __float2bfloat16(r1);
    float r2 = __fsub_rn(r1, __bfloat162float(b1));
    o0 = b0; o1 = b1; o2 = __float2bfloat16(r2);
}

#define CP_ASYNC16(smaddr, gptr) \
    asm volatile("cp.async.cg.shared.global [%0], [%1], 16;\n" :: "r"(smaddr), "l"(gptr))
#define CP_COMMIT() asm volatile("cp.async.commit_group;\n" ::: "memory")
#define CP_WAIT1()  asm volatile("cp.async.wait_group 1;\n" ::: "memory")

__device__ __forceinline__ uint32_t sm_addr(const void* p) {
    return (uint32_t)__cvta_generic_to_shared(p);
}

// ---------------- kernel: token logits ----------------------------
__global__ void k_token_logits(const float* __restrict__ hs,
                               const float* __restrict__ w_attn,
                               const float* __restrict__ b_attn) {
    int warp = (blockIdx.x * blockDim.x + threadIdx.x) >> 5;
    int lane = threadIdx.x & 31;
    if (warp >= T_TOK) return;
    const float* row = hs + (size_t)warp * HID;
    double acc = 0.0;
    #pragma unroll 8
    for (int i = lane; i < HID; i += 32) acc += (double)row[i] * (double)w_attn[i];
    #pragma unroll
    for (int o = 16; o; o >>= 1) acc += __shfl_xor_sync(0xffffffffu, acc, o);
    if (lane == 0) g_logits[warp] = (float)(acc + (double)b_attn[0]);
}

// ---------------- kernel: span embeddings -------------------------
__global__ void k_span_emb(const float* __restrict__ hs,
                           const int* __restrict__ starts,
                           const int* __restrict__ widths,
                           const float* __restrict__ w_width) {
    int c = blockIdx.x;
    int s = starts[c], w = widths[c];
    int e = s + w, L = w + 1;
    __shared__ float p[32];
    int tid = threadIdx.x;
    if (tid < 32) {
        double lg = (tid < L) ? (double)g_logits[s + tid] : -1e300;
        double mx = lg;
        #pragma unroll
        for (int o = 16; o; o >>= 1) {
            double v = __shfl_xor_sync(0xffffffffu, mx, o);
            mx = fmax(mx, v);
        }
        double ex = (tid < L) ? exp(lg - mx) : 0.0;
        double sm = ex;
        #pragma unroll
        for (int o = 16; o; o >>= 1) sm += __shfl_xor_sync(0xffffffffu, sm, o);
        p[tid] = (float)(ex / sm);
    }
    __syncthreads();
    float* out = g_span_emb + (size_t)c * SPAND;
    const float* hrow_s = hs + (size_t)s * HID;
    const float* hrow_e = hs + (size_t)e * HID;
    for (int h = tid; h < HID; h += blockDim.x) {
        out[h]        = hrow_s[h];
        out[HID + h]  = hrow_e[h];
        float acc = 0.f, cmp = 0.f;
        for (int l = 0; l < L; ++l) {
            float y = __fmaf_rn(p[l], hs[(size_t)(s + l) * HID + h], -cmp);
            float t = __fadd_rn(acc, y);
            cmp = __fsub_rn(__fsub_rn(t, acc), y);
            acc = t;
        }
        out[2 * HID + METAF + h] = acc;
    }
    if (tid < METAF) out[2 * HID + tid] = w_width[w * METAF + tid];
}

// ---------------- split: row-major fp32 -> A-frag-128 -------------
__global__ void k_splitA_frag(const float* __restrict__ src,
                              __nv_bfloat16* __restrict__ D0,
                              __nv_bfloat16* __restrict__ D1,
                              __nv_bfloat16* __restrict__ D2) {
    extern __shared__ float ts[];     // [128][68]
    const int tid = threadIdx.x;
    const int kt = blockIdx.x, tm = blockIdx.y;
    for (int i = tid; i < 128 * 16; i += 256) {
        int r = i >> 4, c4 = i & 15;
        int k = kt * 64 + c4 * 4;
        float4 v = make_float4(0.f, 0.f, 0.f, 0.f);
        if (k < SPAND)
            v = *(const float4*)&src[(size_t)(tm * 128 + r) * SPAND + k];
        float* d = &ts[r * 68 + c4 * 4];
        d[0] = v.x; d[1] = v.y; d[2] = v.z; d[3] = v.w;
    }
    __syncthreads();
    size_t wb = (size_t)(tm * NKT + kt) * 4096;
    uint32_t* o0 = (uint32_t*)D0;
    uint32_t* o1 = (uint32_t*)D1;
    uint32_t* o2 = (uint32_t*)D2;
    for (int w = tid; w < 4096; w += 256) {
        int rloc, k16, kp;
        a_inv(w, rloc, k16, kp);
        int kk = k16 * 16 + kp * 2;
        float x0 = ts[rloc * 68 + kk], x1 = ts[rloc * 68 + kk + 1];
        __nv_bfloat16 a0, a1, a2, b0, b1, b2;
        split3(x0, a0, a1, a2);
        split3(x1, b0, b1, b2);
        o0[wb + w] = pack_bf(a0, b0);
        o1[wb + w] = pack_bf(a1, b1);
        if (D2) o2[wb + w] = pack_bf(a2, b2);
    }
}

// ---------------- split: W[K,N] -> B-frag (transpose) -------------
template<int BN, int NS>
__global__ void k_splitB_frag(const float* __restrict__ W, int ldw, int Kmax, int Nmax,
                              __nv_bfloat16* __restrict__ D0,
                              __nv_bfloat16* __restrict__ D1,
                              __nv_bfloat16* __restrict__ D2) {
    extern __shared__ float ts[];     // [64][BN+4]
    const int PAD = BN + 4;
    const int tid = threadIdx.x;
    const int kt = blockIdx.x, tn = blockIdx.y;
    for (int i = tid; i < 64 * (BN / 4); i += 256) {
        int kk = i / (BN / 4), c4 = i % (BN / 4);
        int gk = kt * 64 + kk, gn = tn * BN + c4 * 4;
        float4 v = make_float4(0.f, 0.f, 0.f, 0.f);
        if (gk < Kmax && gn < Nmax)
            v = *(const float4*)&W[(size_t)gk * ldw + gn];
        float* d = &ts[kk * PAD + c4 * 4];
        d[0] = v.x; d[1] = v.y; d[2] = v.z; d[3] = v.w;
    }
    __syncthreads();
    const int WORDS = BN * 32;
    size_t wb = (size_t)(tn * NKT + kt) * WORDS;
    uint32_t* o0 = (uint32_t*)D0;
    uint32_t* o1 = (uint32_t*)D1;
    uint32_t* o2 = (uint32_t*)D2;
    for (int w = tid; w < WORDS; w += 256) {
        int nloc, k16, kp;
        b_inv<BN>(w, nloc, k16, kp);
        int kk = k16 * 16 + kp * 2;
        float x0 = ts[kk * PAD + nloc], x1 = ts[(kk + 1) * PAD + nloc];
        if (NS == 2) {
            __nv_bfloat16 a0 = __float2bfloat16(x0);
            __nv_bfloat16 a1 = __float2bfloat16(__fsub_rn(x0, __bfloat162float(a0)));
            __nv_bfloat16 b0 = __float2bfloat16(x1);
            __nv_bfloat16 b1 = __float2bfloat16(__fsub_rn(x1, __bfloat162float(b0)));
            o0[wb + w] = pack_bf(a0, b0);
            o1[wb + w] = pack_bf(a1, b1);
        } else {
            __nv_bfloat16 a0, a1, a2, b0, b1, b2;
            split3(x0, a0, a1, a2);
            split3(x1, b0, b1, b2);
            o0[wb + w] = pack_bf(a0, b0);
            o1[wb + w] = pack_bf(a1, b1);
            o2[wb + w] = pack_bf(a2, b2);
        }
    }
}

// ---------------- gathers -----------------------------------------
__global__ void k_gatherA() {         // grid (NKT, 8)
    __shared__ int cidx[128];
    const int tid = threadIdx.x;
    const int kt = blockIdx.x, tm = blockIdx.y;
    if (tid < 128) cidx[tid] = g_topidx[tm * 128 + tid];
    __syncthreads();
    size_t wb = (size_t)(tm * NKT + kt) * 4096;
    for (int w = tid; w < 4096; w += 256) {
        int rloc, k16, kp;
        a_inv(w, rloc, k16, kp);
        int ci = cidx[rloc];
        size_t sw = (size_t)((ci >> 7) * NKT + kt) * 4096 + a_word(ci & 127, k16, kp);
        ((uint32_t*)g_ta0)[wb + w] = ((const uint32_t*)g_sa0)[sw];
        ((uint32_t*)g_ta1)[wb + w] = ((const uint32_t*)g_sa1)[sw];
        ((uint32_t*)g_ta2)[wb + w] = ((const uint32_t*)g_sa2)[sw];
    }
}
__global__ void k_gatherB() {         // grid (NKT, 16)
    __shared__ int cidx[64];
    const int tid = threadIdx.x;
    const int kt = blockIdx.x, tn = blockIdx.y;
    if (tid < 64) cidx[tid] = g_topidx[tn * 64 + tid];
    __syncthreads();
    size_t wb = (size_t)(tn * NKT + kt) * 2048;
    for (int w = tid; w < 2048; w += 256) {
        int nloc, k16, kp;
        b_inv<64>(w, nloc, k16, kp);
        int ci = cidx[nloc];
        size_t sw = (size_t)((ci >> 7) * NKT + kt) * 4096 + a_word(ci & 127, k16, kp);
        ((uint32_t*)g_taB0)[wb + w] = ((const uint32_t*)g_sa0)[sw];
        ((uint32_t*)g_taB1)[wb + w] = ((const uint32_t*)g_sa1)[sw];
        ((uint32_t*)g_taB2)[wb + w] = ((const uint32_t*)g_sa2)[sw];
    }
}
__global__ void k_topmeta(float* __restrict__ out_topidx) {
    int t = threadIdx.x;
    int ci = g_topidx[t];
    g_topm[t] = g_mention[ci];
    out_topidx[t] = (float)ci;
}

// ---------------- bf16 MMA ----------------------------------------
__device__ __forceinline__ void mma_bf16(float c[4], const uint4& a, const uint2& b) {
    asm volatile(
        "mma.sync.aligned.m16n8k16.row.col.f32.bf16.bf16.f32 "
        "{%0,%1,%2,%3}, {%4,%5,%6,%7}, {%8,%9}, {%0,%1,%2,%3};"
        : "+f"(c[0]), "+f"(c[1]), "+f"(c[2]), "+f"(c[3])
        : "r"(a.x), "r"(a.y), "r"(a.z), "r"(a.w), "r"(b.x), "r"(b.y));
}

// ---------------- GEMM3: bf16x2 3-pass, cp.async pipelined --------
__global__ __launch_bounds__(256, 1)
void k_gemm3(const float* __restrict__ bias, float* __restrict__ C) {
    extern __shared__ char sm[];
    const int tid = threadIdx.x, lane = tid & 31, wid = tid >> 5;
    const int warp_m = wid >> 1, warp_n = wid & 1;
    const int tm = blockIdx.y, tn = blockIdx.x;
    const __nv_bfloat16* Ab[2] = {g_sa0, g_sa1};
    const __nv_bfloat16* Bb[2] = {g_wb0, g_wb1};

    float c[2][8][4];
    #pragma unroll
    for (int ma = 0; ma < 2; ++ma)
        #pragma unroll
        for (int nb = 0; nb < 8; ++nb)
            #pragma unroll
            for (int q = 0; q < 4; ++q) c[ma][nb][q] = 0.f;

    auto load_tile = [&](int kt, int buf) {
        char* dst = sm + buf * 65536;
        for (int i = tid; i < 4096; i += 256) {
            int region = i >> 10, off = i & 1023;
            const char* src = (region < 2)
                ? (const char*)Ab[region] + ((size_t)(tm * NKT + kt)) * 16384 + (size_t)off * 16
                : (const char*)Bb[region - 2] + ((size_t)(tn * NKT + kt)) * 16384 + (size_t)off * 16;
            CP_ASYNC16(sm_addr(dst + region * 16384 + off * 16), src);
        }
        CP_COMMIT();
    };
    load_tile(0, 0);
    load_tile(1, 1);

    for (int kt = 0; kt < NKT; ++kt) {
        CP_WAIT1();
        __syncthreads();
        char* bA = sm + (kt & 1) * 65536;
        char* bB = bA + 32768;
        #pragma unroll
        for (int k16 = 0; k16 < 4; ++k16) {
            uint4 a[2][2]; uint2 b[2][8];
            #pragma unroll
            for (int s = 0; s < 2; ++s)
                #pragma unroll
                for (int ma = 0; ma < 2; ++ma)
                    a[s][ma] = *(const uint4*)(bA + s * 16384 + k16 * 4096
                                               + (warp_m * 2 + ma) * 512 + lane * 16);
            #pragma unroll
            for (int s = 0; s < 2; ++s)
                #pragma unroll
                for (int nb = 0; nb < 8; ++nb)
                    b[s][nb] = *(const uint2*)(bB + s * 16384 + k16 * 4096
                                               + (warp_n * 8 + nb) * 256 + lane * 8);
            #pragma unroll
            for (int ma = 0; ma < 2; ++ma)
                #pragma unroll
                for (int nb = 0; nb < 8; ++nb) {
                    mma_bf16(c[ma][nb], a[0][ma], b[0][nb]);
                    mma_bf16(c[ma][nb], a[0][ma], b[1][nb]);
                    mma_bf16(c[ma][nb], a[1][ma], b[0][nb]);
                }
        }
        __syncthreads();
        if (kt + 2 < NKT) load_tile(kt + 2, kt & 1);
        else CP_COMMIT();
    }

    const int g = lane >> 2, t = lane & 3;
    const int row0 = tm * 128, col0 = tn * 128;
    #pragma unroll
    for (int ma = 0; ma < 2; ++ma) {
        int r0 = row0 + (warp_m * 2 + ma) * 16 + g;
        #pragma unroll
        for (int nb = 0; nb < 8; ++nb) {
            int cc = col0 + (warp_n * 8 + nb) * 8 + 2 * t;
            float b0 = bias[cc], b1 = bias[cc + 1];
            float v0 = fmaxf(__fadd_rn(c[ma][nb][0], b0), 0.f);
            float v1 = fmaxf(__fadd_rn(c[ma][nb][1], b1), 0.f);
            float v2 = fmaxf(__fadd_rn(c[ma][nb][2], b0), 0.f);
            float v3 = fmaxf(__fadd_rn(c[ma][nb][3], b1), 0.f);
            *(float2*)&C[(size_t)r0 * UHID + cc] = make_float2(v0, v1);
            *(float2*)&C[(size_t)(r0 + 8) * UHID + cc] = make_float2(v2, v3);
        }
    }
}

// ---------------- GEMM6: bf16x3 6-pass + per-kt Kahan, pipelined --
// R13: Kahan fold once per k64 tile (was per k32). Noise ~1.4e-5,
// still 3.5x under the ~5e-5 flip boundary; halves Kahan op count.
__global__ __launch_bounds__(256, 1)
void k_gemm6(const __nv_bfloat16* __restrict__ A0, const __nv_bfloat16* __restrict__ A1,
             const __nv_bfloat16* __restrict__ A2,
             const __nv_bfloat16* __restrict__ B0, const __nv_bfloat16* __restrict__ B1,
             const __nv_bfloat16* __restrict__ B2,
             const float* __restrict__ bias, float* __restrict__ C,
             int Nstore, int ldc) {
    extern __shared__ char sm[];
    const int tid = threadIdx.x, lane = tid & 31, wid = tid >> 5;
    const int warp_m = wid >> 1, warp_n = wid & 1;
    const int tm = blockIdx.y, tn = blockIdx.x;
    const __nv_bfloat16* Ab[3] = {A0, A1, A2};
    const __nv_bfloat16* Bb[3] = {B0, B1, B2};

    float acc[2][4][4], cmp[2][4][4];
    #pragma unroll
    for (int ma = 0; ma < 2; ++ma)
        #pragma unroll
        for (int nb = 0; nb < 4; ++nb)
            #pragma unroll
            for (int q = 0; q < 4; ++q) { acc[ma][nb][q] = 0.f; cmp[ma][nb][q] = 0.f; }

    auto load_tile = [&](int kt, int buf) {
        char* dst = sm + buf * 73728;
        for (int i = tid; i < 4608; i += 256) {
            const char* src; uint32_t doff;
            if (i < 3072) {
                int s = i >> 10, off = i & 1023;
                src = (const char*)Ab[s] + ((size_t)(tm * NKT + kt)) * 16384 + (size_t)off * 16;
                doff = s * 16384 + off * 16;
            } else {
                int j = i - 3072;
                int s = j >> 9, off = j & 511;
                src = (const char*)Bb[s] + ((size_t)(tn * NKT + kt)) * 8192 + (size_t)off * 16;
                doff = 49152 + s * 8192 + off * 16;
            }
            CP_ASYNC16(sm_addr(dst + doff), src);
        }
        CP_COMMIT();
    };
    load_tile(0, 0);
    load_tile(1, 1);

    const int pa[6] = {0, 0, 1, 1, 0, 2};
    const int pb[6] = {0, 1, 0, 1, 2, 0};

    for (int kt = 0; kt < NKT; ++kt) {
        CP_WAIT1();
        __syncthreads();
        char* bA = sm + (kt & 1) * 73728;
        char* bB = bA + 49152;
        float loc[2][4][4];
        #pragma unroll
        for (int ma = 0; ma < 2; ++ma)
            #pragma unroll
            for (int nb = 0; nb < 4; ++nb)
                #pragma unroll
                for (int q = 0; q < 4; ++q) loc[ma][nb][q] = 0.f;
        #pragma unroll
        for (int k16 = 0; k16 < 4; ++k16) {
            uint4 a[3][2]; uint2 b[3][4];
            #pragma unroll
            for (int s = 0; s < 3; ++s)
                #pragma unroll
                for (int ma = 0; ma < 2; ++ma)
                    a[s][ma] = *(const uint4*)(bA + s * 16384 + k16 * 4096
                                               + (warp_m * 2 + ma) * 512 + lane * 16);
            #pragma unroll
            for (int s = 0; s < 3; ++s)
                #pragma unroll
                for (int nb = 0; nb < 4; ++nb)
                    b[s][nb] = *(const uint2*)(bB + s * 8192 + k16 * 2048
                                               + (warp_n * 4 + nb) * 256 + lane * 8);
            #pragma unroll
            for (int pr = 0; pr < 6; ++pr)
                #pragma unroll
                for (int ma = 0; ma < 2; ++ma)
                    #pragma unroll
                    for (int nb = 0; nb < 4; ++nb)
                        mma_bf16(loc[ma][nb], a[pa[pr]][ma], b[pb[pr]][nb]);
        }
        // exact Kahan fold of k64 partial into master (once per kt)
        #pragma unroll
        for (int ma = 0; ma < 2; ++ma)
            #pragma unroll
            for (int nb = 0; nb < 4; ++nb)
                #pragma unroll
                for (int q = 0; q < 4; ++q) {
                    float y = __fsub_rn(loc[ma][nb][q], cmp[ma][nb][q]);
                    float t = __fadd_rn(acc[ma][nb][q], y);
                    cmp[ma][nb][q] = __fsub_rn(__fsub_rn(t, acc[ma][nb][q]), y);
                    acc[ma][nb][q] = t;
                }
        __syncthreads();
        if (kt + 2 < NKT) load_tile(kt + 2, kt & 1);
        else CP_COMMIT();
    }

    const int g = lane >> 2, t = lane & 3;
    const int row0 = tm * 128, col0 = tn * 64;
    #pragma unroll
    for (int ma = 0; ma < 2; ++ma) {
        int r0 = row0 + (warp_m * 2 + ma) * 16 + g;
        #pragma unroll
        for (int nb = 0; nb < 4; ++nb) {
            int cc = col0 + (warp_n * 4 + nb) * 8 + 2 * t;
            if (cc >= Nstore) continue;
            float v0 = acc[ma][nb][0], v1 = acc[ma][nb][1];
            float v2 = acc[ma][nb][2], v3 = acc[ma][nb][3];
            if (bias) {
                float b0 = bias[cc];
                float b1 = (cc + 1 < Nstore) ? bias[cc + 1] : 0.f;
                v0 = __fadd_rn(v0, b0); v1 = __fadd_rn(v1, b1);
                v2 = __fadd_rn(v2, b0); v3 = __fadd_rn(v3, b1);
            }
            if (cc + 1 < Nstore) {
                *(float2*)&C[(size_t)r0 * ldc + cc] = make_float2(v0, v1);
                *(float2*)&C[(size_t)(r0 + 8) * ldc + cc] = make_float2(v2, v3);
            } else {
                C[(size_t)r0 * ldc + cc] = v0;
                C[(size_t)(r0 + 8) * ldc + cc] = v2;
            }
        }
    }
}

// ---------------- mention score -----------------------------------
__global__ void k_score(const float* __restrict__ w_u2,
                        const float* __restrict__ b_u2) {
    int warp = (blockIdx.x * blockDim.x + threadIdx.x) >> 5;
    int lane = threadIdx.x & 31;
    if (warp >= C_SP) return;
    const float* row = g_hid1 + (size_t)warp * UHID;
    double acc = 0.0;
    #pragma unroll 8
    for (int i = lane; i < UHID; i += 32) acc += (double)row[i] * (double)w_u2[i];
    #pragma unroll
    for (int o = 16; o; o >>= 1) acc += __shfl_xor_sync(0xffffffffu, acc, o);
    if (lane == 0) g_mention[warp] = (float)(acc + (double)b_u2[0]);
}

// ---------------- sort + greedy + compact -------------------------
// R13: hybrid bitonic — phases with distance j<=64 run warp-locally in
// registers (element e owned as e = warp*128 + lane*4 + q); identical
// comparator (desc key, ties asc idx, dir = ((i&k)==0)).
__device__ __forceinline__ bool sort_before(float xk, int xi, float yk, int yi) {
    return (xk > yk) || (xk == yk && xi < yi);
}

__global__ void k_extract(const int* __restrict__ starts,
                          const int* __restrict__ widths) {
    extern __shared__ int sh[];
    float* key = (float*)sh;
    int* idx = sh + 4096;
    int* es  = sh + 8192;
    int* flg = sh + 12288;
    const int tid = threadIdx.x;       // 1024 threads
    const int ln32 = tid & 31, wrp = tid >> 5;
    const int ebase = wrp * 128 + ln32 * 4;

    for (int i = tid; i < C_SP; i += 1024) flg[i] = 0;

    float kq[4]; int iq[4];
    #pragma unroll
    for (int q = 0; q < 4; ++q) { kq[q] = g_mention[ebase + q]; iq[q] = ebase + q; }

    auto reg_phase = [&](unsigned k, unsigned j) {
        if (j >= 4) {
            unsigned lm = j >> 2;
            #pragma unroll
            for (int q = 0; q < 4; ++q) {
                float pk = __shfl_xor_sync(0xffffffffu, kq[q], lm);
                int   pi = __shfl_xor_sync(0xffffffffu, iq[q], lm);
                int e = ebase + q;
                int i = e & ~(int)j;
                bool dir = ((i & (int)k) == 0);
                bool swp;
                if ((e & (int)j) == 0)
                    swp = (sort_before(pk, pi, kq[q], iq[q]) == dir);
                else
                    swp = (sort_before(kq[q], iq[q], pk, pi) == dir);
                if (swp) { kq[q] = pk; iq[q] = pi; }
            }
        } else if (j == 2) {
            #pragma unroll
            for (int q = 0; q < 2; ++q) {
                int i = ebase + q;
                bool dir = ((i & (int)k) == 0);
                if (sort_before(kq[q + 2], iq[q + 2], kq[q], iq[q]) == dir) {
                    float tk = kq[q]; int ti = iq[q];
                    kq[q] = kq[q + 2]; iq[q] = iq[q + 2];
                    kq[q + 2] = tk; iq[q + 2] = ti;
                }
            }
        } else {
            #pragma unroll
            for (int q = 0; q < 4; q += 2) {
                int i = ebase + q;
                bool dir = ((i & (int)k) == 0);
                if (sort_before(kq[q + 1], iq[q + 1], kq[q], iq[q]) == dir) {
                    float tk = kq[q]; int ti = iq[q];
                    kq[q] = kq[q + 1]; iq[q] = iq[q + 1];
                    kq[q + 1] = tk; iq[q + 1] = ti;
                }
            }
        }
    };

    // rounds k=2..128 entirely in registers (no block syncs)
    for (unsigned k = 2; k <= 128; k <<= 1)
        for (unsigned j = k >> 1; j > 0; j >>= 1) reg_phase(k, j);
    #pragma unroll
    for (int q = 0; q < 4; ++q) { key[ebase + q] = kq[q]; idx[ebase + q] = iq[q]; }
    __syncthreads();

    // rounds k=256..4096: smem phases for j>=128, register phases j<=64
    for (unsigned k = 256; k <= 4096; k <<= 1) {
        for (unsigned j = k >> 1; j >= 128; j >>= 1) {
            for (unsigned t = tid; t < 2048; t += 1024) {
                unsigned i = ((t & ~(j - 1)) << 1) | (t & (j - 1));
                unsigned l = i | j;
                float ki = key[i], kl = key[l];
                int   ii = idx[i], il = idx[l];
                bool before_l_i = (kl > ki) || (kl == ki && il < ii);
                bool dir = ((i & k) == 0);
                if (before_l_i == dir) {
                    key[i] = kl; key[l] = ki;
                    idx[i] = il; idx[l] = ii;
                }
            }
            __syncthreads();
        }
        #pragma unroll
        for (int q = 0; q < 4; ++q) { kq[q] = key[ebase + q]; iq[q] = idx[ebase + q]; }
        for (unsigned j = 64; j > 0; j >>= 1) reg_phase(k, j);
        #pragma unroll
        for (int q = 0; q < 4; ++q) { key[ebase + q] = kq[q]; idx[ebase + q] = iq[q]; }
        __syncthreads();
    }

    volatile int* le = (volatile int*)key;
    volatile int* ves = (volatile int*)es;
    for (int i = tid; i < T_TOK; i += 1024) {
        ((int*)key)[i] = -1;
        es[i] = T_TOK;
    }
    __syncthreads();

    if (tid < 32) {
        int lane = tid;
        int count = 0;
        for (int p = 0; p < C_SP && count < M_TOP; ++p) {
            int ci = idx[p];
            int s = starts[ci];
            int w = widths[ci];
            int e = s + w;
            bool crossing = false;
            if (lane < w) {
                crossing = (le[s + 1 + lane] > e) | (ves[s + lane] < s);
            }
            unsigned m = __ballot_sync(0xffffffffu, crossing);
            if (m == 0u) {
                if (lane == 0) {
                    int cur = le[s]; if (e > cur) ((int*)key)[s] = e;
                    int cur2 = ves[e]; if (s < cur2) es[e] = s;
                    flg[ci] = 1;
                }
                count++;
            }
            __syncwarp();
        }
    }
    __syncthreads();

    __shared__ int wsum[32];
    __shared__ int woff[33];
    int base = tid * 4;
    int f0 = flg[base], f1 = flg[base + 1], f2 = flg[base + 2], f3 = flg[base + 3];
    int c = f0 + f1 + f2 + f3;
    int inc = c;
    int lane = tid & 31, wid = tid >> 5;
    #pragma unroll
    for (int o = 1; o < 32; o <<= 1) {
        int n = __shfl_up_sync(0xffffffffu, inc, o);
        if (lane >= o) inc += n;
    }
    if (lane == 31) wsum[wid] = inc;
    __syncthreads();
    if (tid == 0) {
        int run = 0;
        for (int i = 0; i < 32; ++i) { woff[i] = run; run += wsum[i]; }
        woff[32] = run;
    }
    __syncthreads();
    int pos = woff[wid] + (inc - c);
    if (f0) { if (pos < M_TOP) g_topidx[pos] = base;     pos++; }
    if (f1) { if (pos < M_TOP) g_topidx[pos] = base + 1; pos++; }
    if (f2) { if (pos < M_TOP) g_topidx[pos] = base + 2; pos++; }
    if (f3) { if (pos < M_TOP) g_topidx[pos] = base + 3; pos++; }
    int total = woff[32];
    for (int p = total + tid; p < M_TOP; p += 1024) g_topidx[p] = C_SP - 1;
}

// ---------------- fast scores + per-row top-50 --------------------
// R13: warp-shuffle reduction (2 barriers/iter instead of 9)
__global__ void k_topk(float* __restrict__ out_ant,
                       float* __restrict__ out_mask,
                       float* __restrict__ out_score) {
    __shared__ float v[M_TOP];
    __shared__ float wv[8];
    __shared__ int   wi[8];
    const int i = blockIdx.x;
    const int tid = threadIdx.x;
    const int lane = tid & 31, wid = tid >> 5;
    const float mi = g_topm[i];
    for (int j = tid; j < M_TOP; j += 256) {
        float val = __fadd_rn(__fadd_rn(__fadd_rn(mi, g_topm[j]),
                                        (j < i) ? 0.f : NEGV),
                              g_fast[(size_t)i * M_TOP + j]);
        v[j] = val;
    }
    __syncthreads();
    for (int k = 0; k < K_ANT; ++k) {
        float bv = -INFINITY; int bi = M_TOP;
        for (int j = tid; j < M_TOP; j += 256) {
            float x = v[j];
            if (x > bv || (x == bv && j < bi)) { bv = x; bi = j; }
        }
        #pragma unroll
        for (int o = 16; o; o >>= 1) {
            float ok = __shfl_xor_sync(0xffffffffu, bv, o);
            int   oi = __shfl_xor_sync(0xffffffffu, bi, o);
            if (ok > bv || (ok == bv && oi < bi)) { bv = ok; bi = oi; }
        }
        if (lane == 0) { wv[wid] = bv; wi[wid] = bi; }
        __syncthreads();
        if (tid == 0) {
            float fv = wv[0]; int fi = wi[0];
            #pragma unroll
            for (int w = 1; w < 8; ++w)
                if (wv[w] > fv || (wv[w] == fv && wi[w] < fi)) { fv = wv[w]; fi = wi[w]; }
            out_ant[(size_t)i * K_ANT + k]   = (float)fi;
            out_mask[(size_t)i * K_ANT + k]  = (fi < i) ? 1.f : 0.f;
            out_score[(size_t)i * K_ANT + k] = fv;
            v[fi] = -INFINITY;
        }
        __syncthreads();
    }
}

// ---------------- launch ------------------------------------------
extern "C" void kernel_launch(void* const* d_in, const int* in_sizes, int n_in,
                              void* d_out, int out_size) {
    const float* hs      = (const float*)d_in[0];
    const int*   starts  = (const int*)d_in[1];
    const int*   widths  = (const int*)d_in[2];
    int base = 3;
    if (n_in >= 14 && in_sizes[3] == 1 && in_sizes[4] == 1) base = 5;
    const float* w_width = (const float*)d_in[base + 0];
    const float* w_attn  = (const float*)d_in[base + 1];
    const float* b_attn  = (const float*)d_in[base + 2];
    const float* w_u1    = (const float*)d_in[base + 3];
    const float* b_u1    = (const float*)d_in[base + 4];
    const float* w_u2    = (const float*)d_in[base + 5];
    const float* b_u2    = (const float*)d_in[base + 6];
    const float* w_fast  = (const float*)d_in[base + 7];
    const float* b_fast  = (const float*)d_in[base + 8];

    float* out = (float*)d_out;
    float* out_topidx = out;
    float* out_ant    = out + M_TOP;
    float* out_mask   = out + M_TOP + M_TOP * K_ANT;
    float* out_score  = out + M_TOP + 2 * M_TOP * K_ANT;

    float *p_span, *p_hid1, *p_tmp, *p_fast;
    __nv_bfloat16 *p_sa0, *p_sa1, *p_sa2, *p_wb0, *p_wb1;
    __nv_bfloat16 *p_fb0, *p_fb1, *p_fb2;
    __nv_bfloat16 *p_ta0, *p_ta1, *p_ta2, *p_taB0, *p_taB1, *p_taB2;
    __nv_bfloat16 *p_tb0, *p_tb1, *p_tb2;
    cudaGetSymbolAddress((void**)&p_span, g_span_emb);
    cudaGetSymbolAddress((void**)&p_hid1, g_hid1);
    cudaGetSymbolAddress((void**)&p_tmp,  g_tmp);
    cudaGetSymbolAddress((void**)&p_fast, g_fast);
    cudaGetSymbolAddress((void**)&p_sa0, g_sa0);
    cudaGetSymbolAddress((void**)&p_sa1, g_sa1);
    cudaGetSymbolAddress((void**)&p_sa2, g_sa2);
    cudaGetSymbolAddress((void**)&p_wb0, g_wb0);
    cudaGetSymbolAddress((void**)&p_wb1, g_wb1);
    cudaGetSymbolAddress((void**)&p_fb0, g_fbx0);
    cudaGetSymbolAddress((void**)&p_fb1, g_fbx1);
    cudaGetSymbolAddress((void**)&p_fb2, g_fbx2);
    cudaGetSymbolAddress((void**)&p_ta0, g_ta0);
    cudaGetSymbolAddress((void**)&p_ta1, g_ta1);
    cudaGetSymbolAddress((void**)&p_ta2, g_ta2);
    cudaGetSymbolAddress((void**)&p_taB0, g_taB0);
    cudaGetSymbolAddress((void**)&p_taB1, g_taB1);
    cudaGetSymbolAddress((void**)&p_taB2, g_taB2);
    cudaGetSymbolAddress((void**)&p_tb0, g_tb0);
    cudaGetSymbolAddress((void**)&p_tb1, g_tb1);
    cudaGetSymbolAddress((void**)&p_tb2, g_tb2);

    cudaFuncSetAttribute(k_gemm3, cudaFuncAttributeMaxDynamicSharedMemorySize, 131072);
    cudaFuncSetAttribute(k_gemm6, cudaFuncAttributeMaxDynamicSharedMemorySize, 147456);
    cudaFuncSetAttribute(k_extract, cudaFuncAttributeMaxDynamicSharedMemorySize, 65536);

    const int smA    = 128 * 68 * 4;
    const int smB128 = 64 * 132 * 4;
    const int smB64  = 64 * 68 * 4;

    // independent weight splits first
    { dim3 g(NKT, UHID / 128);
      k_splitB_frag<128, 2><<<g, 256, smB128>>>(w_u1, UHID, SPAND, UHID,
                                                p_wb0, p_wb1, nullptr); }
    { dim3 g(NKT, NKT);
      k_splitB_frag<64, 3><<<g, 256, smB64>>>(w_fast, SPAND, SPAND, SPAND,
                                              p_fb0, p_fb1, p_fb2); }
    // mention path
    k_token_logits<<<T_TOK * 32 / 256, 256>>>(hs, w_attn, b_attn);
    k_span_emb<<<C_SP, 256>>>(hs, starts, widths, w_width);
    { dim3 g(NKT, C_SP / 128);
      k_splitA_frag<<<g, 256, smA>>>(p_span, p_sa0, p_sa1, p_sa2); }
    { dim3 g(UHID / 128, C_SP / 128);
      k_gemm3<<<g, 256, 131072>>>(b_u1, p_hid1); }
    k_score<<<C_SP * 32 / 256, 256>>>(w_u2, b_u2);
    k_extract<<<1, 1024, 65536>>>(starts, widths);
    k_topmeta<<<1, 1024>>>(out_topidx);
    { dim3 g(NKT, 8);  k_gatherA<<<g, 256>>>(); }
    { dim3 g(NKT, 16); k_gatherB<<<g, 256>>>(); }
    // antecedent path
    { dim3 g(NKT, M_TOP / 128);
      k_gemm6<<<g, 256, 147456>>>(p_ta0, p_ta1, p_ta2, p_fb0, p_fb1, p_fb2,
                                  b_fast, p_tmp, SPAND, SPAND); }
    { dim3 g(NKT, M_TOP / 128);
      k_splitA_frag<<<g, 256, smA>>>(p_tmp, p_tb0, p_tb1, p_tb2); }
    { dim3 g(M_TOP / 64, M_TOP / 128);
      k_gemm6<<<g, 256, 147456>>>(p_tb0, p_tb1, p_tb2, p_taB0, p_taB1, p_taB2,
                                  nullptr, p_fast, M_TOP, M_TOP); }
    k_topk<<<M_TOP, 256>>>(out_ant, out_mask, out_score);

    (void)in_sizes; (void)n_in; (void)out_size;
}

// round 14
// speedup vs baseline: 5.4781x; 1.0073x over previous
#include <cuda_runtime.h>
#include <cuda_bf16.h>
#include <math.h>
#include <float.h>
#include <stdint.h>

// ---------------- problem constants -------------------------------
#define T_TOK 4096
#define C_SP  4096
#define HID   1024
#define METAF 20
#define SPAND 3092
#define UHID  1024
#define M_TOP 1024
#define K_ANT 50
#define NEGV  (-1e30f)
#define KPAD  3136
#define NKT   49            // KPAD/64 k-tiles

// ---------------- device scratch ----------------------------------
__device__ float g_logits[T_TOK];
__device__ float g_span_emb[(size_t)C_SP * SPAND];
__device__ float g_hid1[(size_t)C_SP * UHID];
__device__ float g_mention[C_SP];
__device__ int   g_topidx[M_TOP];
__device__ float g_topm[M_TOP];
__device__ float g_tmp[(size_t)M_TOP * SPAND];
__device__ float g_fast[(size_t)M_TOP * M_TOP];
// fragment-major bf16 split operands
__device__ __nv_bfloat16 g_sa0[(size_t)C_SP * KPAD];   // span_emb, A-frag-128
__device__ __nv_bfloat16 g_sa1[(size_t)C_SP * KPAD];
__device__ __nv_bfloat16 g_sa2[(size_t)C_SP * KPAD];
__device__ __nv_bfloat16 g_wb0[(size_t)UHID * KPAD];   // w_u1^T, B-frag-128
__device__ __nv_bfloat16 g_wb1[(size_t)UHID * KPAD];
__device__ __nv_bfloat16 g_fbx0[(size_t)KPAD * KPAD];  // w_fast^T, B-frag-64
__device__ __nv_bfloat16 g_fbx1[(size_t)KPAD * KPAD];
__device__ __nv_bfloat16 g_fbx2[(size_t)KPAD * KPAD];
__device__ __nv_bfloat16 g_ta0[(size_t)M_TOP * KPAD];  // top_emb, A-frag-128
__device__ __nv_bfloat16 g_ta1[(size_t)M_TOP * KPAD];
__device__ __nv_bfloat16 g_ta2[(size_t)M_TOP * KPAD];
__device__ __nv_bfloat16 g_taB0[(size_t)M_TOP * KPAD]; // top_emb, B-frag-64
__device__ __nv_bfloat16 g_taB1[(size_t)M_TOP * KPAD];
__device__ __nv_bfloat16 g_taB2[(size_t)M_TOP * KPAD];
__device__ __nv_bfloat16 g_tb0[(size_t)M_TOP * KPAD];  // tmp, A-frag-128
__device__ __nv_bfloat16 g_tb1[(size_t)M_TOP * KPAD];
__device__ __nv_bfloat16 g_tb2[(size_t)M_TOP * KPAD];

// ---------------- fragment-layout helpers -------------------------
__device__ __forceinline__ uint32_t a_word(int rloc, int k16, int kp) {
    int rr = rloc & 15;
    return (uint32_t)(k16 * 1024 + (rloc >> 4) * 128
                      + ((rr & 7) * 4 + (kp & 3)) * 4 + (rr >> 3) + 2 * (kp >> 2));
}
__device__ __forceinline__ void a_inv(int w, int& rloc, int& k16, int& kp) {
    k16 = w >> 10; int r = w & 1023;
    int matom = r >> 7; int r2 = r & 127;
    int lane = r2 >> 2, j = r2 & 3;
    int rr = (lane >> 2) + 8 * (j & 1);
    kp = (lane & 3) + 4 * (j >> 1);
    rloc = matom * 16 + rr;
}
template<int BN>
__device__ __forceinline__ void b_inv(int w, int& nloc, int& k16, int& kp) {
    if (BN == 128) { k16 = w >> 10; } else { k16 = w >> 9; }
    int r = w & (BN * 8 - 1);
    int natom = r >> 6; int r2 = r & 63;
    int lane = r2 >> 1, j = r2 & 1;
    kp = (lane & 3) + 4 * j;
    nloc = natom * 8 + (lane >> 2);
}

__device__ __forceinline__ uint32_t pack_bf(__nv_bfloat16 lo, __nv_bfloat16 hi) {
    return (uint32_t)__bfloat16_as_ushort(lo) | ((uint32_t)__bfloat16_as_ushort(hi) << 16);
}
__device__ __forceinline__ void split3(float x, __nv_bfloat16& o0,
                                       __nv_bfloat16& o1, __nv_bfloat16& o2) {
    __nv_bfloat16 b0 = __float2bfloat16(x);
    float r1 = __fsub_rn(x, __bfloat162float(b0));
    __nv_bfloat16 b1 = __float2bfloat16(r1);
    float r2 = __fsub_rn(r1, __bfloat162float(b1));
    o0 = b0; o1 = b1; o2 = __float2bfloat16(r2);
}

#define CP_ASYNC16(smaddr, gptr) \
    asm volatile("cp.async.cg.shared.global [%0], [%1], 16;\n" :: "r"(smaddr), "l"(gptr))
#define CP_COMMIT() asm volatile("cp.async.commit_group;\n" ::: "memory")
#define CP_WAIT1()  asm volatile("cp.async.wait_group 1;\n" ::: "memory")
#define CP_WAIT0()  asm volatile("cp.async.wait_group 0;\n" ::: "memory")

__device__ __forceinline__ uint32_t sm_addr(const void* p) {
    return (uint32_t)__cvta_generic_to_shared(p);
}

// ---------------- fused pre-kernel: token logits + w_u1 split -----
// blocks [0,512): token logits (warp-per-token, fp64 accumulate)
// blocks [512,904): w_u1[K,N] -> wb0/wb1 B-frag-128 tiles (NS=2)
__global__ void k_pre(const float* __restrict__ hs,
                      const float* __restrict__ w_attn,
                      const float* __restrict__ b_attn,
                      const float* __restrict__ w_u1) {
    extern __shared__ float ts[];     // used by split blocks: [64][132]
    const int tid = threadIdx.x;
    if (blockIdx.x < 512) {
        int warp = (blockIdx.x * 256 + tid) >> 5;
        int lane = tid & 31;
        const float* row = hs + (size_t)warp * HID;
        double acc = 0.0;
        #pragma unroll 8
        for (int i = lane; i < HID; i += 32) acc += (double)row[i] * (double)w_attn[i];
        #pragma unroll
        for (int o = 16; o; o >>= 1) acc += __shfl_xor_sync(0xffffffffu, acc, o);
        if (lane == 0) g_logits[warp] = (float)(acc + (double)b_attn[0]);
        return;
    }
    const int bi = blockIdx.x - 512;
    const int kt = bi % NKT, tn = bi / NKT;
    const int PAD = 132;
    for (int i = tid; i < 64 * 32; i += 256) {
        int kk = i >> 5, c4 = i & 31;
        int gk = kt * 64 + kk, gn = tn * 128 + c4 * 4;
        float4 v = make_float4(0.f, 0.f, 0.f, 0.f);
        if (gk < SPAND)
            v = *(const float4*)&w_u1[(size_t)gk * UHID + gn];
        float* d = &ts[kk * PAD + c4 * 4];
        d[0] = v.x; d[1] = v.y; d[2] = v.z; d[3] = v.w;
    }
    __syncthreads();
    size_t wb = (size_t)(tn * NKT + kt) * 4096;
    uint32_t* o0 = (uint32_t*)g_wb0;
    uint32_t* o1 = (uint32_t*)g_wb1;
    for (int w = tid; w < 4096; w += 256) {
        int nloc, k16, kp;
        b_inv<128>(w, nloc, k16, kp);
        int kk = k16 * 16 + kp * 2;
        float x0 = ts[kk * PAD + nloc], x1 = ts[(kk + 1) * PAD + nloc];
        __nv_bfloat16 a0 = __float2bfloat16(x0);
        __nv_bfloat16 a1 = __float2bfloat16(__fsub_rn(x0, __bfloat162float(a0)));
        __nv_bfloat16 b0 = __float2bfloat16(x1);
        __nv_bfloat16 b1 = __float2bfloat16(__fsub_rn(x1, __bfloat162float(b0)));
        o0[wb + w] = pack_bf(a0, b0);
        o1[wb + w] = pack_bf(a1, b1);
    }
}

// ---------------- kernel: span embeddings -------------------------
__global__ void k_span_emb(const float* __restrict__ hs,
                           const int* __restrict__ starts,
                           const int* __restrict__ widths,
                           const float* __restrict__ w_width) {
    int c = blockIdx.x;
    int s = starts[c], w = widths[c];
    int e = s + w, L = w + 1;
    __shared__ float p[32];
    int tid = threadIdx.x;
    if (tid < 32) {
        double lg = (tid < L) ? (double)g_logits[s + tid] : -1e300;
        double mx = lg;
        #pragma unroll
        for (int o = 16; o; o >>= 1) {
            double v = __shfl_xor_sync(0xffffffffu, mx, o);
            mx = fmax(mx, v);
        }
        double ex = (tid < L) ? exp(lg - mx) : 0.0;
        double sm = ex;
        #pragma unroll
        for (int o = 16; o; o >>= 1) sm += __shfl_xor_sync(0xffffffffu, sm, o);
        p[tid] = (float)(ex / sm);
    }
    __syncthreads();
    float* out = g_span_emb + (size_t)c * SPAND;
    const float* hrow_s = hs + (size_t)s * HID;
    const float* hrow_e = hs + (size_t)e * HID;
    for (int h = tid; h < HID; h += blockDim.x) {
        out[h]        = hrow_s[h];
        out[HID + h]  = hrow_e[h];
        float acc = 0.f, cmp = 0.f;
        for (int l = 0; l < L; ++l) {
            float y = __fmaf_rn(p[l], hs[(size_t)(s + l) * HID + h], -cmp);
            float t = __fadd_rn(acc, y);
            cmp = __fsub_rn(__fsub_rn(t, acc), y);
            acc = t;
        }
        out[2 * HID + METAF + h] = acc;
    }
    if (tid < METAF) out[2 * HID + tid] = w_width[w * METAF + tid];
}

// ---------------- split: row-major fp32 -> A-frag-128 -------------
__global__ void k_splitA_frag(const float* __restrict__ src,
                              __nv_bfloat16* __restrict__ D0,
                              __nv_bfloat16* __restrict__ D1,
                              __nv_bfloat16* __restrict__ D2) {
    extern __shared__ float ts[];     // [128][68]
    const int tid = threadIdx.x;
    const int kt = blockIdx.x, tm = blockIdx.y;
    for (int i = tid; i < 128 * 16; i += 256) {
        int r = i >> 4, c4 = i & 15;
        int k = kt * 64 + c4 * 4;
        float4 v = make_float4(0.f, 0.f, 0.f, 0.f);
        if (k < SPAND)
            v = *(const float4*)&src[(size_t)(tm * 128 + r) * SPAND + k];
        float* d = &ts[r * 68 + c4 * 4];
        d[0] = v.x; d[1] = v.y; d[2] = v.z; d[3] = v.w;
    }
    __syncthreads();
    size_t wb = (size_t)(tm * NKT + kt) * 4096;
    uint32_t* o0 = (uint32_t*)D0;
    uint32_t* o1 = (uint32_t*)D1;
    uint32_t* o2 = (uint32_t*)D2;
    for (int w = tid; w < 4096; w += 256) {
        int rloc, k16, kp;
        a_inv(w, rloc, k16, kp);
        int kk = k16 * 16 + kp * 2;
        float x0 = ts[rloc * 68 + kk], x1 = ts[rloc * 68 + kk + 1];
        __nv_bfloat16 a0, a1, a2, b0, b1, b2;
        split3(x0, a0, a1, a2);
        split3(x1, b0, b1, b2);
        o0[wb + w] = pack_bf(a0, b0);
        o1[wb + w] = pack_bf(a1, b1);
        if (D2) o2[wb + w] = pack_bf(a2, b2);
    }
}

// ---------------- split: w_fast[K,N] -> B-frag-64 x3 --------------
__global__ void k_splitB64(const float* __restrict__ W) {
    extern __shared__ float ts[];     // [64][68]
    const int PAD = 68;
    const int tid = threadIdx.x;
    const int kt = blockIdx.x, tn = blockIdx.y;
    for (int i = tid; i < 64 * 16; i += 256) {
        int kk = i >> 4, c4 = i & 15;
        int gk = kt * 64 + kk, gn = tn * 64 + c4 * 4;
        float4 v = make_float4(0.f, 0.f, 0.f, 0.f);
        if (gk < SPAND && gn < SPAND)
            v = *(const float4*)&W[(size_t)gk * SPAND + gn];
        float* d = &ts[kk * PAD + c4 * 4];
        d[0] = v.x; d[1] = v.y; d[2] = v.z; d[3] = v.w;
    }
    __syncthreads();
    size_t wb = (size_t)(tn * NKT + kt) * 2048;
    uint32_t* o0 = (uint32_t*)g_fbx0;
    uint32_t* o1 = (uint32_t*)g_fbx1;
    uint32_t* o2 = (uint32_t*)g_fbx2;
    for (int w = tid; w < 2048; w += 256) {
        int nloc, k16, kp;
        b_inv<64>(w, nloc, k16, kp);
        int kk = k16 * 16 + kp * 2;
        float x0 = ts[kk * PAD + nloc], x1 = ts[(kk + 1) * PAD + nloc];
        __nv_bfloat16 a0, a1, a2, b0, b1, b2;
        split3(x0, a0, a1, a2);
        split3(x1, b0, b1, b2);
        o0[wb + w] = pack_bf(a0, b0);
        o1[wb + w] = pack_bf(a1, b1);
        o2[wb + w] = pack_bf(a2, b2);
    }
}

// ---------------- gathers -----------------------------------------
__global__ void k_gatherA() {         // grid (NKT, 8)
    __shared__ int cidx[128];
    const int tid = threadIdx.x;
    const int kt = blockIdx.x, tm = blockIdx.y;
    if (tid < 128) cidx[tid] = g_topidx[tm * 128 + tid];
    __syncthreads();
    size_t wb = (size_t)(tm * NKT + kt) * 4096;
    for (int w = tid; w < 4096; w += 256) {
        int rloc, k16, kp;
        a_inv(w, rloc, k16, kp);
        int ci = cidx[rloc];
        size_t sw = (size_t)((ci >> 7) * NKT + kt) * 4096 + a_word(ci & 127, k16, kp);
        ((uint32_t*)g_ta0)[wb + w] = ((const uint32_t*)g_sa0)[sw];
        ((uint32_t*)g_ta1)[wb + w] = ((const uint32_t*)g_sa1)[sw];
        ((uint32_t*)g_ta2)[wb + w] = ((const uint32_t*)g_sa2)[sw];
    }
}
__global__ void k_gatherB() {         // grid (NKT, 16)
    __shared__ int cidx[64];
    const int tid = threadIdx.x;
    const int kt = blockIdx.x, tn = blockIdx.y;
    if (tid < 64) cidx[tid] = g_topidx[tn * 64 + tid];
    __syncthreads();
    size_t wb = (size_t)(tn * NKT + kt) * 2048;
    for (int w = tid; w < 2048; w += 256) {
        int nloc, k16, kp;
        b_inv<64>(w, nloc, k16, kp);
        int ci = cidx[nloc];
        size_t sw = (size_t)((ci >> 7) * NKT + kt) * 4096 + a_word(ci & 127, k16, kp);
        ((uint32_t*)g_taB0)[wb + w] = ((const uint32_t*)g_sa0)[sw];
        ((uint32_t*)g_taB1)[wb + w] = ((const uint32_t*)g_sa1)[sw];
        ((uint32_t*)g_taB2)[wb + w] = ((const uint32_t*)g_sa2)[sw];
    }
}
__global__ void k_topmeta(float* __restrict__ out_topidx) {
    int t = threadIdx.x;
    int ci = g_topidx[t];
    g_topm[t] = g_mention[ci];
    out_topidx[t] = (float)ci;
}

// ---------------- bf16 MMA ----------------------------------------
__device__ __forceinline__ void mma_bf16(float c[4], const uint4& a, const uint2& b) {
    asm volatile(
        "mma.sync.aligned.m16n8k16.row.col.f32.bf16.bf16.f32 "
        "{%0,%1,%2,%3}, {%4,%5,%6,%7}, {%8,%9}, {%0,%1,%2,%3};"
        : "+f"(c[0]), "+f"(c[1]), "+f"(c[2]), "+f"(c[3])
        : "r"(a.x), "r"(a.y), "r"(a.z), "r"(a.w), "r"(b.x), "r"(b.y));
}

// ---------------- GEMM3: bf16x2 3-pass, single-stage 2 CTA/SM -----
// R14 experiment: 64KB single-stage smem + __launch_bounds__(256,2).
// Cross-CTA overlap replaces intra-CTA double buffering; 16 warps/SM
// (4/SMSP) to test whether HMMA time is stall-bound vs rate-bound.
__global__ __launch_bounds__(256, 2)
void k_gemm3(const float* __restrict__ bias, float* __restrict__ C) {
    extern __shared__ char sm[];
    const int tid = threadIdx.x, lane = tid & 31, wid = tid >> 5;
    const int warp_m = wid >> 1, warp_n = wid & 1;
    const int tm = blockIdx.y, tn = blockIdx.x;
    const __nv_bfloat16* Ab[2] = {g_sa0, g_sa1};
    const __nv_bfloat16* Bb[2] = {g_wb0, g_wb1};

    float c[2][8][4];
    #pragma unroll
    for (int ma = 0; ma < 2; ++ma)
        #pragma unroll
        for (int nb = 0; nb < 8; ++nb)
            #pragma unroll
            for (int q = 0; q < 4; ++q) c[ma][nb][q] = 0.f;

    auto load_tile = [&](int kt) {
        for (int i = tid; i < 4096; i += 256) {
            int region = i >> 10, off = i & 1023;
            const char* src = (region < 2)
                ? (const char*)Ab[region] + ((size_t)(tm * NKT + kt)) * 16384 + (size_t)off * 16
                : (const char*)Bb[region - 2] + ((size_t)(tn * NKT + kt)) * 16384 + (size_t)off * 16;
            CP_ASYNC16(sm_addr(sm + region * 16384 + off * 16), src);
        }
        CP_COMMIT();
    };
    load_tile(0);

    for (int kt = 0; kt < NKT; ++kt) {
        CP_WAIT0();
        __syncthreads();
        char* bA = sm;
        char* bB = sm + 32768;
        #pragma unroll
        for (int k16 = 0; k16 < 4; ++k16) {
            uint4 a[2][2]; uint2 b[2][8];
            #pragma unroll
            for (int s = 0; s < 2; ++s)
                #pragma unroll
                for (int ma = 0; ma < 2; ++ma)
                    a[s][ma] = *(const uint4*)(bA + s * 16384 + k16 * 4096
                                               + (warp_m * 2 + ma) * 512 + lane * 16);
            #pragma unroll
            for (int s = 0; s < 2; ++s)
                #pragma unroll
                for (int nb = 0; nb < 8; ++nb)
                    b[s][nb] = *(const uint2*)(bB + s * 16384 + k16 * 4096
                                               + (warp_n * 8 + nb) * 256 + lane * 8);
            #pragma unroll
            for (int ma = 0; ma < 2; ++ma)
                #pragma unroll
                for (int nb = 0; nb < 8; ++nb) {
                    mma_bf16(c[ma][nb], a[0][ma], b[0][nb]);
                    mma_bf16(c[ma][nb], a[0][ma], b[1][nb]);
                    mma_bf16(c[ma][nb], a[1][ma], b[0][nb]);
                }
        }
        __syncthreads();
        if (kt + 1 < NKT) load_tile(kt + 1);
    }

    const int g = lane >> 2, t = lane & 3;
    const int row0 = tm * 128, col0 = tn * 128;
    #pragma unroll
    for (int ma = 0; ma < 2; ++ma) {
        int r0 = row0 + (warp_m * 2 + ma) * 16 + g;
        #pragma unroll
        for (int nb = 0; nb < 8; ++nb) {
            int cc = col0 + (warp_n * 8 + nb) * 8 + 2 * t;
            float b0 = bias[cc], b1 = bias[cc + 1];
            float v0 = fmaxf(__fadd_rn(c[ma][nb][0], b0), 0.f);
            float v1 = fmaxf(__fadd_rn(c[ma][nb][1], b1), 0.f);
            float v2 = fmaxf(__fadd_rn(c[ma][nb][2], b0), 0.f);
            float v3 = fmaxf(__fadd_rn(c[ma][nb][3], b1), 0.f);
            *(float2*)&C[(size_t)r0 * UHID + cc] = make_float2(v0, v1);
            *(float2*)&C[(size_t)(r0 + 8) * UHID + cc] = make_float2(v2, v3);
        }
    }
}

// ---------------- GEMM6: bf16x3 6-pass + per-kt Kahan, pipelined --
__global__ __launch_bounds__(256, 1)
void k_gemm6(const __nv_bfloat16* __restrict__ A0, const __nv_bfloat16* __restrict__ A1,
             const __nv_bfloat16* __restrict__ A2,
             const __nv_bfloat16* __restrict__ B0, const __nv_bfloat16* __restrict__ B1,
             const __nv_bfloat16* __restrict__ B2,
             const float* __restrict__ bias, float* __restrict__ C,
             int Nstore, int ldc) {
    extern __shared__ char sm[];
    const int tid = threadIdx.x, lane = tid & 31, wid = tid >> 5;
    const int warp_m = wid >> 1, warp_n = wid & 1;
    const int tm = blockIdx.y, tn = blockIdx.x;
    const __nv_bfloat16* Ab[3] = {A0, A1, A2};
    const __nv_bfloat16* Bb[3] = {B0, B1, B2};

    float acc[2][4][4], cmp[2][4][4];
    #pragma unroll
    for (int ma = 0; ma < 2; ++ma)
        #pragma unroll
        for (int nb = 0; nb < 4; ++nb)
            #pragma unroll
            for (int q = 0; q < 4; ++q) { acc[ma][nb][q] = 0.f; cmp[ma][nb][q] = 0.f; }

    auto load_tile = [&](int kt, int buf) {
        char* dst = sm + buf * 73728;
        for (int i = tid; i < 4608; i += 256) {
            const char* src; uint32_t doff;
            if (i < 3072) {
                int s = i >> 10, off = i & 1023;
                src = (const char*)Ab[s] + ((size_t)(tm * NKT + kt)) * 16384 + (size_t)off * 16;
                doff = s * 16384 + off * 16;
            } else {
                int j = i - 3072;
                int s = j >> 9, off = j & 511;
                src = (const char*)Bb[s] + ((size_t)(tn * NKT + kt)) * 8192 + (size_t)off * 16;
                doff = 49152 + s * 8192 + off * 16;
            }
            CP_ASYNC16(sm_addr(dst + doff), src);
        }
        CP_COMMIT();
    };
    load_tile(0, 0);
    load_tile(1, 1);

    const int pa[6] = {0, 0, 1, 1, 0, 2};
    const int pb[6] = {0, 1, 0, 1, 2, 0};

    for (int kt = 0; kt < NKT; ++kt) {
        CP_WAIT1();
        __syncthreads();
        char* bA = sm + (kt & 1) * 73728;
        char* bB = bA + 49152;
        float loc[2][4][4];
        #pragma unroll
        for (int ma = 0; ma < 2; ++ma)
            #pragma unroll
            for (int nb = 0; nb < 4; ++nb)
                #pragma unroll
                for (int q = 0; q < 4; ++q) loc[ma][nb][q] = 0.f;
        #pragma unroll
        for (int k16 = 0; k16 < 4; ++k16) {
            uint4 a[3][2]; uint2 b[3][4];
            #pragma unroll
            for (int s = 0; s < 3; ++s)
                #pragma unroll
                for (int ma = 0; ma < 2; ++ma)
                    a[s][ma] = *(const uint4*)(bA + s * 16384 + k16 * 4096
                                               + (warp_m * 2 + ma) * 512 + lane * 16);
            #pragma unroll
            for (int s = 0; s < 3; ++s)
                #pragma unroll
                for (int nb = 0; nb < 4; ++nb)
                    b[s][nb] = *(const uint2*)(bB + s * 8192 + k16 * 2048
                                               + (warp_n * 4 + nb) * 256 + lane * 8);
            #pragma unroll
            for (int pr = 0; pr < 6; ++pr)
                #pragma unroll
                for (int ma = 0; ma < 2; ++ma)
                    #pragma unroll
                    for (int nb = 0; nb < 4; ++nb)
                        mma_bf16(loc[ma][nb], a[pa[pr]][ma], b[pb[pr]][nb]);
        }
        #pragma unroll
        for (int ma = 0; ma < 2; ++ma)
            #pragma unroll
            for (int nb = 0; nb < 4; ++nb)
                #pragma unroll
                for (int q = 0; q < 4; ++q) {
                    float y = __fsub_rn(loc[ma][nb][q], cmp[ma][nb][q]);
                    float t = __fadd_rn(acc[ma][nb][q], y);
                    cmp[ma][nb][q] = __fsub_rn(__fsub_rn(t, acc[ma][nb][q]), y);
                    acc[ma][nb][q] = t;
                }
        __syncthreads();
        if (kt + 2 < NKT) load_tile(kt + 2, kt & 1);
        else CP_COMMIT();
    }

    const int g = lane >> 2, t = lane & 3;
    const int row0 = tm * 128, col0 = tn * 64;
    #pragma unroll
    for (int ma = 0; ma < 2; ++ma) {
        int r0 = row0 + (warp_m * 2 + ma) * 16 + g;
        #pragma unroll
        for (int nb = 0; nb < 4; ++nb) {
            int cc = col0 + (warp_n * 4 + nb) * 8 + 2 * t;
            if (cc >= Nstore) continue;
            float v0 = acc[ma][nb][0], v1 = acc[ma][nb][1];
            float v2 = acc[ma][nb][2], v3 = acc[ma][nb][3];
            if (bias) {
                float b0 = bias[cc];
                float b1 = (cc + 1 < Nstore) ? bias[cc + 1] : 0.f;
                v0 = __fadd_rn(v0, b0); v1 = __fadd_rn(v1, b1);
                v2 = __fadd_rn(v2, b0); v3 = __fadd_rn(v3, b1);
            }
            if (cc + 1 < Nstore) {
                *(float2*)&C[(size_t)r0 * ldc + cc] = make_float2(v0, v1);
                *(float2*)&C[(size_t)(r0 + 8) * ldc + cc] = make_float2(v2, v3);
            } else {
                C[(size_t)r0 * ldc + cc] = v0;
                C[(size_t)(r0 + 8) * ldc + cc] = v2;
            }
        }
    }
}

// ---------------- mention score -----------------------------------
__global__ void k_score(const float* __restrict__ w_u2,
                        const float* __restrict__ b_u2) {
    int warp = (blockIdx.x * blockDim.x + threadIdx.x) >> 5;
    int lane = threadIdx.x & 31;
    if (warp >= C_SP) return;
    const float* row = g_hid1 + (size_t)warp * UHID;
    double acc = 0.0;
    #pragma unroll 8
    for (int i = lane; i < UHID; i += 32) acc += (double)row[i] * (double)w_u2[i];
    #pragma unroll
    for (int o = 16; o; o >>= 1) acc += __shfl_xor_sync(0xffffffffu, acc, o);
    if (lane == 0) g_mention[warp] = (float)(acc + (double)b_u2[0]);
}

// ---------------- sort + greedy + compact -------------------------
__device__ __forceinline__ bool sort_before(float xk, int xi, float yk, int yi) {
    return (xk > yk) || (xk == yk && xi < yi);
}

__global__ void k_extract(const int* __restrict__ starts,
                          const int* __restrict__ widths) {
    extern __shared__ int sh[];
    float* key = (float*)sh;
    int* idx = sh + 4096;
    int* es  = sh + 8192;
    int* flg = sh + 12288;
    const int tid = threadIdx.x;       // 1024 threads
    const int ln32 = tid & 31, wrp = tid >> 5;
    const int ebase = wrp * 128 + ln32 * 4;

    for (int i = tid; i < C_SP; i += 1024) flg[i] = 0;

    float kq[4]; int iq[4];
    #pragma unroll
    for (int q = 0; q < 4; ++q) { kq[q] = g_mention[ebase + q]; iq[q] = ebase + q; }

    auto reg_phase = [&](unsigned k, unsigned j) {
        if (j >= 4) {
            unsigned lm = j >> 2;
            #pragma unroll
            for (int q = 0; q < 4; ++q) {
                float pk = __shfl_xor_sync(0xffffffffu, kq[q], lm);
                int   pi = __shfl_xor_sync(0xffffffffu, iq[q], lm);
                int e = ebase + q;
                int i = e & ~(int)j;
                bool dir = ((i & (int)k) == 0);
                bool swp;
                if ((e & (int)j) == 0)
                    swp = (sort_before(pk, pi, kq[q], iq[q]) == dir);
                else
                    swp = (sort_before(kq[q], iq[q], pk, pi) == dir);
                if (swp) { kq[q] = pk; iq[q] = pi; }
            }
        } else if (j == 2) {
            #pragma unroll
            for (int q = 0; q < 2; ++q) {
                int i = ebase + q;
                bool dir = ((i & (int)k) == 0);
                if (sort_before(kq[q + 2], iq[q + 2], kq[q], iq[q]) == dir) {
                    float tk = kq[q]; int ti = iq[q];
                    kq[q] = kq[q + 2]; iq[q] = iq[q + 2];
                    kq[q + 2] = tk; iq[q + 2] = ti;
                }
            }
        } else {
            #pragma unroll
            for (int q = 0; q < 4; q += 2) {
                int i = ebase + q;
                bool dir = ((i & (int)k) == 0);
                if (sort_before(kq[q + 1], iq[q + 1], kq[q], iq[q]) == dir) {
                    float tk = kq[q]; int ti = iq[q];
                    kq[q] = kq[q + 1]; iq[q] = iq[q + 1];
                    kq[q + 1] = tk; iq[q + 1] = ti;
                }
            }
        }
    };

    for (unsigned k = 2; k <= 128; k <<= 1)
        for (unsigned j = k >> 1; j > 0; j >>= 1) reg_phase(k, j);
    #pragma unroll
    for (int q = 0; q < 4; ++q) { key[ebase + q] = kq[q]; idx[ebase + q] = iq[q]; }
    __syncthreads();

    for (unsigned k = 256; k <= 4096; k <<= 1) {
        for (unsigned j = k >> 1; j >= 128; j >>= 1) {
            for (unsigned t = tid; t < 2048; t += 1024) {
                unsigned i = ((t & ~(j - 1)) << 1) | (t & (j - 1));
                unsigned l = i | j;
                float ki = key[i], kl = key[l];
                int   ii = idx[i], il = idx[l];
                bool before_l_i = (kl > ki) || (kl == ki && il < ii);
                bool dir = ((i & k) == 0);
                if (before_l_i == dir) {
                    key[i] = kl; key[l] = ki;
                    idx[i] = il; idx[l] = ii;
                }
            }
            __syncthreads();
        }
        #pragma unroll
        for (int q = 0; q < 4; ++q) { kq[q] = key[ebase + q]; iq[q] = idx[ebase + q]; }
        for (unsigned j = 64; j > 0; j >>= 1) reg_phase(k, j);
        #pragma unroll
        for (int q = 0; q < 4; ++q) { key[ebase + q] = kq[q]; idx[ebase + q] = iq[q]; }
        __syncthreads();
    }

    volatile int* le = (volatile int*)key;
    volatile int* ves = (volatile int*)es;
    for (int i = tid; i < T_TOK; i += 1024) {
        ((int*)key)[i] = -1;
        es[i] = T_TOK;
    }
    __syncthreads();

    if (tid < 32) {
        int lane = tid;
        int count = 0;
        for (int p = 0; p < C_SP && count < M_TOP; ++p) {
            int ci = idx[p];
            int s = starts[ci];
            int w = widths[ci];
            int e = s + w;
            bool crossing = false;
            if (lane < w) {
                crossing = (le[s + 1 + lane] > e) | (ves[s + lane] < s);
            }
            unsigned m = __ballot_sync(0xffffffffu, crossing);
            if (m == 0u) {
                if (lane == 0) {
                    int cur = le[s]; if (e > cur) ((int*)key)[s] = e;
                    int cur2 = ves[e]; if (s < cur2) es[e] = s;
                    flg[ci] = 1;
                }
                count++;
            }
            __syncwarp();
        }
    }
    __syncthreads();

    __shared__ int wsum[32];
    __shared__ int woff[33];
    int base = tid * 4;
    int f0 = flg[base], f1 = flg[base + 1], f2 = flg[base + 2], f3 = flg[base + 3];
    int c = f0 + f1 + f2 + f3;
    int inc = c;
    int lane = tid & 31, wid = tid >> 5;
    #pragma unroll
    for (int o = 1; o < 32; o <<= 1) {
        int n = __shfl_up_sync(0xffffffffu, inc, o);
        if (lane >= o) inc += n;
    }
    if (lane == 31) wsum[wid] = inc;
    __syncthreads();
    if (tid == 0) {
        int run = 0;
        for (int i = 0; i < 32; ++i) { woff[i] = run; run += wsum[i]; }
        woff[32] = run;
    }
    __syncthreads();
    int pos = woff[wid] + (inc - c);
    if (f0) { if (pos < M_TOP) g_topidx[pos] = base;     pos++; }
    if (f1) { if (pos < M_TOP) g_topidx[pos] = base + 1; pos++; }
    if (f2) { if (pos < M_TOP) g_topidx[pos] = base + 2; pos++; }
    if (f3) { if (pos < M_TOP) g_topidx[pos] = base + 3; pos++; }
    int total = woff[32];
    for (int p = total + tid; p < M_TOP; p += 1024) g_topidx[p] = C_SP - 1;
}

// ---------------- fast scores + per-row top-50 --------------------
__global__ void k_topk(float* __restrict__ out_ant,
                       float* __restrict__ out_mask,
                       float* __restrict__ out_score) {
    __shared__ float v[M_TOP];
    __shared__ float wv[8];
    __shared__ int   wi[8];
    const int i = blockIdx.x;
    const int tid = threadIdx.x;
    const int lane = tid & 31, wid = tid >> 5;
    const float mi = g_topm[i];
    for (int j = tid; j < M_TOP; j += 256) {
        float val = __fadd_rn(__fadd_rn(__fadd_rn(mi, g_topm[j]),
                                        (j < i) ? 0.f : NEGV),
                              g_fast[(size_t)i * M_TOP + j]);
        v[j] = val;
    }
    __syncthreads();
    for (int k = 0; k < K_ANT; ++k) {
        float bv = -INFINITY; int bi = M_TOP;
        for (int j = tid; j < M_TOP; j += 256) {
            float x = v[j];
            if (x > bv || (x == bv && j < bi)) { bv = x; bi = j; }
        }
        #pragma unroll
        for (int o = 16; o; o >>= 1) {
            float ok = __shfl_xor_sync(0xffffffffu, bv, o);
            int   oi = __shfl_xor_sync(0xffffffffu, bi, o);
            if (ok > bv || (ok == bv && oi < bi)) { bv = ok; bi = oi; }
        }
        if (lane == 0) { wv[wid] = bv; wi[wid] = bi; }
        __syncthreads();
        if (tid == 0) {
            float fv = wv[0]; int fi = wi[0];
            #pragma unroll
            for (int w = 1; w < 8; ++w)
                if (wv[w] > fv || (wv[w] == fv && wi[w] < fi)) { fv = wv[w]; fi = wi[w]; }
            out_ant[(size_t)i * K_ANT + k]   = (float)fi;
            out_mask[(size_t)i * K_ANT + k]  = (fi < i) ? 1.f : 0.f;
            out_score[(size_t)i * K_ANT + k] = fv;
            v[fi] = -INFINITY;
        }
        __syncthreads();
    }
}

// ---------------- launch ------------------------------------------
extern "C" void kernel_launch(void* const* d_in, const int* in_sizes, int n_in,
                              void* d_out, int out_size) {
    const float* hs      = (const float*)d_in[0];
    const int*   starts  = (const int*)d_in[1];
    const int*   widths  = (const int*)d_in[2];
    int base = 3;
    if (n_in >= 14 && in_sizes[3] == 1 && in_sizes[4] == 1) base = 5;
    const float* w_width = (const float*)d_in[base + 0];
    const float* w_attn  = (const float*)d_in[base + 1];
    const float* b_attn  = (const float*)d_in[base + 2];
    const float* w_u1    = (const float*)d_in[base + 3];
    const float* b_u1    = (const float*)d_in[base + 4];
    const float* w_u2    = (const float*)d_in[base + 5];
    const float* b_u2    = (const float*)d_in[base + 6];
    const float* w_fast  = (const float*)d_in[base + 7];
    const float* b_fast  = (const float*)d_in[base + 8];

    float* out = (float*)d_out;
    float* out_topidx = out;
    float* out_ant    = out + M_TOP;
    float* out_mask   = out + M_TOP + M_TOP * K_ANT;
    float* out_score  = out + M_TOP + 2 * M_TOP * K_ANT;

    float *p_span, *p_hid1, *p_tmp, *p_fast;
    __nv_bfloat16 *p_sa0, *p_sa1, *p_sa2;
    __nv_bfloat16 *p_fb0, *p_fb1, *p_fb2;
    __nv_bfloat16 *p_ta0, *p_ta1, *p_ta2, *p_taB0, *p_taB1, *p_taB2;
    __nv_bfloat16 *p_tb0, *p_tb1, *p_tb2;
    cudaGetSymbolAddress((void**)&p_span, g_span_emb);
    cudaGetSymbolAddress((void**)&p_hid1, g_hid1);
    cudaGetSymbolAddress((void**)&p_tmp,  g_tmp);
    cudaGetSymbolAddress((void**)&p_fast, g_fast);
    cudaGetSymbolAddress((void**)&p_sa0, g_sa0);
    cudaGetSymbolAddress((void**)&p_sa1, g_sa1);
    cudaGetSymbolAddress((void**)&p_sa2, g_sa2);
    cudaGetSymbolAddress((void**)&p_fb0, g_fbx0);
    cudaGetSymbolAddress((void**)&p_fb1, g_fbx1);
    cudaGetSymbolAddress((void**)&p_fb2, g_fbx2);
    cudaGetSymbolAddress((void**)&p_ta0, g_ta0);
    cudaGetSymbolAddress((void**)&p_ta1, g_ta1);
    cudaGetSymbolAddress((void**)&p_ta2, g_ta2);
    cudaGetSymbolAddress((void**)&p_taB0, g_taB0);
    cudaGetSymbolAddress((void**)&p_taB1, g_taB1);
    cudaGetSymbolAddress((void**)&p_taB2, g_taB2);
    cudaGetSymbolAddress((void**)&p_tb0, g_tb0);
    cudaGetSymbolAddress((void**)&p_tb1, g_tb1);
    cudaGetSymbolAddress((void**)&p_tb2, g_tb2);

    cudaFuncSetAttribute(k_gemm3, cudaFuncAttributeMaxDynamicSharedMemorySize, 65536);
    cudaFuncSetAttribute(k_gemm6, cudaFuncAttributeMaxDynamicSharedMemorySize, 147456);
    cudaFuncSetAttribute(k_extract, cudaFuncAttributeMaxDynamicSharedMemorySize, 65536);

    const int smPre  = 64 * 132 * 4;     // k_pre split part
    const int smA    = 128 * 68 * 4;     // k_splitA_frag
    const int smB64  = 64 * 68 * 4;      // k_splitB64

    // #0: fused token_logits + w_u1 split
    k_pre<<<512 + NKT * 8, 256, smPre>>>(hs, w_attn, b_attn, w_u1);
    // #1: span embeddings
    k_span_emb<<<C_SP, 256>>>(hs, starts, widths, w_width);
    // #2: span_emb -> A-frag splits
    { dim3 g(NKT, C_SP / 128);
      k_splitA_frag<<<g, 256, smA>>>(p_span, p_sa0, p_sa1, p_sa2); }
    // #3: GEMM3 (ncu capture target)
    { dim3 g(UHID / 128, C_SP / 128);
      k_gemm3<<<g, 256, 65536>>>(b_u1, p_hid1); }
    // w_fast split (needed only by GEMM7)
    { dim3 g(NKT, NKT); k_splitB64<<<g, 256, smB64>>>(w_fast); }
    k_score<<<C_SP * 32 / 256, 256>>>(w_u2, b_u2);
    k_extract<<<1, 1024, 65536>>>(starts, widths);
    k_topmeta<<<1, 1024>>>(out_topidx);
    { dim3 g(NKT, 8);  k_gatherA<<<g, 256>>>(); }
    { dim3 g(NKT, 16); k_gatherB<<<g, 256>>>(); }
    { dim3 g(NKT, M_TOP / 128);
      k_gemm6<<<g, 256, 147456>>>(p_ta0, p_ta1, p_ta2, p_fb0, p_fb1, p_fb2,
                                  b_fast, p_tmp, SPAND, SPAND); }
    { dim3 g(NKT, M_TOP / 128);
      k_splitA_frag<<<g, 256, smA>>>(p_tmp, p_tb0, p_tb1, p_tb2); }
    { dim3 g(M_TOP / 64, M_TOP / 128);
      k_gemm6<<<g, 256, 147456>>>(p_tb0, p_tb1, p_tb2, p_taB0, p_taB1, p_taB2,
                                  nullptr, p_fast, M_TOP, M_TOP); }
    k_topk<<<M_TOP, 256>>>(out_ant, out_mask, out_score);

    (void)in_sizes; (void)n_in; (void)out_size;
}